// round 10
// baseline (speedup 1.0000x reference)
#include <cuda_runtime.h>

#define V 512

// ---------------- scratch (device globals; no runtime alloc) ----------------
__device__ float g_tlo[256*133*V];
__device__ float g_thi[256*133*V];
__device__ float g_ll1[133*133*V];
__device__ float g_lh1[133*133*V];
__device__ float g_hl1[133*133*V];
__device__ float g_hh1[133*133*V];
__device__ float g_ll2[72*72*V];
__device__ float g_lh2[72*72*V];
__device__ float g_hl2[72*72*V];
__device__ float g_hh2[72*72*V];
__device__ float g_ll3[41*41*V];
__device__ float g_lh3[41*41*V];
__device__ float g_hl3[41*41*V];
__device__ float g_hh3[41*41*V];
__device__ float g_r2 [134*134*V];
__device__ float g_wt [64*64*64*64]; // weights transposed to [gy*64+gx][i][o]

// ---------------- filter taps as literal constants ----------------
#define AFB_TAPS(X) \
  X(0,  0.11154074335008017f,    -0.00107730108499558f)   \
  X(1,  0.4946238903983854f,     -0.004777257511010651f)  \
  X(2,  0.7511339080215775f,      0.0005538422009938016f) \
  X(3,  0.3152503517092432f,      0.031582039318031156f)  \
  X(4, -0.22626469396516913f,     0.02752286553001629f)   \
  X(5, -0.12976686756709563f,    -0.09750160558707936f)   \
  X(6,  0.09750160558707936f,    -0.12976686756709563f)   \
  X(7,  0.02752286553001629f,     0.22626469396516913f)   \
  X(8, -0.031582039318031156f,    0.3152503517092432f)    \
  X(9,  0.0005538422009938016f,  -0.7511339080215775f)    \
  X(10, 0.004777257511010651f,    0.4946238903983854f)    \
  X(11,-0.00107730108499558f,    -0.11154074335008017f)

#define SFB_EVEN(X) \
  X(0,  0.004777257511010651f,    0.4946238903983854f)    \
  X(1, -0.031582039318031156f,    0.3152503517092432f)    \
  X(2,  0.09750160558707936f,    -0.12976686756709563f)   \
  X(3, -0.22626469396516913f,     0.02752286553001629f)   \
  X(4,  0.7511339080215775f,      0.0005538422009938016f) \
  X(5,  0.11154074335008017f,    -0.00107730108499558f)
#define SFB_ODD(X) \
  X(0, -0.00107730108499558f,    -0.11154074335008017f)   \
  X(1,  0.0005538422009938016f,  -0.7511339080215775f)    \
  X(2,  0.02752286553001629f,     0.22626469396516913f)   \
  X(3, -0.12976686756709563f,    -0.09750160558707936f)   \
  X(4,  0.3152503517092432f,      0.031582039318031156f)  \
  X(5,  0.4946238903983854f,     -0.004777257511010651f)

// ---------------- weight transpose: in[i][o][c] -> out[c][i][o] -------------
__global__ __launch_bounds__(256) void wtrans2(const float* __restrict__ in,
                                               float* __restrict__ out) {
    __shared__ float t[8][32][33];
    int i0 = blockIdx.x * 8, o0 = blockIdx.y * 32, c0 = blockIdx.z * 32;
    int tid = threadIdx.x;
    for (int l = tid; l < 8192; l += 256) {
        int ii = l >> 10, rest = l & 1023;
        int oy = rest >> 5, cx = rest & 31;
        t[ii][oy][cx] = in[(long)(i0 + ii) * 262144 + (long)(o0 + oy) * 4096 + c0 + cx];
    }
    __syncthreads();
    int ii = tid >> 5, ox = tid & 31;
    long ob = (long)(i0 + ii) * 64 + o0 + ox;
    #pragma unroll
    for (int cr = 0; cr < 32; cr++)
        out[(long)(c0 + cr) * 4096 + ob] = t[ii][ox][cr];
}

// ---------------- fused: NCHW input -> level-1 W-direction afb -> HWC -------
__global__ __launch_bounds__(256) void afb_w_first(const float* __restrict__ x,
    float* __restrict__ lo, float* __restrict__ hi) {
    __shared__ float srow[32][277];
    int y = blockIdx.y, q0 = blockIdx.x * 32;
    int tid = threadIdx.x;
    for (int idx = tid; idx < 32 * 276; idx += 256) {
        int ql = idx / 276, ew = idx - ql * 276;
        int t = ew - 10;
        t = (t < 0) ? (-1 - t) : ((t >= 256) ? (511 - t) : t);
        srow[ql][ew] = x[(q0 + ql) * 65536 + y * 256 + t];
    }
    __syncthreads();
    int ql = tid & 31, jj = tid >> 5;
    int j0 = jj * 17;
    float w[12];
    #pragma unroll
    for (int k = 0; k < 12; k++) w[k] = srow[ql][2 * j0 + k];
    int ob = y * 133 * 512 + q0 + ql;
    #pragma unroll
    for (int u = 0; u < 17; u++) {
        int j = j0 + u;
        if (j < 133) {
            float alo = 0.f, ahi = 0.f;
#define TAP(K, CLO, CHI) { float xv = w[K]; alo += (CLO) * xv; ahi += (CHI) * xv; }
            AFB_TAPS(TAP)
#undef TAP
            lo[ob + j * 512] = alo;
            hi[ob + j * 512] = ahi;
        }
        if (u < 16 && j < 132) {
            #pragma unroll
            for (int k = 0; k < 10; k++) w[k] = w[k + 2];
            w[10] = srow[ql][2 * j + 12];
            w[11] = srow[ql][2 * j + 13];
        }
    }
}

// ---------------- fused: final W-direction sfb -> NCHW output ---------------
__global__ __launch_bounds__(256) void sfb_w_last(const float* __restrict__ lo,
    const float* __restrict__ hi, float* __restrict__ out) {
    __shared__ float sout[256][33];
    int y = blockIdx.y, q0 = blockIdx.x * 32;
    int tid = threadIdx.x, ql = tid & 31, mm = tid >> 5;
    int m0 = mm * 32;
    const float* plo = lo + y * 133 * 512 + q0 + ql;
    const float* phi = hi + y * 133 * 512 + q0 + ql;
    int t0 = m0 >> 1;
    float wl[6], wh[6];
    #pragma unroll
    for (int k = 0; k < 6; k++) {
        wl[k] = plo[(t0 + k) * 512];
        wh[k] = phi[(t0 + k) * 512];
    }
    #pragma unroll
    for (int p = 0; p < 16; p++) {
        float ae = 0.f, ao = 0.f;
#define ETAP(KK, CLO, CHI) { ae += (CLO) * wl[KK]; ae += (CHI) * wh[KK]; }
        SFB_EVEN(ETAP)
#undef ETAP
#define OTAP(KK, CLO, CHI) { ao += (CLO) * wl[KK]; ao += (CHI) * wh[KK]; }
        SFB_ODD(OTAP)
#undef OTAP
        sout[m0 + 2 * p][ql]     = ae;
        sout[m0 + 2 * p + 1][ql] = ao;
        if (p < 15) {
            #pragma unroll
            for (int k = 0; k < 5; k++) { wl[k] = wl[k + 1]; wh[k] = wh[k + 1]; }
            int t = t0 + p + 6;
            wl[5] = plo[t * 512];
            wh[5] = phi[t * 512];
        }
    }
    __syncthreads();
    int obase = y * 256 + tid;
    #pragma unroll
    for (int i = 0; i < 32; i++)
        out[(q0 + i) * 65536 + obase] = sout[tid][i];
}

// ---------------- afb core (sliding window, 4 outputs/thread) ---------------
__device__ __forceinline__ void afb_core(
    const float* __restrict__ in, float* __restrict__ lo, float* __restrict__ hi,
    int nf_in, int nf_out, int sf_in, int so_in, int sf_out, int so_out,
    int bx, int by, int bz) {
    int lane = threadIdx.x & 31;
    int jj = threadIdx.x >> 5;
    int j0 = (bx * 8 + jj) * 4;
    if (j0 >= nf_out) return;
    int vo = bz * 128 + lane * 4;
    const float* pin = in + by * so_in + vo;
    int tb = 2 * j0 - 10;
    float4 w[12];
    #pragma unroll
    for (int k = 0; k < 12; k++) {
        int t = tb + k;
        t = (t < 0) ? (-1 - t) : ((t >= nf_in) ? (2 * nf_in - 1 - t) : t);
        w[k] = *(const float4*)(pin + t * sf_in);
    }
    int oo = by * so_out + j0 * sf_out + vo;
    float* plo = lo + oo;
    float* phi = hi + oo;
    #pragma unroll
    for (int u = 0; u < 4; u++) {
        if (j0 + u < nf_out) {
            float4 alo = {0.f,0.f,0.f,0.f}, ahi = {0.f,0.f,0.f,0.f};
#define TAP(K, CLO, CHI) { float4 xv = w[K];                                   \
            alo.x += (CLO) * xv.x; alo.y += (CLO) * xv.y;                      \
            alo.z += (CLO) * xv.z; alo.w += (CLO) * xv.w;                      \
            ahi.x += (CHI) * xv.x; ahi.y += (CHI) * xv.y;                      \
            ahi.z += (CHI) * xv.z; ahi.w += (CHI) * xv.w; }
            AFB_TAPS(TAP)
#undef TAP
            *(float4*)plo = alo;
            *(float4*)phi = ahi;
        }
        if (u < 3) {
            #pragma unroll
            for (int k = 0; k < 10; k++) w[k] = w[k + 2];
            int t0n = tb + 12 + 2 * u;
            int t1n = t0n + 1;
            t0n = (t0n >= nf_in) ? (2 * nf_in - 1 - t0n) : t0n;
            t1n = (t1n >= nf_in) ? (2 * nf_in - 1 - t1n) : t1n;
            w[10] = *(const float4*)(pin + t0n * sf_in);
            w[11] = *(const float4*)(pin + t1n * sf_in);
            plo += sf_out;
            phi += sf_out;
        }
    }
}

__global__ __launch_bounds__(256) void afb_kernel(
    const float* __restrict__ in, float* __restrict__ lo, float* __restrict__ hi,
    int nf_in, int nf_out, int sf_in, int so_in, int sf_out, int so_out) {
    afb_core(in, lo, hi, nf_in, nf_out, sf_in, so_in, sf_out, so_out,
             blockIdx.x, blockIdx.y, blockIdx.z);
}

__global__ __launch_bounds__(256) void afb_pair(
    const float* __restrict__ in0, float* __restrict__ lo0, float* __restrict__ hi0,
    const float* __restrict__ in1, float* __restrict__ lo1, float* __restrict__ hi1,
    int nf_in, int nf_out, int sf_in, int so_in, int sf_out, int so_out) {
    int sel = blockIdx.z >> 2, bz = blockIdx.z & 3;
    afb_core(sel ? in1 : in0, sel ? lo1 : lo0, sel ? hi1 : hi0,
             nf_in, nf_out, sf_in, so_in, sf_out, so_out,
             blockIdx.x, blockIdx.y, bz);
}

// ---------------- sfb core (sliding window, 4 outputs/thread) ---------------
__device__ __forceinline__ void sfb_core(
    const float* __restrict__ lo, const float* __restrict__ hi, float* __restrict__ out,
    int n_t, int nf_out, int sflo, int solo, int sfhi, int sohi,
    int sf_out, int so_out, int bx, int by, int bz) {
    int lane = threadIdx.x & 31;
    int mm = threadIdx.x >> 5;
    int m0 = (bx * 8 + mm) * 4;
    if (m0 >= nf_out) return;
    int vo = bz * 128 + lane * 4;
    const float* plo = lo + by * solo + vo;
    const float* phi = hi + by * sohi + vo;
    int t0 = m0 >> 1;
    float4 wl[6], wh[6];
    #pragma unroll
    for (int k = 0; k < 6; k++) {
        int t = t0 + k;
        bool ok = (unsigned)t < (unsigned)n_t;
        wl[k] = ok ? *(const float4*)(plo + t * sflo) : make_float4(0.f,0.f,0.f,0.f);
        wh[k] = ok ? *(const float4*)(phi + t * sfhi) : make_float4(0.f,0.f,0.f,0.f);
    }
    float* pout = out + by * so_out + m0 * sf_out + vo;
    #pragma unroll
    for (int p = 0; p < 2; p++) {
        float4 ae = {0.f,0.f,0.f,0.f}, ao = {0.f,0.f,0.f,0.f};
#define ETAP(KK, CLO, CHI) { float4 a = wl[KK]; float4 b = wh[KK];             \
        ae.x += (CLO)*a.x; ae.x += (CHI)*b.x;  ae.y += (CLO)*a.y; ae.y += (CHI)*b.y; \
        ae.z += (CLO)*a.z; ae.z += (CHI)*b.z;  ae.w += (CLO)*a.w; ae.w += (CHI)*b.w; }
        SFB_EVEN(ETAP)
#undef ETAP
#define OTAP(KK, CLO, CHI) { float4 a = wl[KK]; float4 b = wh[KK];             \
        ao.x += (CLO)*a.x; ao.x += (CHI)*b.x;  ao.y += (CLO)*a.y; ao.y += (CHI)*b.y; \
        ao.z += (CLO)*a.z; ao.z += (CHI)*b.z;  ao.w += (CLO)*a.w; ao.w += (CHI)*b.w; }
        SFB_ODD(OTAP)
#undef OTAP
        int me = m0 + 2 * p;
        if (me < nf_out)     *(float4*)pout = ae;
        if (me + 1 < nf_out) *(float4*)(pout + sf_out) = ao;
        if (p == 0) {
            #pragma unroll
            for (int k = 0; k < 5; k++) { wl[k] = wl[k + 1]; wh[k] = wh[k + 1]; }
            int t = t0 + 6;
            bool ok = (unsigned)t < (unsigned)n_t;
            wl[5] = ok ? *(const float4*)(plo + t * sflo) : make_float4(0.f,0.f,0.f,0.f);
            wh[5] = ok ? *(const float4*)(phi + t * sfhi) : make_float4(0.f,0.f,0.f,0.f);
            pout += 2 * sf_out;
        }
    }
}

__global__ __launch_bounds__(256) void sfb_kernel(
    const float* __restrict__ lo, const float* __restrict__ hi, float* __restrict__ out,
    int n_t, int nf_out, int sflo, int solo, int sfhi, int sohi,
    int sf_out, int so_out) {
    sfb_core(lo, hi, out, n_t, nf_out, sflo, solo, sfhi, sohi, sf_out, so_out,
             blockIdx.x, blockIdx.y, blockIdx.z);
}

__global__ __launch_bounds__(256) void sfb_pair(
    const float* __restrict__ lo0, const float* __restrict__ hi0, float* __restrict__ out0,
    const float* __restrict__ lo1, const float* __restrict__ hi1, float* __restrict__ out1,
    int n_t, int nf_out, int sflo0, int sflo1, int solo, int sfhi, int sohi,
    int sf_out, int so_out) {
    int sel = blockIdx.z >> 2, bz = blockIdx.z & 3;
    sfb_core(sel ? lo1 : lo0, sel ? hi1 : hi0, sel ? out1 : out0,
             n_t, nf_out, sel ? sflo1 : sflo0, solo, sfhi, sohi, sf_out, so_out,
             blockIdx.x, blockIdx.y, bz);
}

// ---------------- conv, 2 pixels/CTA, 64 threads/pixel, TR=6 (S=3 only) -----
__global__ __launch_bounds__(128, 4) void conv2(
    float* p0, float* p1, float* p2, int n) {
    constexpr int S = 3;
    constexpr int R = S * 8;          // 24
    constexpr int TR = R / 4;         // 6 rows per thread
    __shared__ float w_s[2][64 * 64];
    __shared__ float in_s[2][R * 64];
    int tid = threadIdx.x;
    int sel = tid >> 6, t = tid & 63;
    int jy = blockIdx.y, jx = blockIdx.x * 2 + sel;
    bool act = jx < n;
    long pix = 0;
    if (act) {
        float sc = (float)(64.0 / n);
        float yc = fminf(fmaxf((jy + 0.5f) * sc - 0.5f, 0.0f), 63.0f);
        float xc = fminf(fmaxf((jx + 0.5f) * sc - 0.5f, 0.0f), 63.0f);
        int y0 = (int)floorf(yc), x0 = (int)floorf(xc);
        int y1 = min(y0 + 1, 63), x1 = min(x0 + 1, 63);
        float ty = yc - (float)y0, tx = xc - (float)x0;
        float c00 = (1.f - ty) * (1.f - tx), c01 = (1.f - ty) * tx;
        float c10 = ty * (1.f - tx),         c11 = ty * tx;
        const float* w00 = g_wt + ((long)y0 * 64 + x0) * 4096;
        const float* w01 = g_wt + ((long)y0 * 64 + x1) * 4096;
        const float* w10 = g_wt + ((long)y1 * 64 + x0) * 4096;
        const float* w11 = g_wt + ((long)y1 * 64 + x1) * 4096;
        #pragma unroll 2
        for (int c = 0; c < 16; c++) {
            int e = c * 256 + t * 4;
            float4 a = *(const float4*)(w00 + e);
            float4 b = *(const float4*)(w01 + e);
            float4 d = *(const float4*)(w10 + e);
            float4 f = *(const float4*)(w11 + e);
            float4 wv;
            wv.x = c00 * a.x + c01 * b.x + c10 * d.x + c11 * f.x;
            wv.y = c00 * a.y + c01 * b.y + c10 * d.y + c11 * f.y;
            wv.z = c00 * a.z + c01 * b.z + c10 * d.z + c11 * f.z;
            wv.w = c00 * a.w + c01 * b.w + c10 * d.w + c11 * f.w;
            *(float4*)&w_s[sel][e] = wv;
        }
        pix = ((long)jy * n + jx) * V;
        #pragma unroll
        for (int l = 0; l < R / 4; l++) {
            int idx = l * 64 + t;
            int r = idx >> 4, i4 = (idx & 15) * 4;
            int ss = r >> 3, b = r & 7;
            const float* p = (ss == 0) ? p0 : (ss == 1) ? p1 : p2;
            *(float4*)&in_s[sel][r * 64 + i4] = *(const float4*)(p + pix + b * 64 + i4);
        }
    }
    __syncthreads();
    if (act) {
        int colg = t & 15, rowg = t >> 4;
        int o0 = colg * 4, r0 = rowg * TR;
        float4 acc[TR];
        #pragma unroll
        for (int r = 0; r < TR; r++) acc[r] = make_float4(0.f, 0.f, 0.f, 0.f);
        #pragma unroll 8
        for (int i = 0; i < 64; i += 4) {
            float4 w0 = *(const float4*)&w_s[sel][(i + 0) * 64 + o0];
            float4 w1 = *(const float4*)&w_s[sel][(i + 1) * 64 + o0];
            float4 w2 = *(const float4*)&w_s[sel][(i + 2) * 64 + o0];
            float4 w3 = *(const float4*)&w_s[sel][(i + 3) * 64 + o0];
            #pragma unroll
            for (int r = 0; r < TR; r++) {
                float4 v = *(const float4*)&in_s[sel][(r0 + r) * 64 + i];
                acc[r].x += v.x * w0.x; acc[r].y += v.x * w0.y;
                acc[r].z += v.x * w0.z; acc[r].w += v.x * w0.w;
                acc[r].x += v.y * w1.x; acc[r].y += v.y * w1.y;
                acc[r].z += v.y * w1.z; acc[r].w += v.y * w1.w;
                acc[r].x += v.z * w2.x; acc[r].y += v.z * w2.y;
                acc[r].z += v.z * w2.z; acc[r].w += v.z * w2.w;
                acc[r].x += v.w * w3.x; acc[r].y += v.w * w3.y;
                acc[r].z += v.w * w3.z; acc[r].w += v.w * w3.w;
            }
        }
        #pragma unroll
        for (int r = 0; r < TR; r++) {
            int rr = r0 + r;
            int ss = rr >> 3, b = rr & 7;
            float* p = (ss == 0) ? p0 : (ss == 1) ? p1 : p2;
            *(float4*)(p + pix + b * 64 + o0) = acc[r];
        }
    }
}

// ---------------- per-pixel conv (level 3, S=4) ----------------
template <int S>
__global__ __launch_bounds__(128, 4) void conv_kernel(
    float* p0, float* p1, float* p2, float* p3, int n) {
    constexpr int R  = S * 8;
    constexpr int TR = R / 8;
    __shared__ float w_s[64 * 64];    // [i][o]
    __shared__ float in_s[R * 64];    // [r][k]
    int jx = blockIdx.x, jy = blockIdx.y, tid = threadIdx.x;
    float sc = (float)(64.0 / n);
    float yc = fminf(fmaxf((jy + 0.5f) * sc - 0.5f, 0.0f), 63.0f);
    float xc = fminf(fmaxf((jx + 0.5f) * sc - 0.5f, 0.0f), 63.0f);
    int y0 = (int)floorf(yc), x0 = (int)floorf(xc);
    int y1 = min(y0 + 1, 63), x1 = min(x0 + 1, 63);
    float ty = yc - (float)y0, tx = xc - (float)x0;
    float c00 = (1.f - ty) * (1.f - tx), c01 = (1.f - ty) * tx;
    float c10 = ty * (1.f - tx),         c11 = ty * tx;
    const float* w00 = g_wt + ((long)y0 * 64 + x0) * 4096;
    const float* w01 = g_wt + ((long)y0 * 64 + x1) * 4096;
    const float* w10 = g_wt + ((long)y1 * 64 + x0) * 4096;
    const float* w11 = g_wt + ((long)y1 * 64 + x1) * 4096;
    #pragma unroll 2
    for (int c = 0; c < 8; c++) {
        int e = c * 512 + tid * 4;
        float4 a = *(const float4*)(w00 + e);
        float4 b = *(const float4*)(w01 + e);
        float4 d = *(const float4*)(w10 + e);
        float4 f = *(const float4*)(w11 + e);
        float4 wv;
        wv.x = c00 * a.x + c01 * b.x + c10 * d.x + c11 * f.x;
        wv.y = c00 * a.y + c01 * b.y + c10 * d.y + c11 * f.y;
        wv.z = c00 * a.z + c01 * b.z + c10 * d.z + c11 * f.z;
        wv.w = c00 * a.w + c01 * b.w + c10 * d.w + c11 * f.w;
        *(float4*)&w_s[e] = wv;
    }
    long pix = ((long)jy * n + jx) * V;
    {
        int b = tid >> 4, i4 = (tid & 15) * 4;
        #pragma unroll
        for (int ss = 0; ss < S; ss++) {
            const float* p = (ss == 0) ? p0 : (ss == 1) ? p1 : (ss == 2) ? p2 : p3;
            *(float4*)&in_s[(ss * 8 + b) * 64 + i4] = *(const float4*)(p + pix + b * 64 + i4);
        }
    }
    __syncthreads();
    int colg = tid & 15, rowg = tid >> 4;
    int o0 = colg * 4, r0 = rowg * TR;
    float4 acc[TR];
    #pragma unroll
    for (int r = 0; r < TR; r++) acc[r] = make_float4(0.f, 0.f, 0.f, 0.f);
    #pragma unroll 8
    for (int i = 0; i < 64; i += 4) {
        float4 w0 = *(const float4*)&w_s[(i + 0) * 64 + o0];
        float4 w1 = *(const float4*)&w_s[(i + 1) * 64 + o0];
        float4 w2 = *(const float4*)&w_s[(i + 2) * 64 + o0];
        float4 w3 = *(const float4*)&w_s[(i + 3) * 64 + o0];
        #pragma unroll
        for (int r = 0; r < TR; r++) {
            float4 v = *(const float4*)&in_s[(r0 + r) * 64 + i];
            acc[r].x += v.x * w0.x; acc[r].y += v.x * w0.y;
            acc[r].z += v.x * w0.z; acc[r].w += v.x * w0.w;
            acc[r].x += v.y * w1.x; acc[r].y += v.y * w1.y;
            acc[r].z += v.y * w1.z; acc[r].w += v.y * w1.w;
            acc[r].x += v.z * w2.x; acc[r].y += v.z * w2.y;
            acc[r].z += v.z * w2.z; acc[r].w += v.z * w2.w;
            acc[r].x += v.w * w3.x; acc[r].y += v.w * w3.y;
            acc[r].z += v.w * w3.z; acc[r].w += v.w * w3.w;
        }
    }
    #pragma unroll
    for (int r = 0; r < TR; r++) {
        int rr = r0 + r;
        int ss = rr >> 3, b = rr & 7;
        float* p = (ss == 0) ? p0 : (ss == 1) ? p1 : (ss == 2) ? p2 : p3;
        *(float4*)(p + pix + b * 64 + o0) = acc[r];
    }
}

// ---------------- host ----------------
#define SYM(var, sym) float* var; { void* _p; cudaGetSymbolAddress(&_p, sym); var = (float*)_p; }

extern "C" void kernel_launch(void* const* d_in, const int* in_sizes, int n_in,
                              void* d_out, int out_size) {
    const float* x = (const float*)d_in[0];
    const float* w = (const float*)d_in[1];
    float* out = (float*)d_out;
    SYM(TLO, g_tlo) SYM(THI, g_thi)
    SYM(LL1, g_ll1) SYM(LH1, g_lh1) SYM(HL1, g_hl1) SYM(HH1, g_hh1)
    SYM(LL2, g_ll2) SYM(LH2, g_lh2) SYM(HL2, g_hl2) SYM(HH2, g_hh2)
    SYM(LL3, g_ll3) SYM(LH3, g_lh3) SYM(HL3, g_hl3) SYM(HH3, g_hh3)
    SYM(R2, g_r2)  SYM(WT, g_wt)

    // #1..#3
    wtrans2<<<dim3(8, 2, 128), 256>>>(w, WT);
    afb_w_first<<<dim3(16, 256), 256>>>(x, TLO, THI);
    afb_pair<<<dim3(5, 133, 8), 256>>>(TLO, LL1, LH1, THI, HL1, HH1,
                                       256, 133, 133*512, 512, 133*512, 512);
    // #4: the dominant conv — profiled slot
    conv2<<<dim3(67, 133), 128>>>(LH1, HL1, HH1, 133);
    // remaining DWT
    afb_kernel<<<dim3(3, 133, 4), 256>>>(LL1, TLO, THI, 133, 72, 512, 133*512, 512, 72*512);
    afb_pair<<<dim3(3, 72, 8), 256>>>(TLO, LL2, LH2, THI, HL2, HH2,
                                      133, 72, 72*512, 512, 72*512, 512);
    conv2<<<dim3(36, 72), 128>>>(LH2, HL2, HH2, 72);
    afb_kernel<<<dim3(2, 72, 4), 256>>>(LL2, TLO, THI, 72, 41, 512, 72*512, 512, 41*512);
    afb_pair<<<dim3(2, 41, 8), 256>>>(TLO, LL3, LH3, THI, HL3, HH3,
                                      72, 41, 41*512, 512, 41*512, 512);
    conv_kernel<4><<<dim3(41, 41), 128>>>(LL3, LH3, HL3, HH3, 41);

    // ---- IDWT ----
    sfb_pair<<<dim3(3, 41, 8), 256>>>(LL3, LH3, TLO, HL3, HH3, THI,
        41, 72, 41*512, 41*512, 512, 41*512, 512, 41*512, 512);
    sfb_kernel<<<dim3(3, 72, 4), 256>>>(TLO, THI, LL2, 41, 72,
        512, 41*512, 512, 41*512, 512, 72*512);
    sfb_pair<<<dim3(5, 72, 8), 256>>>(LL2, LH2, TLO, HL2, HH2, THI,
        72, 134, 72*512, 72*512, 512, 72*512, 512, 72*512, 512);
    sfb_kernel<<<dim3(5, 134, 4), 256>>>(TLO, THI, R2, 72, 134,
        512, 72*512, 512, 72*512, 512, 134*512);
    sfb_pair<<<dim3(8, 133, 8), 256>>>(R2, LH1, TLO, HL1, HH1, THI,
        133, 256, 134*512, 133*512, 512, 133*512, 512, 133*512, 512);
    sfb_w_last<<<dim3(16, 256), 256>>>(TLO, THI, out);
}

// round 11
// speedup vs baseline: 1.0153x; 1.0153x over previous
#include <cuda_runtime.h>

#define V 512

// ---------------- scratch (device globals; no runtime alloc) ----------------
__device__ float g_tlo[256*133*V];
__device__ float g_thi[256*133*V];
__device__ float g_ll1[133*133*V];
__device__ float g_lh1[133*133*V];
__device__ float g_hl1[133*133*V];
__device__ float g_hh1[133*133*V];
__device__ float g_ll2[72*72*V];
__device__ float g_lh2[72*72*V];
__device__ float g_hl2[72*72*V];
__device__ float g_hh2[72*72*V];
__device__ float g_ll3[41*41*V];
__device__ float g_lh3[41*41*V];
__device__ float g_hl3[41*41*V];
__device__ float g_hh3[41*41*V];
__device__ float g_r2 [134*134*V];
__device__ float g_wt [64*64*64*64]; // weights transposed to [gy*64+gx][i][o]

// ---------------- filter taps as literal constants ----------------
#define AFB_TAPS(X) \
  X(0,  0.11154074335008017f,    -0.00107730108499558f)   \
  X(1,  0.4946238903983854f,     -0.004777257511010651f)  \
  X(2,  0.7511339080215775f,      0.0005538422009938016f) \
  X(3,  0.3152503517092432f,      0.031582039318031156f)  \
  X(4, -0.22626469396516913f,     0.02752286553001629f)   \
  X(5, -0.12976686756709563f,    -0.09750160558707936f)   \
  X(6,  0.09750160558707936f,    -0.12976686756709563f)   \
  X(7,  0.02752286553001629f,     0.22626469396516913f)   \
  X(8, -0.031582039318031156f,    0.3152503517092432f)    \
  X(9,  0.0005538422009938016f,  -0.7511339080215775f)    \
  X(10, 0.004777257511010651f,    0.4946238903983854f)    \
  X(11,-0.00107730108499558f,    -0.11154074335008017f)

#define SFB_EVEN(X) \
  X(0,  0.004777257511010651f,    0.4946238903983854f)    \
  X(1, -0.031582039318031156f,    0.3152503517092432f)    \
  X(2,  0.09750160558707936f,    -0.12976686756709563f)   \
  X(3, -0.22626469396516913f,     0.02752286553001629f)   \
  X(4,  0.7511339080215775f,      0.0005538422009938016f) \
  X(5,  0.11154074335008017f,    -0.00107730108499558f)
#define SFB_ODD(X) \
  X(0, -0.00107730108499558f,    -0.11154074335008017f)   \
  X(1,  0.0005538422009938016f,  -0.7511339080215775f)    \
  X(2,  0.02752286553001629f,     0.22626469396516913f)   \
  X(3, -0.12976686756709563f,    -0.09750160558707936f)   \
  X(4,  0.3152503517092432f,      0.031582039318031156f)  \
  X(5,  0.4946238903983854f,     -0.004777257511010651f)

// ---------------- weight transpose: in[i][o][c] -> out[c][i][o] -------------
__global__ __launch_bounds__(256) void wtrans2(const float* __restrict__ in,
                                               float* __restrict__ out) {
    __shared__ float t[8][32][33];
    int i0 = blockIdx.x * 8, o0 = blockIdx.y * 32, c0 = blockIdx.z * 32;
    int tid = threadIdx.x;
    for (int l = tid; l < 8192; l += 256) {
        int ii = l >> 10, rest = l & 1023;
        int oy = rest >> 5, cx = rest & 31;
        t[ii][oy][cx] = in[(long)(i0 + ii) * 262144 + (long)(o0 + oy) * 4096 + c0 + cx];
    }
    __syncthreads();
    int ii = tid >> 5, ox = tid & 31;
    long ob = (long)(i0 + ii) * 64 + o0 + ox;
    #pragma unroll
    for (int cr = 0; cr < 32; cr++)
        out[(long)(c0 + cr) * 4096 + ob] = t[ii][ox][cr];
}

// ---------------- fused: NCHW input -> level-1 W-direction afb -> HWC -------
__global__ __launch_bounds__(256) void afb_w_first(const float* __restrict__ x,
    float* __restrict__ lo, float* __restrict__ hi) {
    __shared__ float srow[32][277];
    int y = blockIdx.y, q0 = blockIdx.x * 32;
    int tid = threadIdx.x;
    for (int idx = tid; idx < 32 * 276; idx += 256) {
        int ql = idx / 276, ew = idx - ql * 276;
        int t = ew - 10;
        t = (t < 0) ? (-1 - t) : ((t >= 256) ? (511 - t) : t);
        srow[ql][ew] = x[(q0 + ql) * 65536 + y * 256 + t];
    }
    __syncthreads();
    int ql = tid & 31, jj = tid >> 5;
    int j0 = jj * 17;
    float w[12];
    #pragma unroll
    for (int k = 0; k < 12; k++) w[k] = srow[ql][2 * j0 + k];
    int ob = y * 133 * 512 + q0 + ql;
    #pragma unroll
    for (int u = 0; u < 17; u++) {
        int j = j0 + u;
        if (j < 133) {
            float alo = 0.f, ahi = 0.f;
#define TAP(K, CLO, CHI) { float xv = w[K]; alo += (CLO) * xv; ahi += (CHI) * xv; }
            AFB_TAPS(TAP)
#undef TAP
            lo[ob + j * 512] = alo;
            hi[ob + j * 512] = ahi;
        }
        if (u < 16 && j < 132) {
            #pragma unroll
            for (int k = 0; k < 10; k++) w[k] = w[k + 2];
            w[10] = srow[ql][2 * j + 12];
            w[11] = srow[ql][2 * j + 13];
        }
    }
}

// ---------------- fused: final W-direction sfb -> NCHW output ---------------
__global__ __launch_bounds__(256) void sfb_w_last(const float* __restrict__ lo,
    const float* __restrict__ hi, float* __restrict__ out) {
    __shared__ float sout[256][33];
    int y = blockIdx.y, q0 = blockIdx.x * 32;
    int tid = threadIdx.x, ql = tid & 31, mm = tid >> 5;
    int m0 = mm * 32;
    const float* plo = lo + y * 133 * 512 + q0 + ql;
    const float* phi = hi + y * 133 * 512 + q0 + ql;
    int t0 = m0 >> 1;
    float wl[6], wh[6];
    #pragma unroll
    for (int k = 0; k < 6; k++) {
        wl[k] = plo[(t0 + k) * 512];
        wh[k] = phi[(t0 + k) * 512];
    }
    #pragma unroll
    for (int p = 0; p < 16; p++) {
        float ae = 0.f, ao = 0.f;
#define ETAP(KK, CLO, CHI) { ae += (CLO) * wl[KK]; ae += (CHI) * wh[KK]; }
        SFB_EVEN(ETAP)
#undef ETAP
#define OTAP(KK, CLO, CHI) { ao += (CLO) * wl[KK]; ao += (CHI) * wh[KK]; }
        SFB_ODD(OTAP)
#undef OTAP
        sout[m0 + 2 * p][ql]     = ae;
        sout[m0 + 2 * p + 1][ql] = ao;
        if (p < 15) {
            #pragma unroll
            for (int k = 0; k < 5; k++) { wl[k] = wl[k + 1]; wh[k] = wh[k + 1]; }
            int t = t0 + p + 6;
            wl[5] = plo[t * 512];
            wh[5] = phi[t * 512];
        }
    }
    __syncthreads();
    int obase = y * 256 + tid;
    #pragma unroll
    for (int i = 0; i < 32; i++)
        out[(q0 + i) * 65536 + obase] = sout[tid][i];
}

// ---------------- afb core (sliding window, 4 outputs/thread) ---------------
__device__ __forceinline__ void afb_core(
    const float* __restrict__ in, float* __restrict__ lo, float* __restrict__ hi,
    int nf_in, int nf_out, int sf_in, int so_in, int sf_out, int so_out,
    int bx, int by, int bz) {
    int lane = threadIdx.x & 31;
    int jj = threadIdx.x >> 5;
    int j0 = (bx * 8 + jj) * 4;
    if (j0 >= nf_out) return;
    int vo = bz * 128 + lane * 4;
    const float* pin = in + by * so_in + vo;
    int tb = 2 * j0 - 10;
    float4 w[12];
    #pragma unroll
    for (int k = 0; k < 12; k++) {
        int t = tb + k;
        t = (t < 0) ? (-1 - t) : ((t >= nf_in) ? (2 * nf_in - 1 - t) : t);
        w[k] = *(const float4*)(pin + t * sf_in);
    }
    int oo = by * so_out + j0 * sf_out + vo;
    float* plo = lo + oo;
    float* phi = hi + oo;
    #pragma unroll
    for (int u = 0; u < 4; u++) {
        if (j0 + u < nf_out) {
            float4 alo = {0.f,0.f,0.f,0.f}, ahi = {0.f,0.f,0.f,0.f};
#define TAP(K, CLO, CHI) { float4 xv = w[K];                                   \
            alo.x += (CLO) * xv.x; alo.y += (CLO) * xv.y;                      \
            alo.z += (CLO) * xv.z; alo.w += (CLO) * xv.w;                      \
            ahi.x += (CHI) * xv.x; ahi.y += (CHI) * xv.y;                      \
            ahi.z += (CHI) * xv.z; ahi.w += (CHI) * xv.w; }
            AFB_TAPS(TAP)
#undef TAP
            *(float4*)plo = alo;
            *(float4*)phi = ahi;
        }
        if (u < 3) {
            #pragma unroll
            for (int k = 0; k < 10; k++) w[k] = w[k + 2];
            int t0n = tb + 12 + 2 * u;
            int t1n = t0n + 1;
            t0n = (t0n >= nf_in) ? (2 * nf_in - 1 - t0n) : t0n;
            t1n = (t1n >= nf_in) ? (2 * nf_in - 1 - t1n) : t1n;
            w[10] = *(const float4*)(pin + t0n * sf_in);
            w[11] = *(const float4*)(pin + t1n * sf_in);
            plo += sf_out;
            phi += sf_out;
        }
    }
}

__global__ __launch_bounds__(256) void afb_kernel(
    const float* __restrict__ in, float* __restrict__ lo, float* __restrict__ hi,
    int nf_in, int nf_out, int sf_in, int so_in, int sf_out, int so_out) {
    afb_core(in, lo, hi, nf_in, nf_out, sf_in, so_in, sf_out, so_out,
             blockIdx.x, blockIdx.y, blockIdx.z);
}

__global__ __launch_bounds__(256) void afb_pair(
    const float* __restrict__ in0, float* __restrict__ lo0, float* __restrict__ hi0,
    const float* __restrict__ in1, float* __restrict__ lo1, float* __restrict__ hi1,
    int nf_in, int nf_out, int sf_in, int so_in, int sf_out, int so_out) {
    int sel = blockIdx.z >> 2, bz = blockIdx.z & 3;
    afb_core(sel ? in1 : in0, sel ? lo1 : lo0, sel ? hi1 : hi0,
             nf_in, nf_out, sf_in, so_in, sf_out, so_out,
             blockIdx.x, blockIdx.y, bz);
}

// ---------------- sfb core (sliding window, 4 outputs/thread) ---------------
__device__ __forceinline__ void sfb_core(
    const float* __restrict__ lo, const float* __restrict__ hi, float* __restrict__ out,
    int n_t, int nf_out, int sflo, int solo, int sfhi, int sohi,
    int sf_out, int so_out, int bx, int by, int bz) {
    int lane = threadIdx.x & 31;
    int mm = threadIdx.x >> 5;
    int m0 = (bx * 8 + mm) * 4;
    if (m0 >= nf_out) return;
    int vo = bz * 128 + lane * 4;
    const float* plo = lo + by * solo + vo;
    const float* phi = hi + by * sohi + vo;
    int t0 = m0 >> 1;
    float4 wl[6], wh[6];
    #pragma unroll
    for (int k = 0; k < 6; k++) {
        int t = t0 + k;
        bool ok = (unsigned)t < (unsigned)n_t;
        wl[k] = ok ? *(const float4*)(plo + t * sflo) : make_float4(0.f,0.f,0.f,0.f);
        wh[k] = ok ? *(const float4*)(phi + t * sfhi) : make_float4(0.f,0.f,0.f,0.f);
    }
    float* pout = out + by * so_out + m0 * sf_out + vo;
    #pragma unroll
    for (int p = 0; p < 2; p++) {
        float4 ae = {0.f,0.f,0.f,0.f}, ao = {0.f,0.f,0.f,0.f};
#define ETAP(KK, CLO, CHI) { float4 a = wl[KK]; float4 b = wh[KK];             \
        ae.x += (CLO)*a.x; ae.x += (CHI)*b.x;  ae.y += (CLO)*a.y; ae.y += (CHI)*b.y; \
        ae.z += (CLO)*a.z; ae.z += (CHI)*b.z;  ae.w += (CLO)*a.w; ae.w += (CHI)*b.w; }
        SFB_EVEN(ETAP)
#undef ETAP
#define OTAP(KK, CLO, CHI) { float4 a = wl[KK]; float4 b = wh[KK];             \
        ao.x += (CLO)*a.x; ao.x += (CHI)*b.x;  ao.y += (CLO)*a.y; ao.y += (CHI)*b.y; \
        ao.z += (CLO)*a.z; ao.z += (CHI)*b.z;  ao.w += (CLO)*a.w; ao.w += (CHI)*b.w; }
        SFB_ODD(OTAP)
#undef OTAP
        int me = m0 + 2 * p;
        if (me < nf_out)     *(float4*)pout = ae;
        if (me + 1 < nf_out) *(float4*)(pout + sf_out) = ao;
        if (p == 0) {
            #pragma unroll
            for (int k = 0; k < 5; k++) { wl[k] = wl[k + 1]; wh[k] = wh[k + 1]; }
            int t = t0 + 6;
            bool ok = (unsigned)t < (unsigned)n_t;
            wl[5] = ok ? *(const float4*)(plo + t * sflo) : make_float4(0.f,0.f,0.f,0.f);
            wh[5] = ok ? *(const float4*)(phi + t * sfhi) : make_float4(0.f,0.f,0.f,0.f);
            pout += 2 * sf_out;
        }
    }
}

__global__ __launch_bounds__(256) void sfb_kernel(
    const float* __restrict__ lo, const float* __restrict__ hi, float* __restrict__ out,
    int n_t, int nf_out, int sflo, int solo, int sfhi, int sohi,
    int sf_out, int so_out) {
    sfb_core(lo, hi, out, n_t, nf_out, sflo, solo, sfhi, sohi, sf_out, so_out,
             blockIdx.x, blockIdx.y, blockIdx.z);
}

__global__ __launch_bounds__(256) void sfb_pair(
    const float* __restrict__ lo0, const float* __restrict__ hi0, float* __restrict__ out0,
    const float* __restrict__ lo1, const float* __restrict__ hi1, float* __restrict__ out1,
    int n_t, int nf_out, int sflo0, int sflo1, int solo, int sfhi, int sohi,
    int sf_out, int so_out) {
    int sel = blockIdx.z >> 2, bz = blockIdx.z & 3;
    sfb_core(sel ? lo1 : lo0, sel ? hi1 : hi0, sel ? out1 : out0,
             n_t, nf_out, sel ? sflo1 : sflo0, solo, sfhi, sohi, sf_out, so_out,
             blockIdx.x, blockIdx.y, bz);
}

// ---------------- conv, 2 pixels/CTA, 64 threads/pixel, TR=6 (S=3 only) -----
__global__ __launch_bounds__(128, 4) void conv2(
    float* p0, float* p1, float* p2, int n) {
    constexpr int S = 3;
    constexpr int R = S * 8;          // 24
    constexpr int TR = R / 4;         // 6 rows per thread
    __shared__ float w_s[2][64 * 64];
    __shared__ float in_s[2][R * 64];
    int tid = threadIdx.x;
    int sel = tid >> 6, t = tid & 63;
    int jy = blockIdx.y, jx = blockIdx.x * 2 + sel;
    bool act = jx < n;
    long pix = 0;
    if (act) {
        float sc = (float)(64.0 / n);
        float yc = fminf(fmaxf((jy + 0.5f) * sc - 0.5f, 0.0f), 63.0f);
        float xc = fminf(fmaxf((jx + 0.5f) * sc - 0.5f, 0.0f), 63.0f);
        int y0 = (int)floorf(yc), x0 = (int)floorf(xc);
        int y1 = min(y0 + 1, 63), x1 = min(x0 + 1, 63);
        float ty = yc - (float)y0, tx = xc - (float)x0;
        float c00 = (1.f - ty) * (1.f - tx), c01 = (1.f - ty) * tx;
        float c10 = ty * (1.f - tx),         c11 = ty * tx;
        const float* w00 = g_wt + ((long)y0 * 64 + x0) * 4096;
        const float* w01 = g_wt + ((long)y0 * 64 + x1) * 4096;
        const float* w10 = g_wt + ((long)y1 * 64 + x0) * 4096;
        const float* w11 = g_wt + ((long)y1 * 64 + x1) * 4096;
        #pragma unroll 4
        for (int c = 0; c < 16; c++) {
            int e = c * 256 + t * 4;
            float4 a = *(const float4*)(w00 + e);
            float4 b = *(const float4*)(w01 + e);
            float4 d = *(const float4*)(w10 + e);
            float4 f = *(const float4*)(w11 + e);
            float4 wv;
            wv.x = c00 * a.x + c01 * b.x + c10 * d.x + c11 * f.x;
            wv.y = c00 * a.y + c01 * b.y + c10 * d.y + c11 * f.y;
            wv.z = c00 * a.z + c01 * b.z + c10 * d.z + c11 * f.z;
            wv.w = c00 * a.w + c01 * b.w + c10 * d.w + c11 * f.w;
            *(float4*)&w_s[sel][e] = wv;
        }
        pix = ((long)jy * n + jx) * V;
        #pragma unroll
        for (int l = 0; l < R / 4; l++) {
            int idx = l * 64 + t;
            int r = idx >> 4, i4 = (idx & 15) * 4;
            int ss = r >> 3, b = r & 7;
            const float* p = (ss == 0) ? p0 : (ss == 1) ? p1 : p2;
            *(float4*)&in_s[sel][r * 64 + i4] = *(const float4*)(p + pix + b * 64 + i4);
        }
    }
    __syncthreads();
    if (act) {
        int colg = t & 15, rowg = t >> 4;
        int o0 = colg * 4, r0 = rowg * TR;
        float4 acc[TR];
        #pragma unroll
        for (int r = 0; r < TR; r++) acc[r] = make_float4(0.f, 0.f, 0.f, 0.f);
        #pragma unroll 8
        for (int i = 0; i < 64; i += 4) {
            float4 w0 = *(const float4*)&w_s[sel][(i + 0) * 64 + o0];
            float4 w1 = *(const float4*)&w_s[sel][(i + 1) * 64 + o0];
            float4 w2 = *(const float4*)&w_s[sel][(i + 2) * 64 + o0];
            float4 w3 = *(const float4*)&w_s[sel][(i + 3) * 64 + o0];
            #pragma unroll
            for (int r = 0; r < TR; r++) {
                float4 v = *(const float4*)&in_s[sel][(r0 + r) * 64 + i];
                acc[r].x += v.x * w0.x; acc[r].y += v.x * w0.y;
                acc[r].z += v.x * w0.z; acc[r].w += v.x * w0.w;
                acc[r].x += v.y * w1.x; acc[r].y += v.y * w1.y;
                acc[r].z += v.y * w1.z; acc[r].w += v.y * w1.w;
                acc[r].x += v.z * w2.x; acc[r].y += v.z * w2.y;
                acc[r].z += v.z * w2.z; acc[r].w += v.z * w2.w;
                acc[r].x += v.w * w3.x; acc[r].y += v.w * w3.y;
                acc[r].z += v.w * w3.z; acc[r].w += v.w * w3.w;
            }
        }
        #pragma unroll
        for (int r = 0; r < TR; r++) {
            int rr = r0 + r;
            int ss = rr >> 3, b = rr & 7;
            float* p = (ss == 0) ? p0 : (ss == 1) ? p1 : p2;
            *(float4*)(p + pix + b * 64 + o0) = acc[r];
        }
    }
}

// ---------------- per-pixel conv (level 3, S=4) ----------------
template <int S>
__global__ __launch_bounds__(128, 4) void conv_kernel(
    float* p0, float* p1, float* p2, float* p3, int n) {
    constexpr int R  = S * 8;
    constexpr int TR = R / 8;
    __shared__ float w_s[64 * 64];    // [i][o]
    __shared__ float in_s[R * 64];    // [r][k]
    int jx = blockIdx.x, jy = blockIdx.y, tid = threadIdx.x;
    float sc = (float)(64.0 / n);
    float yc = fminf(fmaxf((jy + 0.5f) * sc - 0.5f, 0.0f), 63.0f);
    float xc = fminf(fmaxf((jx + 0.5f) * sc - 0.5f, 0.0f), 63.0f);
    int y0 = (int)floorf(yc), x0 = (int)floorf(xc);
    int y1 = min(y0 + 1, 63), x1 = min(x0 + 1, 63);
    float ty = yc - (float)y0, tx = xc - (float)x0;
    float c00 = (1.f - ty) * (1.f - tx), c01 = (1.f - ty) * tx;
    float c10 = ty * (1.f - tx),         c11 = ty * tx;
    const float* w00 = g_wt + ((long)y0 * 64 + x0) * 4096;
    const float* w01 = g_wt + ((long)y0 * 64 + x1) * 4096;
    const float* w10 = g_wt + ((long)y1 * 64 + x0) * 4096;
    const float* w11 = g_wt + ((long)y1 * 64 + x1) * 4096;
    #pragma unroll 4
    for (int c = 0; c < 8; c++) {
        int e = c * 512 + tid * 4;
        float4 a = *(const float4*)(w00 + e);
        float4 b = *(const float4*)(w01 + e);
        float4 d = *(const float4*)(w10 + e);
        float4 f = *(const float4*)(w11 + e);
        float4 wv;
        wv.x = c00 * a.x + c01 * b.x + c10 * d.x + c11 * f.x;
        wv.y = c00 * a.y + c01 * b.y + c10 * d.y + c11 * f.y;
        wv.z = c00 * a.z + c01 * b.z + c10 * d.z + c11 * f.z;
        wv.w = c00 * a.w + c01 * b.w + c10 * d.w + c11 * f.w;
        *(float4*)&w_s[e] = wv;
    }
    long pix = ((long)jy * n + jx) * V;
    {
        int b = tid >> 4, i4 = (tid & 15) * 4;
        #pragma unroll
        for (int ss = 0; ss < S; ss++) {
            const float* p = (ss == 0) ? p0 : (ss == 1) ? p1 : (ss == 2) ? p2 : p3;
            *(float4*)&in_s[(ss * 8 + b) * 64 + i4] = *(const float4*)(p + pix + b * 64 + i4);
        }
    }
    __syncthreads();
    int colg = tid & 15, rowg = tid >> 4;
    int o0 = colg * 4, r0 = rowg * TR;
    float4 acc[TR];
    #pragma unroll
    for (int r = 0; r < TR; r++) acc[r] = make_float4(0.f, 0.f, 0.f, 0.f);
    #pragma unroll 8
    for (int i = 0; i < 64; i += 4) {
        float4 w0 = *(const float4*)&w_s[(i + 0) * 64 + o0];
        float4 w1 = *(const float4*)&w_s[(i + 1) * 64 + o0];
        float4 w2 = *(const float4*)&w_s[(i + 2) * 64 + o0];
        float4 w3 = *(const float4*)&w_s[(i + 3) * 64 + o0];
        #pragma unroll
        for (int r = 0; r < TR; r++) {
            float4 v = *(const float4*)&in_s[(r0 + r) * 64 + i];
            acc[r].x += v.x * w0.x; acc[r].y += v.x * w0.y;
            acc[r].z += v.x * w0.z; acc[r].w += v.x * w0.w;
            acc[r].x += v.y * w1.x; acc[r].y += v.y * w1.y;
            acc[r].z += v.y * w1.z; acc[r].w += v.y * w1.w;
            acc[r].x += v.z * w2.x; acc[r].y += v.z * w2.y;
            acc[r].z += v.z * w2.z; acc[r].w += v.z * w2.w;
            acc[r].x += v.w * w3.x; acc[r].y += v.w * w3.y;
            acc[r].z += v.w * w3.z; acc[r].w += v.w * w3.w;
        }
    }
    #pragma unroll
    for (int r = 0; r < TR; r++) {
        int rr = r0 + r;
        int ss = rr >> 3, b = rr & 7;
        float* p = (ss == 0) ? p0 : (ss == 1) ? p1 : (ss == 2) ? p2 : p3;
        *(float4*)(p + pix + b * 64 + o0) = acc[r];
    }
}

// ---------------- host ----------------
#define SYM(var, sym) float* var; { void* _p; cudaGetSymbolAddress(&_p, sym); var = (float*)_p; }

extern "C" void kernel_launch(void* const* d_in, const int* in_sizes, int n_in,
                              void* d_out, int out_size) {
    const float* x = (const float*)d_in[0];
    const float* w = (const float*)d_in[1];
    float* out = (float*)d_out;
    SYM(TLO, g_tlo) SYM(THI, g_thi)
    SYM(LL1, g_ll1) SYM(LH1, g_lh1) SYM(HL1, g_hl1) SYM(HH1, g_hh1)
    SYM(LL2, g_ll2) SYM(LH2, g_lh2) SYM(HL2, g_hl2) SYM(HH2, g_hh2)
    SYM(LL3, g_ll3) SYM(LH3, g_lh3) SYM(HL3, g_hl3) SYM(HH3, g_hh3)
    SYM(R2, g_r2)  SYM(WT, g_wt)

    // #1..#3
    wtrans2<<<dim3(8, 2, 128), 256>>>(w, WT);
    afb_w_first<<<dim3(16, 256), 256>>>(x, TLO, THI);
    afb_pair<<<dim3(5, 133, 8), 256>>>(TLO, LL1, LH1, THI, HL1, HH1,
                                       256, 133, 133*512, 512, 133*512, 512);
    // #4: the dominant conv — profiled slot
    conv2<<<dim3(67, 133), 128>>>(LH1, HL1, HH1, 133);
    // remaining DWT
    afb_kernel<<<dim3(3, 133, 4), 256>>>(LL1, TLO, THI, 133, 72, 512, 133*512, 512, 72*512);
    afb_pair<<<dim3(3, 72, 8), 256>>>(TLO, LL2, LH2, THI, HL2, HH2,
                                      133, 72, 72*512, 512, 72*512, 512);
    conv2<<<dim3(36, 72), 128>>>(LH2, HL2, HH2, 72);
    afb_kernel<<<dim3(2, 72, 4), 256>>>(LL2, TLO, THI, 72, 41, 512, 72*512, 512, 41*512);
    afb_pair<<<dim3(2, 41, 8), 256>>>(TLO, LL3, LH3, THI, HL3, HH3,
                                      72, 41, 41*512, 512, 41*512, 512);
    conv_kernel<4><<<dim3(41, 41), 128>>>(LL3, LH3, HL3, HH3, 41);

    // ---- IDWT ----
    sfb_pair<<<dim3(3, 41, 8), 256>>>(LL3, LH3, TLO, HL3, HH3, THI,
        41, 72, 41*512, 41*512, 512, 41*512, 512, 41*512, 512);
    sfb_kernel<<<dim3(3, 72, 4), 256>>>(TLO, THI, LL2, 41, 72,
        512, 41*512, 512, 41*512, 512, 72*512);
    sfb_pair<<<dim3(5, 72, 8), 256>>>(LL2, LH2, TLO, HL2, HH2, THI,
        72, 134, 72*512, 72*512, 512, 72*512, 512, 72*512, 512);
    sfb_kernel<<<dim3(5, 134, 4), 256>>>(TLO, THI, R2, 72, 134,
        512, 72*512, 512, 72*512, 512, 134*512);
    sfb_pair<<<dim3(8, 133, 8), 256>>>(R2, LH1, TLO, HL1, HH1, THI,
        133, 256, 134*512, 133*512, 512, 133*512, 512, 133*512, 512);
    sfb_w_last<<<dim3(16, 256), 256>>>(TLO, THI, out);
}

// round 12
// speedup vs baseline: 1.0507x; 1.0348x over previous
#include <cuda_runtime.h>

#define V 512

// ---------------- scratch (device globals; no runtime alloc) ----------------
__device__ float g_tlo[256*133*V];
__device__ float g_thi[256*133*V];
__device__ float g_ll1[133*133*V];
__device__ float g_lh1[133*133*V];
__device__ float g_hl1[133*133*V];
__device__ float g_hh1[133*133*V];
__device__ float g_ll2[72*72*V];
__device__ float g_lh2[72*72*V];
__device__ float g_hl2[72*72*V];
__device__ float g_hh2[72*72*V];
__device__ float g_ll3[41*41*V];
__device__ float g_lh3[41*41*V];
__device__ float g_hl3[41*41*V];
__device__ float g_hh3[41*41*V];
__device__ float g_r2 [134*134*V];
__device__ float g_wt [64*64*64*64]; // weights transposed to [gy*64+gx][i][o]

// ---------------- filter taps as literal constants ----------------
#define AFB_TAPS(X) \
  X(0,  0.11154074335008017f,    -0.00107730108499558f)   \
  X(1,  0.4946238903983854f,     -0.004777257511010651f)  \
  X(2,  0.7511339080215775f,      0.0005538422009938016f) \
  X(3,  0.3152503517092432f,      0.031582039318031156f)  \
  X(4, -0.22626469396516913f,     0.02752286553001629f)   \
  X(5, -0.12976686756709563f,    -0.09750160558707936f)   \
  X(6,  0.09750160558707936f,    -0.12976686756709563f)   \
  X(7,  0.02752286553001629f,     0.22626469396516913f)   \
  X(8, -0.031582039318031156f,    0.3152503517092432f)    \
  X(9,  0.0005538422009938016f,  -0.7511339080215775f)    \
  X(10, 0.004777257511010651f,    0.4946238903983854f)    \
  X(11,-0.00107730108499558f,    -0.11154074335008017f)

#define SFB_EVEN(X) \
  X(0,  0.004777257511010651f,    0.4946238903983854f)    \
  X(1, -0.031582039318031156f,    0.3152503517092432f)    \
  X(2,  0.09750160558707936f,    -0.12976686756709563f)   \
  X(3, -0.22626469396516913f,     0.02752286553001629f)   \
  X(4,  0.7511339080215775f,      0.0005538422009938016f) \
  X(5,  0.11154074335008017f,    -0.00107730108499558f)
#define SFB_ODD(X) \
  X(0, -0.00107730108499558f,    -0.11154074335008017f)   \
  X(1,  0.0005538422009938016f,  -0.7511339080215775f)    \
  X(2,  0.02752286553001629f,     0.22626469396516913f)   \
  X(3, -0.12976686756709563f,    -0.09750160558707936f)   \
  X(4,  0.3152503517092432f,      0.031582039318031156f)  \
  X(5,  0.4946238903983854f,     -0.004777257511010651f)

// ---------------- weight transpose: in[i][o][c] -> out[c][i][o] -------------
__global__ __launch_bounds__(256) void wtrans2(const float* __restrict__ in,
                                               float* __restrict__ out) {
    __shared__ float t[8][32][33];
    int i0 = blockIdx.x * 8, o0 = blockIdx.y * 32, c0 = blockIdx.z * 32;
    int tid = threadIdx.x;
    for (int l = tid; l < 8192; l += 256) {
        int ii = l >> 10, rest = l & 1023;
        int oy = rest >> 5, cx = rest & 31;
        t[ii][oy][cx] = in[(long)(i0 + ii) * 262144 + (long)(o0 + oy) * 4096 + c0 + cx];
    }
    __syncthreads();
    int ii = tid >> 5, ox = tid & 31;
    long ob = (long)(i0 + ii) * 64 + o0 + ox;
    #pragma unroll
    for (int cr = 0; cr < 32; cr++)
        out[(long)(c0 + cr) * 4096 + ob] = t[ii][ox][cr];
}

// ---------------- fused: NCHW input -> level-1 W-direction afb -> HWC -------
__global__ __launch_bounds__(256) void afb_w_first(const float* __restrict__ x,
    float* __restrict__ lo, float* __restrict__ hi) {
    __shared__ float srow[32][277];
    int y = blockIdx.y, q0 = blockIdx.x * 32;
    int tid = threadIdx.x;
    for (int idx = tid; idx < 32 * 276; idx += 256) {
        int ql = idx / 276, ew = idx - ql * 276;
        int t = ew - 10;
        t = (t < 0) ? (-1 - t) : ((t >= 256) ? (511 - t) : t);
        srow[ql][ew] = x[(q0 + ql) * 65536 + y * 256 + t];
    }
    __syncthreads();
    int ql = tid & 31, jj = tid >> 5;
    int j0 = jj * 17;
    float w[12];
    #pragma unroll
    for (int k = 0; k < 12; k++) w[k] = srow[ql][2 * j0 + k];
    int ob = y * 133 * 512 + q0 + ql;
    #pragma unroll
    for (int u = 0; u < 17; u++) {
        int j = j0 + u;
        if (j < 133) {
            float alo = 0.f, ahi = 0.f;
#define TAP(K, CLO, CHI) { float xv = w[K]; alo += (CLO) * xv; ahi += (CHI) * xv; }
            AFB_TAPS(TAP)
#undef TAP
            lo[ob + j * 512] = alo;
            hi[ob + j * 512] = ahi;
        }
        if (u < 16 && j < 132) {
            #pragma unroll
            for (int k = 0; k < 10; k++) w[k] = w[k + 2];
            w[10] = srow[ql][2 * j + 12];
            w[11] = srow[ql][2 * j + 13];
        }
    }
}

// ---------------- fused: final W-direction sfb -> NCHW output ---------------
__global__ __launch_bounds__(256) void sfb_w_last(const float* __restrict__ lo,
    const float* __restrict__ hi, float* __restrict__ out) {
    __shared__ float sout[256][33];
    int y = blockIdx.y, q0 = blockIdx.x * 32;
    int tid = threadIdx.x, ql = tid & 31, mm = tid >> 5;
    int m0 = mm * 32;
    const float* plo = lo + y * 133 * 512 + q0 + ql;
    const float* phi = hi + y * 133 * 512 + q0 + ql;
    int t0 = m0 >> 1;
    float wl[6], wh[6];
    #pragma unroll
    for (int k = 0; k < 6; k++) {
        wl[k] = plo[(t0 + k) * 512];
        wh[k] = phi[(t0 + k) * 512];
    }
    #pragma unroll
    for (int p = 0; p < 16; p++) {
        float ae = 0.f, ao = 0.f;
#define ETAP(KK, CLO, CHI) { ae += (CLO) * wl[KK]; ae += (CHI) * wh[KK]; }
        SFB_EVEN(ETAP)
#undef ETAP
#define OTAP(KK, CLO, CHI) { ao += (CLO) * wl[KK]; ao += (CHI) * wh[KK]; }
        SFB_ODD(OTAP)
#undef OTAP
        sout[m0 + 2 * p][ql]     = ae;
        sout[m0 + 2 * p + 1][ql] = ao;
        if (p < 15) {
            #pragma unroll
            for (int k = 0; k < 5; k++) { wl[k] = wl[k + 1]; wh[k] = wh[k + 1]; }
            int t = t0 + p + 6;
            wl[5] = plo[t * 512];
            wh[5] = phi[t * 512];
        }
    }
    __syncthreads();
    int obase = y * 256 + tid;
    #pragma unroll
    for (int i = 0; i < 32; i++)
        out[(q0 + i) * 65536 + obase] = sout[tid][i];
}

// ---------------- afb core (sliding window, 4 outputs/thread) ---------------
__device__ __forceinline__ void afb_core(
    const float* __restrict__ in, float* __restrict__ lo, float* __restrict__ hi,
    int nf_in, int nf_out, int sf_in, int so_in, int sf_out, int so_out,
    int bx, int by, int bz) {
    int lane = threadIdx.x & 31;
    int jj = threadIdx.x >> 5;
    int j0 = (bx * 8 + jj) * 4;
    if (j0 >= nf_out) return;
    int vo = bz * 128 + lane * 4;
    const float* pin = in + by * so_in + vo;
    int tb = 2 * j0 - 10;
    float4 w[12];
    #pragma unroll
    for (int k = 0; k < 12; k++) {
        int t = tb + k;
        t = (t < 0) ? (-1 - t) : ((t >= nf_in) ? (2 * nf_in - 1 - t) : t);
        w[k] = *(const float4*)(pin + t * sf_in);
    }
    int oo = by * so_out + j0 * sf_out + vo;
    float* plo = lo + oo;
    float* phi = hi + oo;
    #pragma unroll
    for (int u = 0; u < 4; u++) {
        if (j0 + u < nf_out) {
            float4 alo = {0.f,0.f,0.f,0.f}, ahi = {0.f,0.f,0.f,0.f};
#define TAP(K, CLO, CHI) { float4 xv = w[K];                                   \
            alo.x += (CLO) * xv.x; alo.y += (CLO) * xv.y;                      \
            alo.z += (CLO) * xv.z; alo.w += (CLO) * xv.w;                      \
            ahi.x += (CHI) * xv.x; ahi.y += (CHI) * xv.y;                      \
            ahi.z += (CHI) * xv.z; ahi.w += (CHI) * xv.w; }
            AFB_TAPS(TAP)
#undef TAP
            *(float4*)plo = alo;
            *(float4*)phi = ahi;
        }
        if (u < 3) {
            #pragma unroll
            for (int k = 0; k < 10; k++) w[k] = w[k + 2];
            int t0n = tb + 12 + 2 * u;
            int t1n = t0n + 1;
            t0n = (t0n >= nf_in) ? (2 * nf_in - 1 - t0n) : t0n;
            t1n = (t1n >= nf_in) ? (2 * nf_in - 1 - t1n) : t1n;
            w[10] = *(const float4*)(pin + t0n * sf_in);
            w[11] = *(const float4*)(pin + t1n * sf_in);
            plo += sf_out;
            phi += sf_out;
        }
    }
}

__global__ __launch_bounds__(256) void afb_kernel(
    const float* __restrict__ in, float* __restrict__ lo, float* __restrict__ hi,
    int nf_in, int nf_out, int sf_in, int so_in, int sf_out, int so_out) {
    afb_core(in, lo, hi, nf_in, nf_out, sf_in, so_in, sf_out, so_out,
             blockIdx.x, blockIdx.y, blockIdx.z);
}

__global__ __launch_bounds__(256) void afb_pair(
    const float* __restrict__ in0, float* __restrict__ lo0, float* __restrict__ hi0,
    const float* __restrict__ in1, float* __restrict__ lo1, float* __restrict__ hi1,
    int nf_in, int nf_out, int sf_in, int so_in, int sf_out, int so_out) {
    int sel = blockIdx.z >> 2, bz = blockIdx.z & 3;
    afb_core(sel ? in1 : in0, sel ? lo1 : lo0, sel ? hi1 : hi0,
             nf_in, nf_out, sf_in, so_in, sf_out, so_out,
             blockIdx.x, blockIdx.y, bz);
}

// ---------------- sfb core (sliding window, 4 outputs/thread) ---------------
__device__ __forceinline__ void sfb_core(
    const float* __restrict__ lo, const float* __restrict__ hi, float* __restrict__ out,
    int n_t, int nf_out, int sflo, int solo, int sfhi, int sohi,
    int sf_out, int so_out, int bx, int by, int bz) {
    int lane = threadIdx.x & 31;
    int mm = threadIdx.x >> 5;
    int m0 = (bx * 8 + mm) * 4;
    if (m0 >= nf_out) return;
    int vo = bz * 128 + lane * 4;
    const float* plo = lo + by * solo + vo;
    const float* phi = hi + by * sohi + vo;
    int t0 = m0 >> 1;
    float4 wl[6], wh[6];
    #pragma unroll
    for (int k = 0; k < 6; k++) {
        int t = t0 + k;
        bool ok = (unsigned)t < (unsigned)n_t;
        wl[k] = ok ? *(const float4*)(plo + t * sflo) : make_float4(0.f,0.f,0.f,0.f);
        wh[k] = ok ? *(const float4*)(phi + t * sfhi) : make_float4(0.f,0.f,0.f,0.f);
    }
    float* pout = out + by * so_out + m0 * sf_out + vo;
    #pragma unroll
    for (int p = 0; p < 2; p++) {
        float4 ae = {0.f,0.f,0.f,0.f}, ao = {0.f,0.f,0.f,0.f};
#define ETAP(KK, CLO, CHI) { float4 a = wl[KK]; float4 b = wh[KK];             \
        ae.x += (CLO)*a.x; ae.x += (CHI)*b.x;  ae.y += (CLO)*a.y; ae.y += (CHI)*b.y; \
        ae.z += (CLO)*a.z; ae.z += (CHI)*b.z;  ae.w += (CLO)*a.w; ae.w += (CHI)*b.w; }
        SFB_EVEN(ETAP)
#undef ETAP
#define OTAP(KK, CLO, CHI) { float4 a = wl[KK]; float4 b = wh[KK];             \
        ao.x += (CLO)*a.x; ao.x += (CHI)*b.x;  ao.y += (CLO)*a.y; ao.y += (CHI)*b.y; \
        ao.z += (CLO)*a.z; ao.z += (CHI)*b.z;  ao.w += (CLO)*a.w; ao.w += (CHI)*b.w; }
        SFB_ODD(OTAP)
#undef OTAP
        int me = m0 + 2 * p;
        if (me < nf_out)     *(float4*)pout = ae;
        if (me + 1 < nf_out) *(float4*)(pout + sf_out) = ao;
        if (p == 0) {
            #pragma unroll
            for (int k = 0; k < 5; k++) { wl[k] = wl[k + 1]; wh[k] = wh[k + 1]; }
            int t = t0 + 6;
            bool ok = (unsigned)t < (unsigned)n_t;
            wl[5] = ok ? *(const float4*)(plo + t * sflo) : make_float4(0.f,0.f,0.f,0.f);
            wh[5] = ok ? *(const float4*)(phi + t * sfhi) : make_float4(0.f,0.f,0.f,0.f);
            pout += 2 * sf_out;
        }
    }
}

__global__ __launch_bounds__(256) void sfb_kernel(
    const float* __restrict__ lo, const float* __restrict__ hi, float* __restrict__ out,
    int n_t, int nf_out, int sflo, int solo, int sfhi, int sohi,
    int sf_out, int so_out) {
    sfb_core(lo, hi, out, n_t, nf_out, sflo, solo, sfhi, sohi, sf_out, so_out,
             blockIdx.x, blockIdx.y, blockIdx.z);
}

__global__ __launch_bounds__(256) void sfb_pair(
    const float* __restrict__ lo0, const float* __restrict__ hi0, float* __restrict__ out0,
    const float* __restrict__ lo1, const float* __restrict__ hi1, float* __restrict__ out1,
    int n_t, int nf_out, int sflo0, int sflo1, int solo, int sfhi, int sohi,
    int sf_out, int so_out) {
    int sel = blockIdx.z >> 2, bz = blockIdx.z & 3;
    sfb_core(sel ? lo1 : lo0, sel ? hi1 : hi0, sel ? out1 : out0,
             n_t, nf_out, sel ? sflo1 : sflo0, solo, sfhi, sohi, sf_out, so_out,
             blockIdx.x, blockIdx.y, bz);
}

// ---------------- conv, 2 pixels/CTA, 64 threads/pixel, TR=6 (S=3 only) -----
// w_s stride 64 (reads are 64-consecutive-float spans, conflict-free);
// in_s stride 68 (row-pair delta 6*68 % 32 != 0 -> conflict-free broadcasts).
__global__ __launch_bounds__(128, 4) void conv2(
    float* p0, float* p1, float* p2, int n) {
    constexpr int S = 3;
    constexpr int R = S * 8;          // 24
    constexpr int TR = R / 4;         // 6 rows per thread
    __shared__ float w_s[2][64 * 64];
    __shared__ float in_s[2][R * 68];
    int tid = threadIdx.x;
    int sel = tid >> 6, t = tid & 63;
    int jy = blockIdx.y, jx = blockIdx.x * 2 + sel;
    bool act = jx < n;
    long pix = 0;
    if (act) {
        float sc = (float)(64.0 / n);
        float yc = fminf(fmaxf((jy + 0.5f) * sc - 0.5f, 0.0f), 63.0f);
        float xc = fminf(fmaxf((jx + 0.5f) * sc - 0.5f, 0.0f), 63.0f);
        int y0 = (int)floorf(yc), x0 = (int)floorf(xc);
        int y1 = min(y0 + 1, 63), x1 = min(x0 + 1, 63);
        float ty = yc - (float)y0, tx = xc - (float)x0;
        float c00 = (1.f - ty) * (1.f - tx), c01 = (1.f - ty) * tx;
        float c10 = ty * (1.f - tx),         c11 = ty * tx;
        const float* w00 = g_wt + ((long)y0 * 64 + x0) * 4096;
        const float* w01 = g_wt + ((long)y0 * 64 + x1) * 4096;
        const float* w10 = g_wt + ((long)y1 * 64 + x0) * 4096;
        const float* w11 = g_wt + ((long)y1 * 64 + x1) * 4096;
        #pragma unroll 4
        for (int c = 0; c < 16; c++) {
            int e = c * 256 + t * 4;
            float4 a = *(const float4*)(w00 + e);
            float4 b = *(const float4*)(w01 + e);
            float4 d = *(const float4*)(w10 + e);
            float4 f = *(const float4*)(w11 + e);
            float4 wv;
            wv.x = c00 * a.x + c01 * b.x + c10 * d.x + c11 * f.x;
            wv.y = c00 * a.y + c01 * b.y + c10 * d.y + c11 * f.y;
            wv.z = c00 * a.z + c01 * b.z + c10 * d.z + c11 * f.z;
            wv.w = c00 * a.w + c01 * b.w + c10 * d.w + c11 * f.w;
            *(float4*)&w_s[sel][e] = wv;
        }
        pix = ((long)jy * n + jx) * V;
        #pragma unroll
        for (int l = 0; l < R / 4; l++) {
            int idx = l * 64 + t;
            int r = idx >> 4, i4 = (idx & 15) * 4;
            int ss = r >> 3, b = r & 7;
            const float* p = (ss == 0) ? p0 : (ss == 1) ? p1 : p2;
            *(float4*)&in_s[sel][r * 68 + i4] = *(const float4*)(p + pix + b * 64 + i4);
        }
    }
    __syncthreads();
    if (act) {
        int colg = t & 15, rowg = t >> 4;
        int o0 = colg * 4, r0 = rowg * TR;
        float4 acc[TR];
        #pragma unroll
        for (int r = 0; r < TR; r++) acc[r] = make_float4(0.f, 0.f, 0.f, 0.f);
        #pragma unroll 8
        for (int i = 0; i < 64; i += 4) {
            float4 w0 = *(const float4*)&w_s[sel][(i + 0) * 64 + o0];
            float4 w1 = *(const float4*)&w_s[sel][(i + 1) * 64 + o0];
            float4 w2 = *(const float4*)&w_s[sel][(i + 2) * 64 + o0];
            float4 w3 = *(const float4*)&w_s[sel][(i + 3) * 64 + o0];
            #pragma unroll
            for (int r = 0; r < TR; r++) {
                float4 v = *(const float4*)&in_s[sel][(r0 + r) * 68 + i];
                acc[r].x += v.x * w0.x; acc[r].y += v.x * w0.y;
                acc[r].z += v.x * w0.z; acc[r].w += v.x * w0.w;
                acc[r].x += v.y * w1.x; acc[r].y += v.y * w1.y;
                acc[r].z += v.y * w1.z; acc[r].w += v.y * w1.w;
                acc[r].x += v.z * w2.x; acc[r].y += v.z * w2.y;
                acc[r].z += v.z * w2.z; acc[r].w += v.z * w2.w;
                acc[r].x += v.w * w3.x; acc[r].y += v.w * w3.y;
                acc[r].z += v.w * w3.z; acc[r].w += v.w * w3.w;
            }
        }
        #pragma unroll
        for (int r = 0; r < TR; r++) {
            int rr = r0 + r;
            int ss = rr >> 3, b = rr & 7;
            float* p = (ss == 0) ? p0 : (ss == 1) ? p1 : p2;
            *(float4*)(p + pix + b * 64 + o0) = acc[r];
        }
    }
}

// ---------------- per-pixel conv (level 3, S=4) ----------------
template <int S>
__global__ __launch_bounds__(128, 4) void conv_kernel(
    float* p0, float* p1, float* p2, float* p3, int n) {
    constexpr int R  = S * 8;
    constexpr int TR = R / 8;
    __shared__ float w_s[64 * 64];    // [i][o]
    __shared__ float in_s[R * 68];    // [r][k], padded
    int jx = blockIdx.x, jy = blockIdx.y, tid = threadIdx.x;
    float sc = (float)(64.0 / n);
    float yc = fminf(fmaxf((jy + 0.5f) * sc - 0.5f, 0.0f), 63.0f);
    float xc = fminf(fmaxf((jx + 0.5f) * sc - 0.5f, 0.0f), 63.0f);
    int y0 = (int)floorf(yc), x0 = (int)floorf(xc);
    int y1 = min(y0 + 1, 63), x1 = min(x0 + 1, 63);
    float ty = yc - (float)y0, tx = xc - (float)x0;
    float c00 = (1.f - ty) * (1.f - tx), c01 = (1.f - ty) * tx;
    float c10 = ty * (1.f - tx),         c11 = ty * tx;
    const float* w00 = g_wt + ((long)y0 * 64 + x0) * 4096;
    const float* w01 = g_wt + ((long)y0 * 64 + x1) * 4096;
    const float* w10 = g_wt + ((long)y1 * 64 + x0) * 4096;
    const float* w11 = g_wt + ((long)y1 * 64 + x1) * 4096;
    #pragma unroll 4
    for (int c = 0; c < 8; c++) {
        int e = c * 512 + tid * 4;
        float4 a = *(const float4*)(w00 + e);
        float4 b = *(const float4*)(w01 + e);
        float4 d = *(const float4*)(w10 + e);
        float4 f = *(const float4*)(w11 + e);
        float4 wv;
        wv.x = c00 * a.x + c01 * b.x + c10 * d.x + c11 * f.x;
        wv.y = c00 * a.y + c01 * b.y + c10 * d.y + c11 * f.y;
        wv.z = c00 * a.z + c01 * b.z + c10 * d.z + c11 * f.z;
        wv.w = c00 * a.w + c01 * b.w + c10 * d.w + c11 * f.w;
        *(float4*)&w_s[e] = wv;
    }
    long pix = ((long)jy * n + jx) * V;
    {
        int b = tid >> 4, i4 = (tid & 15) * 4;
        #pragma unroll
        for (int ss = 0; ss < S; ss++) {
            const float* p = (ss == 0) ? p0 : (ss == 1) ? p1 : (ss == 2) ? p2 : p3;
            *(float4*)&in_s[(ss * 8 + b) * 68 + i4] = *(const float4*)(p + pix + b * 64 + i4);
        }
    }
    __syncthreads();
    int colg = tid & 15, rowg = tid >> 4;
    int o0 = colg * 4, r0 = rowg * TR;
    float4 acc[TR];
    #pragma unroll
    for (int r = 0; r < TR; r++) acc[r] = make_float4(0.f, 0.f, 0.f, 0.f);
    #pragma unroll 8
    for (int i = 0; i < 64; i += 4) {
        float4 w0 = *(const float4*)&w_s[(i + 0) * 64 + o0];
        float4 w1 = *(const float4*)&w_s[(i + 1) * 64 + o0];
        float4 w2 = *(const float4*)&w_s[(i + 2) * 64 + o0];
        float4 w3 = *(const float4*)&w_s[(i + 3) * 64 + o0];
        #pragma unroll
        for (int r = 0; r < TR; r++) {
            float4 v = *(const float4*)&in_s[(r0 + r) * 68 + i];
            acc[r].x += v.x * w0.x; acc[r].y += v.x * w0.y;
            acc[r].z += v.x * w0.z; acc[r].w += v.x * w0.w;
            acc[r].x += v.y * w1.x; acc[r].y += v.y * w1.y;
            acc[r].z += v.y * w1.z; acc[r].w += v.y * w1.w;
            acc[r].x += v.z * w2.x; acc[r].y += v.z * w2.y;
            acc[r].z += v.z * w2.z; acc[r].w += v.z * w2.w;
            acc[r].x += v.w * w3.x; acc[r].y += v.w * w3.y;
            acc[r].z += v.w * w3.z; acc[r].w += v.w * w3.w;
        }
    }
    #pragma unroll
    for (int r = 0; r < TR; r++) {
        int rr = r0 + r;
        int ss = rr >> 3, b = rr & 7;
        float* p = (ss == 0) ? p0 : (ss == 1) ? p1 : (ss == 2) ? p2 : p3;
        *(float4*)(p + pix + b * 64 + o0) = acc[r];
    }
}

// ---------------- host ----------------
#define SYM(var, sym) float* var; { void* _p; cudaGetSymbolAddress(&_p, sym); var = (float*)_p; }

extern "C" void kernel_launch(void* const* d_in, const int* in_sizes, int n_in,
                              void* d_out, int out_size) {
    const float* x = (const float*)d_in[0];
    const float* w = (const float*)d_in[1];
    float* out = (float*)d_out;
    SYM(TLO, g_tlo) SYM(THI, g_thi)
    SYM(LL1, g_ll1) SYM(LH1, g_lh1) SYM(HL1, g_hl1) SYM(HH1, g_hh1)
    SYM(LL2, g_ll2) SYM(LH2, g_lh2) SYM(HL2, g_hl2) SYM(HH2, g_hh2)
    SYM(LL3, g_ll3) SYM(LH3, g_lh3) SYM(HL3, g_hl3) SYM(HH3, g_hh3)
    SYM(R2, g_r2)  SYM(WT, g_wt)

    // #1..#3
    wtrans2<<<dim3(8, 2, 128), 256>>>(w, WT);
    afb_w_first<<<dim3(16, 256), 256>>>(x, TLO, THI);
    afb_pair<<<dim3(5, 133, 8), 256>>>(TLO, LL1, LH1, THI, HL1, HH1,
                                       256, 133, 133*512, 512, 133*512, 512);
    // #4: the dominant conv — profiled slot
    conv2<<<dim3(67, 133), 128>>>(LH1, HL1, HH1, 133);
    // remaining DWT
    afb_kernel<<<dim3(3, 133, 4), 256>>>(LL1, TLO, THI, 133, 72, 512, 133*512, 512, 72*512);
    afb_pair<<<dim3(3, 72, 8), 256>>>(TLO, LL2, LH2, THI, HL2, HH2,
                                      133, 72, 72*512, 512, 72*512, 512);
    conv2<<<dim3(36, 72), 128>>>(LH2, HL2, HH2, 72);
    afb_kernel<<<dim3(2, 72, 4), 256>>>(LL2, TLO, THI, 72, 41, 512, 72*512, 512, 41*512);
    afb_pair<<<dim3(2, 41, 8), 256>>>(TLO, LL3, LH3, THI, HL3, HH3,
                                      72, 41, 41*512, 512, 41*512, 512);
    conv_kernel<4><<<dim3(41, 41), 128>>>(LL3, LH3, HL3, HH3, 41);

    // ---- IDWT ----
    sfb_pair<<<dim3(3, 41, 8), 256>>>(LL3, LH3, TLO, HL3, HH3, THI,
        41, 72, 41*512, 41*512, 512, 41*512, 512, 41*512, 512);
    sfb_kernel<<<dim3(3, 72, 4), 256>>>(TLO, THI, LL2, 41, 72,
        512, 41*512, 512, 41*512, 512, 72*512);
    sfb_pair<<<dim3(5, 72, 8), 256>>>(LL2, LH2, TLO, HL2, HH2, THI,
        72, 134, 72*512, 72*512, 512, 72*512, 512, 72*512, 512);
    sfb_kernel<<<dim3(5, 134, 4), 256>>>(TLO, THI, R2, 72, 134,
        512, 72*512, 512, 72*512, 512, 134*512);
    sfb_pair<<<dim3(8, 133, 8), 256>>>(R2, LH1, TLO, HL1, HH1, THI,
        133, 256, 134*512, 133*512, 512, 133*512, 512, 133*512, 512);
    sfb_w_last<<<dim3(16, 256), 256>>>(TLO, THI, out);
}

// round 13
// speedup vs baseline: 1.1055x; 1.0522x over previous
#include <cuda_runtime.h>

#define V 512

// ---------------- scratch (device globals; no runtime alloc) ----------------
__device__ float g_tlo[256*133*V];
__device__ float g_thi[256*133*V];
__device__ float g_ll1[133*133*V];
__device__ float g_lh1[133*133*V];
__device__ float g_hl1[133*133*V];
__device__ float g_hh1[133*133*V];
__device__ float g_ll2[72*72*V];
__device__ float g_lh2[72*72*V];
__device__ float g_hl2[72*72*V];
__device__ float g_hh2[72*72*V];
__device__ float g_ll3[41*41*V];
__device__ float g_lh3[41*41*V];
__device__ float g_hl3[41*41*V];
__device__ float g_hh3[41*41*V];
__device__ float g_r2 [134*134*V];
__device__ float g_wt [64*64*64*64]; // weights transposed to [gy*64+gx][i][o]

// ---------------- filter taps as literal constants ----------------
#define AFB_TAPS(X) \
  X(0,  0.11154074335008017f,    -0.00107730108499558f)   \
  X(1,  0.4946238903983854f,     -0.004777257511010651f)  \
  X(2,  0.7511339080215775f,      0.0005538422009938016f) \
  X(3,  0.3152503517092432f,      0.031582039318031156f)  \
  X(4, -0.22626469396516913f,     0.02752286553001629f)   \
  X(5, -0.12976686756709563f,    -0.09750160558707936f)   \
  X(6,  0.09750160558707936f,    -0.12976686756709563f)   \
  X(7,  0.02752286553001629f,     0.22626469396516913f)   \
  X(8, -0.031582039318031156f,    0.3152503517092432f)    \
  X(9,  0.0005538422009938016f,  -0.7511339080215775f)    \
  X(10, 0.004777257511010651f,    0.4946238903983854f)    \
  X(11,-0.00107730108499558f,    -0.11154074335008017f)

#define SFB_EVEN(X) \
  X(0,  0.004777257511010651f,    0.4946238903983854f)    \
  X(1, -0.031582039318031156f,    0.3152503517092432f)    \
  X(2,  0.09750160558707936f,    -0.12976686756709563f)   \
  X(3, -0.22626469396516913f,     0.02752286553001629f)   \
  X(4,  0.7511339080215775f,      0.0005538422009938016f) \
  X(5,  0.11154074335008017f,    -0.00107730108499558f)
#define SFB_ODD(X) \
  X(0, -0.00107730108499558f,    -0.11154074335008017f)   \
  X(1,  0.0005538422009938016f,  -0.7511339080215775f)    \
  X(2,  0.02752286553001629f,     0.22626469396516913f)   \
  X(3, -0.12976686756709563f,    -0.09750160558707936f)   \
  X(4,  0.3152503517092432f,      0.031582039318031156f)  \
  X(5,  0.4946238903983854f,     -0.004777257511010651f)

// packed fp32x2 FMA helpers (Blackwell FFMA2 — only reachable via PTX)
#define FFMA2(acc, w2, v2) \
    asm("fma.rn.f32x2 %0, %1, %2, %3;" : "=l"(acc) : "l"(w2), "l"(v2), "l"(acc))
#define BCAST2(dst, f) \
    asm("mov.b64 %0, {%1, %1};" : "=l"(dst) : "r"(__float_as_uint(f)))
#define UNPACK2(lo, hi, p) \
    asm("mov.b64 {%0, %1}, %2;" : "=f"(lo), "=f"(hi) : "l"(p))

// ---------------- weight transpose: in[i][o][c] -> out[c][i][o] -------------
__global__ __launch_bounds__(256) void wtrans2(const float* __restrict__ in,
                                               float* __restrict__ out) {
    __shared__ float t[8][32][33];
    int i0 = blockIdx.x * 8, o0 = blockIdx.y * 32, c0 = blockIdx.z * 32;
    int tid = threadIdx.x;
    for (int l = tid; l < 8192; l += 256) {
        int ii = l >> 10, rest = l & 1023;
        int oy = rest >> 5, cx = rest & 31;
        t[ii][oy][cx] = in[(long)(i0 + ii) * 262144 + (long)(o0 + oy) * 4096 + c0 + cx];
    }
    __syncthreads();
    int ii = tid >> 5, ox = tid & 31;
    long ob = (long)(i0 + ii) * 64 + o0 + ox;
    #pragma unroll
    for (int cr = 0; cr < 32; cr++)
        out[(long)(c0 + cr) * 4096 + ob] = t[ii][ox][cr];
}

// ---------------- fused: NCHW input -> level-1 W-direction afb -> HWC -------
__global__ __launch_bounds__(256) void afb_w_first(const float* __restrict__ x,
    float* __restrict__ lo, float* __restrict__ hi) {
    __shared__ float srow[32][277];
    int y = blockIdx.y, q0 = blockIdx.x * 32;
    int tid = threadIdx.x;
    for (int idx = tid; idx < 32 * 276; idx += 256) {
        int ql = idx / 276, ew = idx - ql * 276;
        int t = ew - 10;
        t = (t < 0) ? (-1 - t) : ((t >= 256) ? (511 - t) : t);
        srow[ql][ew] = x[(q0 + ql) * 65536 + y * 256 + t];
    }
    __syncthreads();
    int ql = tid & 31, jj = tid >> 5;
    int j0 = jj * 17;
    float w[12];
    #pragma unroll
    for (int k = 0; k < 12; k++) w[k] = srow[ql][2 * j0 + k];
    int ob = y * 133 * 512 + q0 + ql;
    #pragma unroll
    for (int u = 0; u < 17; u++) {
        int j = j0 + u;
        if (j < 133) {
            float alo = 0.f, ahi = 0.f;
#define TAP(K, CLO, CHI) { float xv = w[K]; alo += (CLO) * xv; ahi += (CHI) * xv; }
            AFB_TAPS(TAP)
#undef TAP
            lo[ob + j * 512] = alo;
            hi[ob + j * 512] = ahi;
        }
        if (u < 16 && j < 132) {
            #pragma unroll
            for (int k = 0; k < 10; k++) w[k] = w[k + 2];
            w[10] = srow[ql][2 * j + 12];
            w[11] = srow[ql][2 * j + 13];
        }
    }
}

// ---------------- fused: final W-direction sfb -> NCHW output ---------------
__global__ __launch_bounds__(256) void sfb_w_last(const float* __restrict__ lo,
    const float* __restrict__ hi, float* __restrict__ out) {
    __shared__ float sout[256][33];
    int y = blockIdx.y, q0 = blockIdx.x * 32;
    int tid = threadIdx.x, ql = tid & 31, mm = tid >> 5;
    int m0 = mm * 32;
    const float* plo = lo + y * 133 * 512 + q0 + ql;
    const float* phi = hi + y * 133 * 512 + q0 + ql;
    int t0 = m0 >> 1;
    float wl[6], wh[6];
    #pragma unroll
    for (int k = 0; k < 6; k++) {
        wl[k] = plo[(t0 + k) * 512];
        wh[k] = phi[(t0 + k) * 512];
    }
    #pragma unroll
    for (int p = 0; p < 16; p++) {
        float ae = 0.f, ao = 0.f;
#define ETAP(KK, CLO, CHI) { ae += (CLO) * wl[KK]; ae += (CHI) * wh[KK]; }
        SFB_EVEN(ETAP)
#undef ETAP
#define OTAP(KK, CLO, CHI) { ao += (CLO) * wl[KK]; ao += (CHI) * wh[KK]; }
        SFB_ODD(OTAP)
#undef OTAP
        sout[m0 + 2 * p][ql]     = ae;
        sout[m0 + 2 * p + 1][ql] = ao;
        if (p < 15) {
            #pragma unroll
            for (int k = 0; k < 5; k++) { wl[k] = wl[k + 1]; wh[k] = wh[k + 1]; }
            int t = t0 + p + 6;
            wl[5] = plo[t * 512];
            wh[5] = phi[t * 512];
        }
    }
    __syncthreads();
    int obase = y * 256 + tid;
    #pragma unroll
    for (int i = 0; i < 32; i++)
        out[(q0 + i) * 65536 + obase] = sout[tid][i];
}

// ---------------- afb core (sliding window, 4 outputs/thread) ---------------
__device__ __forceinline__ void afb_core(
    const float* __restrict__ in, float* __restrict__ lo, float* __restrict__ hi,
    int nf_in, int nf_out, int sf_in, int so_in, int sf_out, int so_out,
    int bx, int by, int bz) {
    int lane = threadIdx.x & 31;
    int jj = threadIdx.x >> 5;
    int j0 = (bx * 8 + jj) * 4;
    if (j0 >= nf_out) return;
    int vo = bz * 128 + lane * 4;
    const float* pin = in + by * so_in + vo;
    int tb = 2 * j0 - 10;
    float4 w[12];
    #pragma unroll
    for (int k = 0; k < 12; k++) {
        int t = tb + k;
        t = (t < 0) ? (-1 - t) : ((t >= nf_in) ? (2 * nf_in - 1 - t) : t);
        w[k] = *(const float4*)(pin + t * sf_in);
    }
    int oo = by * so_out + j0 * sf_out + vo;
    float* plo = lo + oo;
    float* phi = hi + oo;
    #pragma unroll
    for (int u = 0; u < 4; u++) {
        if (j0 + u < nf_out) {
            float4 alo = {0.f,0.f,0.f,0.f}, ahi = {0.f,0.f,0.f,0.f};
#define TAP(K, CLO, CHI) { float4 xv = w[K];                                   \
            alo.x += (CLO) * xv.x; alo.y += (CLO) * xv.y;                      \
            alo.z += (CLO) * xv.z; alo.w += (CLO) * xv.w;                      \
            ahi.x += (CHI) * xv.x; ahi.y += (CHI) * xv.y;                      \
            ahi.z += (CHI) * xv.z; ahi.w += (CHI) * xv.w; }
            AFB_TAPS(TAP)
#undef TAP
            *(float4*)plo = alo;
            *(float4*)phi = ahi;
        }
        if (u < 3) {
            #pragma unroll
            for (int k = 0; k < 10; k++) w[k] = w[k + 2];
            int t0n = tb + 12 + 2 * u;
            int t1n = t0n + 1;
            t0n = (t0n >= nf_in) ? (2 * nf_in - 1 - t0n) : t0n;
            t1n = (t1n >= nf_in) ? (2 * nf_in - 1 - t1n) : t1n;
            w[10] = *(const float4*)(pin + t0n * sf_in);
            w[11] = *(const float4*)(pin + t1n * sf_in);
            plo += sf_out;
            phi += sf_out;
        }
    }
}

__global__ __launch_bounds__(256) void afb_kernel(
    const float* __restrict__ in, float* __restrict__ lo, float* __restrict__ hi,
    int nf_in, int nf_out, int sf_in, int so_in, int sf_out, int so_out) {
    afb_core(in, lo, hi, nf_in, nf_out, sf_in, so_in, sf_out, so_out,
             blockIdx.x, blockIdx.y, blockIdx.z);
}

__global__ __launch_bounds__(256) void afb_pair(
    const float* __restrict__ in0, float* __restrict__ lo0, float* __restrict__ hi0,
    const float* __restrict__ in1, float* __restrict__ lo1, float* __restrict__ hi1,
    int nf_in, int nf_out, int sf_in, int so_in, int sf_out, int so_out) {
    int sel = blockIdx.z >> 2, bz = blockIdx.z & 3;
    afb_core(sel ? in1 : in0, sel ? lo1 : lo0, sel ? hi1 : hi0,
             nf_in, nf_out, sf_in, so_in, sf_out, so_out,
             blockIdx.x, blockIdx.y, bz);
}

// ---------------- sfb core (sliding window, 4 outputs/thread) ---------------
__device__ __forceinline__ void sfb_core(
    const float* __restrict__ lo, const float* __restrict__ hi, float* __restrict__ out,
    int n_t, int nf_out, int sflo, int solo, int sfhi, int sohi,
    int sf_out, int so_out, int bx, int by, int bz) {
    int lane = threadIdx.x & 31;
    int mm = threadIdx.x >> 5;
    int m0 = (bx * 8 + mm) * 4;
    if (m0 >= nf_out) return;
    int vo = bz * 128 + lane * 4;
    const float* plo = lo + by * solo + vo;
    const float* phi = hi + by * sohi + vo;
    int t0 = m0 >> 1;
    float4 wl[6], wh[6];
    #pragma unroll
    for (int k = 0; k < 6; k++) {
        int t = t0 + k;
        bool ok = (unsigned)t < (unsigned)n_t;
        wl[k] = ok ? *(const float4*)(plo + t * sflo) : make_float4(0.f,0.f,0.f,0.f);
        wh[k] = ok ? *(const float4*)(phi + t * sfhi) : make_float4(0.f,0.f,0.f,0.f);
    }
    float* pout = out + by * so_out + m0 * sf_out + vo;
    #pragma unroll
    for (int p = 0; p < 2; p++) {
        float4 ae = {0.f,0.f,0.f,0.f}, ao = {0.f,0.f,0.f,0.f};
#define ETAP(KK, CLO, CHI) { float4 a = wl[KK]; float4 b = wh[KK];             \
        ae.x += (CLO)*a.x; ae.x += (CHI)*b.x;  ae.y += (CLO)*a.y; ae.y += (CHI)*b.y; \
        ae.z += (CLO)*a.z; ae.z += (CHI)*b.z;  ae.w += (CLO)*a.w; ae.w += (CHI)*b.w; }
        SFB_EVEN(ETAP)
#undef ETAP
#define OTAP(KK, CLO, CHI) { float4 a = wl[KK]; float4 b = wh[KK];             \
        ao.x += (CLO)*a.x; ao.x += (CHI)*b.x;  ao.y += (CLO)*a.y; ao.y += (CHI)*b.y; \
        ao.z += (CLO)*a.z; ao.z += (CHI)*b.z;  ao.w += (CLO)*a.w; ao.w += (CHI)*b.w; }
        SFB_ODD(OTAP)
#undef OTAP
        int me = m0 + 2 * p;
        if (me < nf_out)     *(float4*)pout = ae;
        if (me + 1 < nf_out) *(float4*)(pout + sf_out) = ao;
        if (p == 0) {
            #pragma unroll
            for (int k = 0; k < 5; k++) { wl[k] = wl[k + 1]; wh[k] = wh[k + 1]; }
            int t = t0 + 6;
            bool ok = (unsigned)t < (unsigned)n_t;
            wl[5] = ok ? *(const float4*)(plo + t * sflo) : make_float4(0.f,0.f,0.f,0.f);
            wh[5] = ok ? *(const float4*)(phi + t * sfhi) : make_float4(0.f,0.f,0.f,0.f);
            pout += 2 * sf_out;
        }
    }
}

__global__ __launch_bounds__(256) void sfb_kernel(
    const float* __restrict__ lo, const float* __restrict__ hi, float* __restrict__ out,
    int n_t, int nf_out, int sflo, int solo, int sfhi, int sohi,
    int sf_out, int so_out) {
    sfb_core(lo, hi, out, n_t, nf_out, sflo, solo, sfhi, sohi, sf_out, so_out,
             blockIdx.x, blockIdx.y, blockIdx.z);
}

__global__ __launch_bounds__(256) void sfb_pair(
    const float* __restrict__ lo0, const float* __restrict__ hi0, float* __restrict__ out0,
    const float* __restrict__ lo1, const float* __restrict__ hi1, float* __restrict__ out1,
    int n_t, int nf_out, int sflo0, int sflo1, int solo, int sfhi, int sohi,
    int sf_out, int so_out) {
    int sel = blockIdx.z >> 2, bz = blockIdx.z & 3;
    sfb_core(sel ? lo1 : lo0, sel ? hi1 : hi0, sel ? out1 : out0,
             n_t, nf_out, sel ? sflo1 : sflo0, solo, sfhi, sohi, sf_out, so_out,
             blockIdx.x, blockIdx.y, bz);
}

// ---------------- conv, 2 pixels/CTA, f32x2 packed GEMM (S=3) ---------------
__global__ __launch_bounds__(128, 4) void conv2(
    float* p0, float* p1, float* p2, int n) {
    constexpr int S = 3;
    constexpr int R = S * 8;          // 24
    constexpr int TR = R / 4;         // 6 rows per thread
    __shared__ float w_s[2][64 * 64];
    __shared__ float in_s[2][R * 68];
    int tid = threadIdx.x;
    int sel = tid >> 6, t = tid & 63;
    int jy = blockIdx.y, jx = blockIdx.x * 2 + sel;
    bool act = jx < n;
    long pix = 0;
    if (act) {
        float sc = (float)(64.0 / n);
        float yc = fminf(fmaxf((jy + 0.5f) * sc - 0.5f, 0.0f), 63.0f);
        float xc = fminf(fmaxf((jx + 0.5f) * sc - 0.5f, 0.0f), 63.0f);
        int y0 = (int)floorf(yc), x0 = (int)floorf(xc);
        int y1 = min(y0 + 1, 63), x1 = min(x0 + 1, 63);
        float ty = yc - (float)y0, tx = xc - (float)x0;
        float c00 = (1.f - ty) * (1.f - tx), c01 = (1.f - ty) * tx;
        float c10 = ty * (1.f - tx),         c11 = ty * tx;
        const float* w00 = g_wt + ((long)y0 * 64 + x0) * 4096;
        const float* w01 = g_wt + ((long)y0 * 64 + x1) * 4096;
        const float* w10 = g_wt + ((long)y1 * 64 + x0) * 4096;
        const float* w11 = g_wt + ((long)y1 * 64 + x1) * 4096;
        #pragma unroll 4
        for (int c = 0; c < 16; c++) {
            int e = c * 256 + t * 4;
            float4 a = *(const float4*)(w00 + e);
            float4 b = *(const float4*)(w01 + e);
            float4 d = *(const float4*)(w10 + e);
            float4 f = *(const float4*)(w11 + e);
            float4 wv;
            wv.x = c00 * a.x + c01 * b.x + c10 * d.x + c11 * f.x;
            wv.y = c00 * a.y + c01 * b.y + c10 * d.y + c11 * f.y;
            wv.z = c00 * a.z + c01 * b.z + c10 * d.z + c11 * f.z;
            wv.w = c00 * a.w + c01 * b.w + c10 * d.w + c11 * f.w;
            *(float4*)&w_s[sel][e] = wv;
        }
        pix = ((long)jy * n + jx) * V;
        #pragma unroll
        for (int l = 0; l < R / 4; l++) {
            int idx = l * 64 + t;
            int r = idx >> 4, i4 = (idx & 15) * 4;
            int ss = r >> 3, b = r & 7;
            const float* p = (ss == 0) ? p0 : (ss == 1) ? p1 : p2;
            *(float4*)&in_s[sel][r * 68 + i4] = *(const float4*)(p + pix + b * 64 + i4);
        }
    }
    __syncthreads();
    if (act) {
        int colg = t & 15, rowg = t >> 4;
        int o0 = colg * 4, r0 = rowg * TR;
        unsigned long long a01[TR], a23[TR];
        #pragma unroll
        for (int r = 0; r < TR; r++) { a01[r] = 0ull; a23[r] = 0ull; }
        #pragma unroll 8
        for (int i = 0; i < 64; i += 4) {
            ulonglong2 w0 = *(const ulonglong2*)&w_s[sel][(i + 0) * 64 + o0];
            ulonglong2 w1 = *(const ulonglong2*)&w_s[sel][(i + 1) * 64 + o0];
            ulonglong2 w2 = *(const ulonglong2*)&w_s[sel][(i + 2) * 64 + o0];
            ulonglong2 w3 = *(const ulonglong2*)&w_s[sel][(i + 3) * 64 + o0];
            #pragma unroll
            for (int r = 0; r < TR; r++) {
                float4 v = *(const float4*)&in_s[sel][(r0 + r) * 68 + i];
                unsigned long long vx, vy, vz, vw;
                BCAST2(vx, v.x); BCAST2(vy, v.y);
                BCAST2(vz, v.z); BCAST2(vw, v.w);
                FFMA2(a01[r], w0.x, vx); FFMA2(a23[r], w0.y, vx);
                FFMA2(a01[r], w1.x, vy); FFMA2(a23[r], w1.y, vy);
                FFMA2(a01[r], w2.x, vz); FFMA2(a23[r], w2.y, vz);
                FFMA2(a01[r], w3.x, vw); FFMA2(a23[r], w3.y, vw);
            }
        }
        #pragma unroll
        for (int r = 0; r < TR; r++) {
            int rr = r0 + r;
            int ss = rr >> 3, b = rr & 7;
            float* p = (ss == 0) ? p0 : (ss == 1) ? p1 : p2;
            float4 outv;
            UNPACK2(outv.x, outv.y, a01[r]);
            UNPACK2(outv.z, outv.w, a23[r]);
            *(float4*)(p + pix + b * 64 + o0) = outv;
        }
    }
}

// ---------------- per-pixel conv (level 3, S=4), f32x2 packed GEMM ----------
template <int S>
__global__ __launch_bounds__(128, 4) void conv_kernel(
    float* p0, float* p1, float* p2, float* p3, int n) {
    constexpr int R  = S * 8;
    constexpr int TR = R / 8;
    __shared__ float w_s[64 * 64];
    __shared__ float in_s[R * 68];
    int jx = blockIdx.x, jy = blockIdx.y, tid = threadIdx.x;
    float sc = (float)(64.0 / n);
    float yc = fminf(fmaxf((jy + 0.5f) * sc - 0.5f, 0.0f), 63.0f);
    float xc = fminf(fmaxf((jx + 0.5f) * sc - 0.5f, 0.0f), 63.0f);
    int y0 = (int)floorf(yc), x0 = (int)floorf(xc);
    int y1 = min(y0 + 1, 63), x1 = min(x0 + 1, 63);
    float ty = yc - (float)y0, tx = xc - (float)x0;
    float c00 = (1.f - ty) * (1.f - tx), c01 = (1.f - ty) * tx;
    float c10 = ty * (1.f - tx),         c11 = ty * tx;
    const float* w00 = g_wt + ((long)y0 * 64 + x0) * 4096;
    const float* w01 = g_wt + ((long)y0 * 64 + x1) * 4096;
    const float* w10 = g_wt + ((long)y1 * 64 + x0) * 4096;
    const float* w11 = g_wt + ((long)y1 * 64 + x1) * 4096;
    #pragma unroll 4
    for (int c = 0; c < 8; c++) {
        int e = c * 512 + tid * 4;
        float4 a = *(const float4*)(w00 + e);
        float4 b = *(const float4*)(w01 + e);
        float4 d = *(const float4*)(w10 + e);
        float4 f = *(const float4*)(w11 + e);
        float4 wv;
        wv.x = c00 * a.x + c01 * b.x + c10 * d.x + c11 * f.x;
        wv.y = c00 * a.y + c01 * b.y + c10 * d.y + c11 * f.y;
        wv.z = c00 * a.z + c01 * b.z + c10 * d.z + c11 * f.z;
        wv.w = c00 * a.w + c01 * b.w + c10 * d.w + c11 * f.w;
        *(float4*)&w_s[e] = wv;
    }
    long pix = ((long)jy * n + jx) * V;
    {
        int b = tid >> 4, i4 = (tid & 15) * 4;
        #pragma unroll
        for (int ss = 0; ss < S; ss++) {
            const float* p = (ss == 0) ? p0 : (ss == 1) ? p1 : (ss == 2) ? p2 : p3;
            *(float4*)&in_s[(ss * 8 + b) * 68 + i4] = *(const float4*)(p + pix + b * 64 + i4);
        }
    }
    __syncthreads();
    int colg = tid & 15, rowg = tid >> 4;
    int o0 = colg * 4, r0 = rowg * TR;
    unsigned long long a01[TR], a23[TR];
    #pragma unroll
    for (int r = 0; r < TR; r++) { a01[r] = 0ull; a23[r] = 0ull; }
    #pragma unroll 8
    for (int i = 0; i < 64; i += 4) {
        ulonglong2 w0 = *(const ulonglong2*)&w_s[(i + 0) * 64 + o0];
        ulonglong2 w1 = *(const ulonglong2*)&w_s[(i + 1) * 64 + o0];
        ulonglong2 w2 = *(const ulonglong2*)&w_s[(i + 2) * 64 + o0];
        ulonglong2 w3 = *(const ulonglong2*)&w_s[(i + 3) * 64 + o0];
        #pragma unroll
        for (int r = 0; r < TR; r++) {
            float4 v = *(const float4*)&in_s[(r0 + r) * 68 + i];
            unsigned long long vx, vy, vz, vw;
            BCAST2(vx, v.x); BCAST2(vy, v.y);
            BCAST2(vz, v.z); BCAST2(vw, v.w);
            FFMA2(a01[r], w0.x, vx); FFMA2(a23[r], w0.y, vx);
            FFMA2(a01[r], w1.x, vy); FFMA2(a23[r], w1.y, vy);
            FFMA2(a01[r], w2.x, vz); FFMA2(a23[r], w2.y, vz);
            FFMA2(a01[r], w3.x, vw); FFMA2(a23[r], w3.y, vw);
        }
    }
    #pragma unroll
    for (int r = 0; r < TR; r++) {
        int rr = r0 + r;
        int ss = rr >> 3, b = rr & 7;
        float* p = (ss == 0) ? p0 : (ss == 1) ? p1 : (ss == 2) ? p2 : p3;
        float4 outv;
        UNPACK2(outv.x, outv.y, a01[r]);
        UNPACK2(outv.z, outv.w, a23[r]);
        *(float4*)(p + pix + b * 64 + o0) = outv;
    }
}

// ---------------- host ----------------
#define SYM(var, sym) float* var; { void* _p; cudaGetSymbolAddress(&_p, sym); var = (float*)_p; }

extern "C" void kernel_launch(void* const* d_in, const int* in_sizes, int n_in,
                              void* d_out, int out_size) {
    const float* x = (const float*)d_in[0];
    const float* w = (const float*)d_in[1];
    float* out = (float*)d_out;
    SYM(TLO, g_tlo) SYM(THI, g_thi)
    SYM(LL1, g_ll1) SYM(LH1, g_lh1) SYM(HL1, g_hl1) SYM(HH1, g_hh1)
    SYM(LL2, g_ll2) SYM(LH2, g_lh2) SYM(HL2, g_hl2) SYM(HH2, g_hh2)
    SYM(LL3, g_ll3) SYM(LH3, g_lh3) SYM(HL3, g_hl3) SYM(HH3, g_hh3)
    SYM(R2, g_r2)  SYM(WT, g_wt)

    // #1..#3
    wtrans2<<<dim3(8, 2, 128), 256>>>(w, WT);
    afb_w_first<<<dim3(16, 256), 256>>>(x, TLO, THI);
    afb_pair<<<dim3(5, 133, 8), 256>>>(TLO, LL1, LH1, THI, HL1, HH1,
                                       256, 133, 133*512, 512, 133*512, 512);
    // #4: the dominant conv — profiled slot
    conv2<<<dim3(67, 133), 128>>>(LH1, HL1, HH1, 133);
    // remaining DWT
    afb_kernel<<<dim3(3, 133, 4), 256>>>(LL1, TLO, THI, 133, 72, 512, 133*512, 512, 72*512);
    afb_pair<<<dim3(3, 72, 8), 256>>>(TLO, LL2, LH2, THI, HL2, HH2,
                                      133, 72, 72*512, 512, 72*512, 512);
    conv2<<<dim3(36, 72), 128>>>(LH2, HL2, HH2, 72);
    afb_kernel<<<dim3(2, 72, 4), 256>>>(LL2, TLO, THI, 72, 41, 512, 72*512, 512, 41*512);
    afb_pair<<<dim3(2, 41, 8), 256>>>(TLO, LL3, LH3, THI, HL3, HH3,
                                      72, 41, 41*512, 512, 41*512, 512);
    conv_kernel<4><<<dim3(41, 41), 128>>>(LL3, LH3, HL3, HH3, 41);

    // ---- IDWT ----
    sfb_pair<<<dim3(3, 41, 8), 256>>>(LL3, LH3, TLO, HL3, HH3, THI,
        41, 72, 41*512, 41*512, 512, 41*512, 512, 41*512, 512);
    sfb_kernel<<<dim3(3, 72, 4), 256>>>(TLO, THI, LL2, 41, 72,
        512, 41*512, 512, 41*512, 512, 72*512);
    sfb_pair<<<dim3(5, 72, 8), 256>>>(LL2, LH2, TLO, HL2, HH2, THI,
        72, 134, 72*512, 72*512, 512, 72*512, 512, 72*512, 512);
    sfb_kernel<<<dim3(5, 134, 4), 256>>>(TLO, THI, R2, 72, 134,
        512, 72*512, 512, 72*512, 512, 134*512);
    sfb_pair<<<dim3(8, 133, 8), 256>>>(R2, LH1, TLO, HL1, HH1, THI,
        133, 256, 134*512, 133*512, 512, 133*512, 512, 133*512, 512);
    sfb_w_last<<<dim3(16, 256), 256>>>(TLO, THI, out);
}

// round 14
// speedup vs baseline: 1.1105x; 1.0045x over previous
#include <cuda_runtime.h>

#define V 512

// ---------------- scratch (device globals; no runtime alloc) ----------------
__device__ float g_tlo[256*133*V];
__device__ float g_thi[256*133*V];
__device__ float g_ll1[133*133*V];
__device__ float g_lh1[133*133*V];
__device__ float g_hl1[133*133*V];
__device__ float g_hh1[133*133*V];
__device__ float g_ll2[72*72*V];
__device__ float g_lh2[72*72*V];
__device__ float g_hl2[72*72*V];
__device__ float g_hh2[72*72*V];
__device__ float g_ll3[41*41*V];
__device__ float g_lh3[41*41*V];
__device__ float g_hl3[41*41*V];
__device__ float g_hh3[41*41*V];
__device__ float g_r2 [134*134*V];
__device__ float g_wt [64*64*64*64]; // weights transposed to [gy*64+gx][i][o]

// ---------------- filter taps as literal constants ----------------
#define AFB_TAPS(X) \
  X(0,  0.11154074335008017f,    -0.00107730108499558f)   \
  X(1,  0.4946238903983854f,     -0.004777257511010651f)  \
  X(2,  0.7511339080215775f,      0.0005538422009938016f) \
  X(3,  0.3152503517092432f,      0.031582039318031156f)  \
  X(4, -0.22626469396516913f,     0.02752286553001629f)   \
  X(5, -0.12976686756709563f,    -0.09750160558707936f)   \
  X(6,  0.09750160558707936f,    -0.12976686756709563f)   \
  X(7,  0.02752286553001629f,     0.22626469396516913f)   \
  X(8, -0.031582039318031156f,    0.3152503517092432f)    \
  X(9,  0.0005538422009938016f,  -0.7511339080215775f)    \
  X(10, 0.004777257511010651f,    0.4946238903983854f)    \
  X(11,-0.00107730108499558f,    -0.11154074335008017f)

#define SFB_EVEN(X) \
  X(0,  0.004777257511010651f,    0.4946238903983854f)    \
  X(1, -0.031582039318031156f,    0.3152503517092432f)    \
  X(2,  0.09750160558707936f,    -0.12976686756709563f)   \
  X(3, -0.22626469396516913f,     0.02752286553001629f)   \
  X(4,  0.7511339080215775f,      0.0005538422009938016f) \
  X(5,  0.11154074335008017f,    -0.00107730108499558f)
#define SFB_ODD(X) \
  X(0, -0.00107730108499558f,    -0.11154074335008017f)   \
  X(1,  0.0005538422009938016f,  -0.7511339080215775f)    \
  X(2,  0.02752286553001629f,     0.22626469396516913f)   \
  X(3, -0.12976686756709563f,    -0.09750160558707936f)   \
  X(4,  0.3152503517092432f,      0.031582039318031156f)  \
  X(5,  0.4946238903983854f,     -0.004777257511010651f)

// packed fp32x2 FMA helpers (Blackwell FFMA2 — only reachable via PTX)
#define FFMA2(acc, w2, v2) \
    asm("fma.rn.f32x2 %0, %1, %2, %3;" : "=l"(acc) : "l"(w2), "l"(v2), "l"(acc))
#define BCAST2(dst, f) \
    asm("mov.b64 %0, {%1, %1};" : "=l"(dst) : "r"(__float_as_uint(f)))
#define UNPACK2(lo, hi, p) \
    asm("mov.b64 {%0, %1}, %2;" : "=f"(lo), "=f"(hi) : "l"(p))

// ---------------- weight transpose: in[i][o][c] -> out[c][i][o] -------------
__global__ __launch_bounds__(256) void wtrans2(const float* __restrict__ in,
                                               float* __restrict__ out) {
    __shared__ float t[8][32][33];
    int i0 = blockIdx.x * 8, o0 = blockIdx.y * 32, c0 = blockIdx.z * 32;
    int tid = threadIdx.x;
    for (int l = tid; l < 8192; l += 256) {
        int ii = l >> 10, rest = l & 1023;
        int oy = rest >> 5, cx = rest & 31;
        t[ii][oy][cx] = in[(long)(i0 + ii) * 262144 + (long)(o0 + oy) * 4096 + c0 + cx];
    }
    __syncthreads();
    int ii = tid >> 5, ox = tid & 31;
    long ob = (long)(i0 + ii) * 64 + o0 + ox;
    #pragma unroll
    for (int cr = 0; cr < 32; cr++)
        out[(long)(c0 + cr) * 4096 + ob] = t[ii][ox][cr];
}

// ---------------- fused: NCHW input -> level-1 W-direction afb -> HWC -------
__global__ __launch_bounds__(256) void afb_w_first(const float* __restrict__ x,
    float* __restrict__ lo, float* __restrict__ hi) {
    __shared__ float srow[32][277];
    int y = blockIdx.y, q0 = blockIdx.x * 32;
    int tid = threadIdx.x;
    for (int idx = tid; idx < 32 * 276; idx += 256) {
        int ql = idx / 276, ew = idx - ql * 276;
        int t = ew - 10;
        t = (t < 0) ? (-1 - t) : ((t >= 256) ? (511 - t) : t);
        srow[ql][ew] = x[(q0 + ql) * 65536 + y * 256 + t];
    }
    __syncthreads();
    int ql = tid & 31, jj = tid >> 5;
    int j0 = jj * 17;
    float w[12];
    #pragma unroll
    for (int k = 0; k < 12; k++) w[k] = srow[ql][2 * j0 + k];
    int ob = y * 133 * 512 + q0 + ql;
    #pragma unroll
    for (int u = 0; u < 17; u++) {
        int j = j0 + u;
        if (j < 133) {
            float alo = 0.f, ahi = 0.f;
#define TAP(K, CLO, CHI) { float xv = w[K]; alo += (CLO) * xv; ahi += (CHI) * xv; }
            AFB_TAPS(TAP)
#undef TAP
            lo[ob + j * 512] = alo;
            hi[ob + j * 512] = ahi;
        }
        if (u < 16 && j < 132) {
            #pragma unroll
            for (int k = 0; k < 10; k++) w[k] = w[k + 2];
            w[10] = srow[ql][2 * j + 12];
            w[11] = srow[ql][2 * j + 13];
        }
    }
}

// ---------------- fused: final W-direction sfb -> NCHW output ---------------
__global__ __launch_bounds__(256) void sfb_w_last(const float* __restrict__ lo,
    const float* __restrict__ hi, float* __restrict__ out) {
    __shared__ float sout[256][33];
    int y = blockIdx.y, q0 = blockIdx.x * 32;
    int tid = threadIdx.x, ql = tid & 31, mm = tid >> 5;
    int m0 = mm * 32;
    const float* plo = lo + y * 133 * 512 + q0 + ql;
    const float* phi = hi + y * 133 * 512 + q0 + ql;
    int t0 = m0 >> 1;
    float wl[6], wh[6];
    #pragma unroll
    for (int k = 0; k < 6; k++) {
        wl[k] = plo[(t0 + k) * 512];
        wh[k] = phi[(t0 + k) * 512];
    }
    #pragma unroll
    for (int p = 0; p < 16; p++) {
        float ae = 0.f, ao = 0.f;
#define ETAP(KK, CLO, CHI) { ae += (CLO) * wl[KK]; ae += (CHI) * wh[KK]; }
        SFB_EVEN(ETAP)
#undef ETAP
#define OTAP(KK, CLO, CHI) { ao += (CLO) * wl[KK]; ao += (CHI) * wh[KK]; }
        SFB_ODD(OTAP)
#undef OTAP
        sout[m0 + 2 * p][ql]     = ae;
        sout[m0 + 2 * p + 1][ql] = ao;
        if (p < 15) {
            #pragma unroll
            for (int k = 0; k < 5; k++) { wl[k] = wl[k + 1]; wh[k] = wh[k + 1]; }
            int t = t0 + p + 6;
            wl[5] = plo[t * 512];
            wh[5] = phi[t * 512];
        }
    }
    __syncthreads();
    int obase = y * 256 + tid;
    #pragma unroll
    for (int i = 0; i < 32; i++)
        out[(q0 + i) * 65536 + obase] = sout[tid][i];
}

// ---------------- afb core (sliding window, 4 outputs/thread) ---------------
__device__ __forceinline__ void afb_core(
    const float* __restrict__ in, float* __restrict__ lo, float* __restrict__ hi,
    int nf_in, int nf_out, int sf_in, int so_in, int sf_out, int so_out,
    int bx, int by, int bz) {
    int lane = threadIdx.x & 31;
    int jj = threadIdx.x >> 5;
    int j0 = (bx * 8 + jj) * 4;
    if (j0 >= nf_out) return;
    int vo = bz * 128 + lane * 4;
    const float* pin = in + by * so_in + vo;
    int tb = 2 * j0 - 10;
    float4 w[12];
    #pragma unroll
    for (int k = 0; k < 12; k++) {
        int t = tb + k;
        t = (t < 0) ? (-1 - t) : ((t >= nf_in) ? (2 * nf_in - 1 - t) : t);
        w[k] = *(const float4*)(pin + t * sf_in);
    }
    int oo = by * so_out + j0 * sf_out + vo;
    float* plo = lo + oo;
    float* phi = hi + oo;
    #pragma unroll
    for (int u = 0; u < 4; u++) {
        if (j0 + u < nf_out) {
            float4 alo = {0.f,0.f,0.f,0.f}, ahi = {0.f,0.f,0.f,0.f};
#define TAP(K, CLO, CHI) { float4 xv = w[K];                                   \
            alo.x += (CLO) * xv.x; alo.y += (CLO) * xv.y;                      \
            alo.z += (CLO) * xv.z; alo.w += (CLO) * xv.w;                      \
            ahi.x += (CHI) * xv.x; ahi.y += (CHI) * xv.y;                      \
            ahi.z += (CHI) * xv.z; ahi.w += (CHI) * xv.w; }
            AFB_TAPS(TAP)
#undef TAP
            *(float4*)plo = alo;
            *(float4*)phi = ahi;
        }
        if (u < 3) {
            #pragma unroll
            for (int k = 0; k < 10; k++) w[k] = w[k + 2];
            int t0n = tb + 12 + 2 * u;
            int t1n = t0n + 1;
            t0n = (t0n >= nf_in) ? (2 * nf_in - 1 - t0n) : t0n;
            t1n = (t1n >= nf_in) ? (2 * nf_in - 1 - t1n) : t1n;
            w[10] = *(const float4*)(pin + t0n * sf_in);
            w[11] = *(const float4*)(pin + t1n * sf_in);
            plo += sf_out;
            phi += sf_out;
        }
    }
}

__global__ __launch_bounds__(256) void afb_kernel(
    const float* __restrict__ in, float* __restrict__ lo, float* __restrict__ hi,
    int nf_in, int nf_out, int sf_in, int so_in, int sf_out, int so_out) {
    afb_core(in, lo, hi, nf_in, nf_out, sf_in, so_in, sf_out, so_out,
             blockIdx.x, blockIdx.y, blockIdx.z);
}

__global__ __launch_bounds__(256) void afb_pair(
    const float* __restrict__ in0, float* __restrict__ lo0, float* __restrict__ hi0,
    const float* __restrict__ in1, float* __restrict__ lo1, float* __restrict__ hi1,
    int nf_in, int nf_out, int sf_in, int so_in, int sf_out, int so_out) {
    int sel = blockIdx.z >> 2, bz = blockIdx.z & 3;
    afb_core(sel ? in1 : in0, sel ? lo1 : lo0, sel ? hi1 : hi0,
             nf_in, nf_out, sf_in, so_in, sf_out, so_out,
             blockIdx.x, blockIdx.y, bz);
}

// ---------------- sfb core (sliding window, 4 outputs/thread) ---------------
__device__ __forceinline__ void sfb_core(
    const float* __restrict__ lo, const float* __restrict__ hi, float* __restrict__ out,
    int n_t, int nf_out, int sflo, int solo, int sfhi, int sohi,
    int sf_out, int so_out, int bx, int by, int bz) {
    int lane = threadIdx.x & 31;
    int mm = threadIdx.x >> 5;
    int m0 = (bx * 8 + mm) * 4;
    if (m0 >= nf_out) return;
    int vo = bz * 128 + lane * 4;
    const float* plo = lo + by * solo + vo;
    const float* phi = hi + by * sohi + vo;
    int t0 = m0 >> 1;
    float4 wl[6], wh[6];
    #pragma unroll
    for (int k = 0; k < 6; k++) {
        int t = t0 + k;
        bool ok = (unsigned)t < (unsigned)n_t;
        wl[k] = ok ? *(const float4*)(plo + t * sflo) : make_float4(0.f,0.f,0.f,0.f);
        wh[k] = ok ? *(const float4*)(phi + t * sfhi) : make_float4(0.f,0.f,0.f,0.f);
    }
    float* pout = out + by * so_out + m0 * sf_out + vo;
    #pragma unroll
    for (int p = 0; p < 2; p++) {
        float4 ae = {0.f,0.f,0.f,0.f}, ao = {0.f,0.f,0.f,0.f};
#define ETAP(KK, CLO, CHI) { float4 a = wl[KK]; float4 b = wh[KK];             \
        ae.x += (CLO)*a.x; ae.x += (CHI)*b.x;  ae.y += (CLO)*a.y; ae.y += (CHI)*b.y; \
        ae.z += (CLO)*a.z; ae.z += (CHI)*b.z;  ae.w += (CLO)*a.w; ae.w += (CHI)*b.w; }
        SFB_EVEN(ETAP)
#undef ETAP
#define OTAP(KK, CLO, CHI) { float4 a = wl[KK]; float4 b = wh[KK];             \
        ao.x += (CLO)*a.x; ao.x += (CHI)*b.x;  ao.y += (CLO)*a.y; ao.y += (CHI)*b.y; \
        ao.z += (CLO)*a.z; ao.z += (CHI)*b.z;  ao.w += (CLO)*a.w; ao.w += (CHI)*b.w; }
        SFB_ODD(OTAP)
#undef OTAP
        int me = m0 + 2 * p;
        if (me < nf_out)     *(float4*)pout = ae;
        if (me + 1 < nf_out) *(float4*)(pout + sf_out) = ao;
        if (p == 0) {
            #pragma unroll
            for (int k = 0; k < 5; k++) { wl[k] = wl[k + 1]; wh[k] = wh[k + 1]; }
            int t = t0 + 6;
            bool ok = (unsigned)t < (unsigned)n_t;
            wl[5] = ok ? *(const float4*)(plo + t * sflo) : make_float4(0.f,0.f,0.f,0.f);
            wh[5] = ok ? *(const float4*)(phi + t * sfhi) : make_float4(0.f,0.f,0.f,0.f);
            pout += 2 * sf_out;
        }
    }
}

__global__ __launch_bounds__(256) void sfb_kernel(
    const float* __restrict__ lo, const float* __restrict__ hi, float* __restrict__ out,
    int n_t, int nf_out, int sflo, int solo, int sfhi, int sohi,
    int sf_out, int so_out) {
    sfb_core(lo, hi, out, n_t, nf_out, sflo, solo, sfhi, sohi, sf_out, so_out,
             blockIdx.x, blockIdx.y, blockIdx.z);
}

__global__ __launch_bounds__(256) void sfb_pair(
    const float* __restrict__ lo0, const float* __restrict__ hi0, float* __restrict__ out0,
    const float* __restrict__ lo1, const float* __restrict__ hi1, float* __restrict__ out1,
    int n_t, int nf_out, int sflo0, int sflo1, int solo, int sfhi, int sohi,
    int sf_out, int so_out) {
    int sel = blockIdx.z >> 2, bz = blockIdx.z & 3;
    sfb_core(sel ? lo1 : lo0, sel ? hi1 : hi0, sel ? out1 : out0,
             n_t, nf_out, sel ? sflo1 : sflo0, solo, sfhi, sohi, sf_out, so_out,
             blockIdx.x, blockIdx.y, bz);
}

// ---------------- conv, 2 VERTICALLY-adjacent pixels/CTA, f32x2 GEMM (S=3) --
// Pixels (jx, 2bx) and (jx, 2bx+1): same x-cell always, same y-cell ~half the
// time -> corner fetches overlap in L1/L2. Consecutive CTAs walk jy within one
// jx column (bx fast), reusing x-corners from L1.
__global__ __launch_bounds__(128, 4) void conv2(
    float* p0, float* p1, float* p2, int n) {
    constexpr int S = 3;
    constexpr int R = S * 8;          // 24
    constexpr int TR = R / 4;         // 6 rows per thread
    __shared__ float w_s[2][64 * 64];
    __shared__ float in_s[2][R * 68];
    int tid = threadIdx.x;
    int sel = tid >> 6, t = tid & 63;
    int jx = blockIdx.y, jy = blockIdx.x * 2 + sel;
    bool act = jy < n;
    long pix = 0;
    if (act) {
        float sc = (float)(64.0 / n);
        float yc = fminf(fmaxf((jy + 0.5f) * sc - 0.5f, 0.0f), 63.0f);
        float xc = fminf(fmaxf((jx + 0.5f) * sc - 0.5f, 0.0f), 63.0f);
        int y0 = (int)floorf(yc), x0 = (int)floorf(xc);
        int y1 = min(y0 + 1, 63), x1 = min(x0 + 1, 63);
        float ty = yc - (float)y0, tx = xc - (float)x0;
        float c00 = (1.f - ty) * (1.f - tx), c01 = (1.f - ty) * tx;
        float c10 = ty * (1.f - tx),         c11 = ty * tx;
        const float* w00 = g_wt + ((long)y0 * 64 + x0) * 4096;
        const float* w01 = g_wt + ((long)y0 * 64 + x1) * 4096;
        const float* w10 = g_wt + ((long)y1 * 64 + x0) * 4096;
        const float* w11 = g_wt + ((long)y1 * 64 + x1) * 4096;
        #pragma unroll 4
        for (int c = 0; c < 16; c++) {
            int e = c * 256 + t * 4;
            float4 a = *(const float4*)(w00 + e);
            float4 b = *(const float4*)(w01 + e);
            float4 d = *(const float4*)(w10 + e);
            float4 f = *(const float4*)(w11 + e);
            float4 wv;
            wv.x = c00 * a.x + c01 * b.x + c10 * d.x + c11 * f.x;
            wv.y = c00 * a.y + c01 * b.y + c10 * d.y + c11 * f.y;
            wv.z = c00 * a.z + c01 * b.z + c10 * d.z + c11 * f.z;
            wv.w = c00 * a.w + c01 * b.w + c10 * d.w + c11 * f.w;
            *(float4*)&w_s[sel][e] = wv;
        }
        pix = ((long)jy * n + jx) * V;
        #pragma unroll
        for (int l = 0; l < R / 4; l++) {
            int idx = l * 64 + t;
            int r = idx >> 4, i4 = (idx & 15) * 4;
            int ss = r >> 3, b = r & 7;
            const float* p = (ss == 0) ? p0 : (ss == 1) ? p1 : p2;
            *(float4*)&in_s[sel][r * 68 + i4] = *(const float4*)(p + pix + b * 64 + i4);
        }
    }
    __syncthreads();
    if (act) {
        int colg = t & 15, rowg = t >> 4;
        int o0 = colg * 4, r0 = rowg * TR;
        unsigned long long a01[TR], a23[TR];
        #pragma unroll
        for (int r = 0; r < TR; r++) { a01[r] = 0ull; a23[r] = 0ull; }
        #pragma unroll 8
        for (int i = 0; i < 64; i += 4) {
            ulonglong2 w0 = *(const ulonglong2*)&w_s[sel][(i + 0) * 64 + o0];
            ulonglong2 w1 = *(const ulonglong2*)&w_s[sel][(i + 1) * 64 + o0];
            ulonglong2 w2 = *(const ulonglong2*)&w_s[sel][(i + 2) * 64 + o0];
            ulonglong2 w3 = *(const ulonglong2*)&w_s[sel][(i + 3) * 64 + o0];
            #pragma unroll
            for (int r = 0; r < TR; r++) {
                float4 v = *(const float4*)&in_s[sel][(r0 + r) * 68 + i];
                unsigned long long vx, vy, vz, vw;
                BCAST2(vx, v.x); BCAST2(vy, v.y);
                BCAST2(vz, v.z); BCAST2(vw, v.w);
                FFMA2(a01[r], w0.x, vx); FFMA2(a23[r], w0.y, vx);
                FFMA2(a01[r], w1.x, vy); FFMA2(a23[r], w1.y, vy);
                FFMA2(a01[r], w2.x, vz); FFMA2(a23[r], w2.y, vz);
                FFMA2(a01[r], w3.x, vw); FFMA2(a23[r], w3.y, vw);
            }
        }
        #pragma unroll
        for (int r = 0; r < TR; r++) {
            int rr = r0 + r;
            int ss = rr >> 3, b = rr & 7;
            float* p = (ss == 0) ? p0 : (ss == 1) ? p1 : p2;
            float4 outv;
            UNPACK2(outv.x, outv.y, a01[r]);
            UNPACK2(outv.z, outv.w, a23[r]);
            *(float4*)(p + pix + b * 64 + o0) = outv;
        }
    }
}

// ---------------- per-pixel conv (level 3, S=4), f32x2 packed GEMM ----------
template <int S>
__global__ __launch_bounds__(128, 4) void conv_kernel(
    float* p0, float* p1, float* p2, float* p3, int n) {
    constexpr int R  = S * 8;
    constexpr int TR = R / 8;
    __shared__ float w_s[64 * 64];
    __shared__ float in_s[R * 68];
    int jx = blockIdx.x, jy = blockIdx.y, tid = threadIdx.x;
    float sc = (float)(64.0 / n);
    float yc = fminf(fmaxf((jy + 0.5f) * sc - 0.5f, 0.0f), 63.0f);
    float xc = fminf(fmaxf((jx + 0.5f) * sc - 0.5f, 0.0f), 63.0f);
    int y0 = (int)floorf(yc), x0 = (int)floorf(xc);
    int y1 = min(y0 + 1, 63), x1 = min(x0 + 1, 63);
    float ty = yc - (float)y0, tx = xc - (float)x0;
    float c00 = (1.f - ty) * (1.f - tx), c01 = (1.f - ty) * tx;
    float c10 = ty * (1.f - tx),         c11 = ty * tx;
    const float* w00 = g_wt + ((long)y0 * 64 + x0) * 4096;
    const float* w01 = g_wt + ((long)y0 * 64 + x1) * 4096;
    const float* w10 = g_wt + ((long)y1 * 64 + x0) * 4096;
    const float* w11 = g_wt + ((long)y1 * 64 + x1) * 4096;
    #pragma unroll 4
    for (int c = 0; c < 8; c++) {
        int e = c * 512 + tid * 4;
        float4 a = *(const float4*)(w00 + e);
        float4 b = *(const float4*)(w01 + e);
        float4 d = *(const float4*)(w10 + e);
        float4 f = *(const float4*)(w11 + e);
        float4 wv;
        wv.x = c00 * a.x + c01 * b.x + c10 * d.x + c11 * f.x;
        wv.y = c00 * a.y + c01 * b.y + c10 * d.y + c11 * f.y;
        wv.z = c00 * a.z + c01 * b.z + c10 * d.z + c11 * f.z;
        wv.w = c00 * a.w + c01 * b.w + c10 * d.w + c11 * f.w;
        *(float4*)&w_s[e] = wv;
    }
    long pix = ((long)jy * n + jx) * V;
    {
        int b = tid >> 4, i4 = (tid & 15) * 4;
        #pragma unroll
        for (int ss = 0; ss < S; ss++) {
            const float* p = (ss == 0) ? p0 : (ss == 1) ? p1 : (ss == 2) ? p2 : p3;
            *(float4*)&in_s[(ss * 8 + b) * 68 + i4] = *(const float4*)(p + pix + b * 64 + i4);
        }
    }
    __syncthreads();
    int colg = tid & 15, rowg = tid >> 4;
    int o0 = colg * 4, r0 = rowg * TR;
    unsigned long long a01[TR], a23[TR];
    #pragma unroll
    for (int r = 0; r < TR; r++) { a01[r] = 0ull; a23[r] = 0ull; }
    #pragma unroll 8
    for (int i = 0; i < 64; i += 4) {
        ulonglong2 w0 = *(const ulonglong2*)&w_s[(i + 0) * 64 + o0];
        ulonglong2 w1 = *(const ulonglong2*)&w_s[(i + 1) * 64 + o0];
        ulonglong2 w2 = *(const ulonglong2*)&w_s[(i + 2) * 64 + o0];
        ulonglong2 w3 = *(const ulonglong2*)&w_s[(i + 3) * 64 + o0];
        #pragma unroll
        for (int r = 0; r < TR; r++) {
            float4 v = *(const float4*)&in_s[(r0 + r) * 68 + i];
            unsigned long long vx, vy, vz, vw;
            BCAST2(vx, v.x); BCAST2(vy, v.y);
            BCAST2(vz, v.z); BCAST2(vw, v.w);
            FFMA2(a01[r], w0.x, vx); FFMA2(a23[r], w0.y, vx);
            FFMA2(a01[r], w1.x, vy); FFMA2(a23[r], w1.y, vy);
            FFMA2(a01[r], w2.x, vz); FFMA2(a23[r], w2.y, vz);
            FFMA2(a01[r], w3.x, vw); FFMA2(a23[r], w3.y, vw);
        }
    }
    #pragma unroll
    for (int r = 0; r < TR; r++) {
        int rr = r0 + r;
        int ss = rr >> 3, b = rr & 7;
        float* p = (ss == 0) ? p0 : (ss == 1) ? p1 : (ss == 2) ? p2 : p3;
        float4 outv;
        UNPACK2(outv.x, outv.y, a01[r]);
        UNPACK2(outv.z, outv.w, a23[r]);
        *(float4*)(p + pix + b * 64 + o0) = outv;
    }
}

// ---------------- host ----------------
#define SYM(var, sym) float* var; { void* _p; cudaGetSymbolAddress(&_p, sym); var = (float*)_p; }

extern "C" void kernel_launch(void* const* d_in, const int* in_sizes, int n_in,
                              void* d_out, int out_size) {
    const float* x = (const float*)d_in[0];
    const float* w = (const float*)d_in[1];
    float* out = (float*)d_out;
    SYM(TLO, g_tlo) SYM(THI, g_thi)
    SYM(LL1, g_ll1) SYM(LH1, g_lh1) SYM(HL1, g_hl1) SYM(HH1, g_hh1)
    SYM(LL2, g_ll2) SYM(LH2, g_lh2) SYM(HL2, g_hl2) SYM(HH2, g_hh2)
    SYM(LL3, g_ll3) SYM(LH3, g_lh3) SYM(HL3, g_hl3) SYM(HH3, g_hh3)
    SYM(R2, g_r2)  SYM(WT, g_wt)

    // #1..#3
    wtrans2<<<dim3(8, 2, 128), 256>>>(w, WT);
    afb_w_first<<<dim3(16, 256), 256>>>(x, TLO, THI);
    afb_pair<<<dim3(5, 133, 8), 256>>>(TLO, LL1, LH1, THI, HL1, HH1,
                                       256, 133, 133*512, 512, 133*512, 512);
    // #4: the dominant conv — profiled slot (vertical pairing: grid = (jy-pairs, jx))
    conv2<<<dim3(67, 133), 128>>>(LH1, HL1, HH1, 133);
    // remaining DWT
    afb_kernel<<<dim3(3, 133, 4), 256>>>(LL1, TLO, THI, 133, 72, 512, 133*512, 512, 72*512);
    afb_pair<<<dim3(3, 72, 8), 256>>>(TLO, LL2, LH2, THI, HL2, HH2,
                                      133, 72, 72*512, 512, 72*512, 512);
    conv2<<<dim3(36, 72), 128>>>(LH2, HL2, HH2, 72);
    afb_kernel<<<dim3(2, 72, 4), 256>>>(LL2, TLO, THI, 72, 41, 512, 72*512, 512, 41*512);
    afb_pair<<<dim3(2, 41, 8), 256>>>(TLO, LL3, LH3, THI, HL3, HH3,
                                      72, 41, 41*512, 512, 41*512, 512);
    conv_kernel<4><<<dim3(41, 41), 128>>>(LL3, LH3, HL3, HH3, 41);

    // ---- IDWT ----
    sfb_pair<<<dim3(3, 41, 8), 256>>>(LL3, LH3, TLO, HL3, HH3, THI,
        41, 72, 41*512, 41*512, 512, 41*512, 512, 41*512, 512);
    sfb_kernel<<<dim3(3, 72, 4), 256>>>(TLO, THI, LL2, 41, 72,
        512, 41*512, 512, 41*512, 512, 72*512);
    sfb_pair<<<dim3(5, 72, 8), 256>>>(LL2, LH2, TLO, HL2, HH2, THI,
        72, 134, 72*512, 72*512, 512, 72*512, 512, 72*512, 512);
    sfb_kernel<<<dim3(5, 134, 4), 256>>>(TLO, THI, R2, 72, 134,
        512, 72*512, 512, 72*512, 512, 134*512);
    sfb_pair<<<dim3(8, 133, 8), 256>>>(R2, LH1, TLO, HL1, HH1, THI,
        133, 256, 134*512, 133*512, 512, 133*512, 512, 133*512, 512);
    sfb_w_last<<<dim3(16, 256), 256>>>(TLO, THI, out);
}

// round 15
// speedup vs baseline: 1.1244x; 1.0125x over previous
#include <cuda_runtime.h>

#define V 512

// ---------------- scratch (device globals; no runtime alloc) ----------------
__device__ float g_tlo[256*133*V];
__device__ float g_thi[256*133*V];
__device__ float g_ll1[133*133*V];
__device__ float g_lh1[133*133*V];
__device__ float g_hl1[133*133*V];
__device__ float g_hh1[133*133*V];
__device__ float g_ll2[72*72*V];
__device__ float g_lh2[72*72*V];
__device__ float g_hl2[72*72*V];
__device__ float g_hh2[72*72*V];
__device__ float g_ll3[41*41*V];
__device__ float g_lh3[41*41*V];
__device__ float g_hl3[41*41*V];
__device__ float g_hh3[41*41*V];
__device__ float g_r2 [134*134*V];
__device__ float g_wt [64*64*64*64]; // weights transposed to [gy*64+gx][i][o]

// ---------------- filter taps as literal constants ----------------
#define AFB_TAPS(X) \
  X(0,  0.11154074335008017f,    -0.00107730108499558f)   \
  X(1,  0.4946238903983854f,     -0.004777257511010651f)  \
  X(2,  0.7511339080215775f,      0.0005538422009938016f) \
  X(3,  0.3152503517092432f,      0.031582039318031156f)  \
  X(4, -0.22626469396516913f,     0.02752286553001629f)   \
  X(5, -0.12976686756709563f,    -0.09750160558707936f)   \
  X(6,  0.09750160558707936f,    -0.12976686756709563f)   \
  X(7,  0.02752286553001629f,     0.22626469396516913f)   \
  X(8, -0.031582039318031156f,    0.3152503517092432f)    \
  X(9,  0.0005538422009938016f,  -0.7511339080215775f)    \
  X(10, 0.004777257511010651f,    0.4946238903983854f)    \
  X(11,-0.00107730108499558f,    -0.11154074335008017f)

#define SFB_EVEN(X) \
  X(0,  0.004777257511010651f,    0.4946238903983854f)    \
  X(1, -0.031582039318031156f,    0.3152503517092432f)    \
  X(2,  0.09750160558707936f,    -0.12976686756709563f)   \
  X(3, -0.22626469396516913f,     0.02752286553001629f)   \
  X(4,  0.7511339080215775f,      0.0005538422009938016f) \
  X(5,  0.11154074335008017f,    -0.00107730108499558f)
#define SFB_ODD(X) \
  X(0, -0.00107730108499558f,    -0.11154074335008017f)   \
  X(1,  0.0005538422009938016f,  -0.7511339080215775f)    \
  X(2,  0.02752286553001629f,     0.22626469396516913f)   \
  X(3, -0.12976686756709563f,    -0.09750160558707936f)   \
  X(4,  0.3152503517092432f,      0.031582039318031156f)  \
  X(5,  0.4946238903983854f,     -0.004777257511010651f)

// packed fp32x2 FMA helpers (Blackwell FFMA2 — only reachable via PTX)
#define FFMA2(acc, w2, v2) \
    asm("fma.rn.f32x2 %0, %1, %2, %3;" : "=l"(acc) : "l"(w2), "l"(v2), "l"(acc))
#define BCAST2(dst, f) \
    asm("mov.b64 %0, {%1, %1};" : "=l"(dst) : "r"(__float_as_uint(f)))
#define UNPACK2(lo, hi, p) \
    asm("mov.b64 {%0, %1}, %2;" : "=f"(lo), "=f"(hi) : "l"(p))

// ---------------- weight transpose: in[i][o][c] -> out[c][i][o] -------------
__global__ __launch_bounds__(256) void wtrans2(const float* __restrict__ in,
                                               float* __restrict__ out) {
    __shared__ float t[8][32][33];
    int i0 = blockIdx.x * 8, o0 = blockIdx.y * 32, c0 = blockIdx.z * 32;
    int tid = threadIdx.x;
    for (int l = tid; l < 8192; l += 256) {
        int ii = l >> 10, rest = l & 1023;
        int oy = rest >> 5, cx = rest & 31;
        t[ii][oy][cx] = in[(long)(i0 + ii) * 262144 + (long)(o0 + oy) * 4096 + c0 + cx];
    }
    __syncthreads();
    int ii = tid >> 5, ox = tid & 31;
    long ob = (long)(i0 + ii) * 64 + o0 + ox;
    #pragma unroll
    for (int cr = 0; cr < 32; cr++)
        out[(long)(c0 + cr) * 4096 + ob] = t[ii][ox][cr];
}

// ---------------- fused: NCHW input -> level-1 W-direction afb -> HWC -------
__global__ __launch_bounds__(256) void afb_w_first(const float* __restrict__ x,
    float* __restrict__ lo, float* __restrict__ hi) {
    __shared__ float srow[32][277];
    int y = blockIdx.y, q0 = blockIdx.x * 32;
    int tid = threadIdx.x;
    for (int idx = tid; idx < 32 * 276; idx += 256) {
        int ql = idx / 276, ew = idx - ql * 276;
        int t = ew - 10;
        t = (t < 0) ? (-1 - t) : ((t >= 256) ? (511 - t) : t);
        srow[ql][ew] = x[(q0 + ql) * 65536 + y * 256 + t];
    }
    __syncthreads();
    int ql = tid & 31, jj = tid >> 5;
    int j0 = jj * 17;
    float w[12];
    #pragma unroll
    for (int k = 0; k < 12; k++) w[k] = srow[ql][2 * j0 + k];
    int ob = y * 133 * 512 + q0 + ql;
    #pragma unroll
    for (int u = 0; u < 17; u++) {
        int j = j0 + u;
        if (j < 133) {
            float alo = 0.f, ahi = 0.f;
#define TAP(K, CLO, CHI) { float xv = w[K]; alo += (CLO) * xv; ahi += (CHI) * xv; }
            AFB_TAPS(TAP)
#undef TAP
            lo[ob + j * 512] = alo;
            hi[ob + j * 512] = ahi;
        }
        if (u < 16 && j < 132) {
            #pragma unroll
            for (int k = 0; k < 10; k++) w[k] = w[k + 2];
            w[10] = srow[ql][2 * j + 12];
            w[11] = srow[ql][2 * j + 13];
        }
    }
}

// ---------------- fused: final W-direction sfb -> NCHW output ---------------
__global__ __launch_bounds__(256) void sfb_w_last(const float* __restrict__ lo,
    const float* __restrict__ hi, float* __restrict__ out) {
    __shared__ float sout[256][33];
    int y = blockIdx.y, q0 = blockIdx.x * 32;
    int tid = threadIdx.x, ql = tid & 31, mm = tid >> 5;
    int m0 = mm * 32;
    const float* plo = lo + y * 133 * 512 + q0 + ql;
    const float* phi = hi + y * 133 * 512 + q0 + ql;
    int t0 = m0 >> 1;
    float wl[6], wh[6];
    #pragma unroll
    for (int k = 0; k < 6; k++) {
        wl[k] = plo[(t0 + k) * 512];
        wh[k] = phi[(t0 + k) * 512];
    }
    #pragma unroll
    for (int p = 0; p < 16; p++) {
        float ae = 0.f, ao = 0.f;
#define ETAP(KK, CLO, CHI) { ae += (CLO) * wl[KK]; ae += (CHI) * wh[KK]; }
        SFB_EVEN(ETAP)
#undef ETAP
#define OTAP(KK, CLO, CHI) { ao += (CLO) * wl[KK]; ao += (CHI) * wh[KK]; }
        SFB_ODD(OTAP)
#undef OTAP
        sout[m0 + 2 * p][ql]     = ae;
        sout[m0 + 2 * p + 1][ql] = ao;
        if (p < 15) {
            #pragma unroll
            for (int k = 0; k < 5; k++) { wl[k] = wl[k + 1]; wh[k] = wh[k + 1]; }
            int t = t0 + p + 6;
            wl[5] = plo[t * 512];
            wh[5] = phi[t * 512];
        }
    }
    __syncthreads();
    int obase = y * 256 + tid;
    #pragma unroll
    for (int i = 0; i < 32; i++)
        out[(q0 + i) * 65536 + obase] = sout[tid][i];
}

// ---------------- afb core (sliding window, 4 outputs/thread) ---------------
__device__ __forceinline__ void afb_core(
    const float* __restrict__ in, float* __restrict__ lo, float* __restrict__ hi,
    int nf_in, int nf_out, int sf_in, int so_in, int sf_out, int so_out,
    int bx, int by, int bz) {
    int lane = threadIdx.x & 31;
    int jj = threadIdx.x >> 5;
    int j0 = (bx * 8 + jj) * 4;
    if (j0 >= nf_out) return;
    int vo = bz * 128 + lane * 4;
    const float* pin = in + by * so_in + vo;
    int tb = 2 * j0 - 10;
    float4 w[12];
    #pragma unroll
    for (int k = 0; k < 12; k++) {
        int t = tb + k;
        t = (t < 0) ? (-1 - t) : ((t >= nf_in) ? (2 * nf_in - 1 - t) : t);
        w[k] = *(const float4*)(pin + t * sf_in);
    }
    int oo = by * so_out + j0 * sf_out + vo;
    float* plo = lo + oo;
    float* phi = hi + oo;
    #pragma unroll
    for (int u = 0; u < 4; u++) {
        if (j0 + u < nf_out) {
            float4 alo = {0.f,0.f,0.f,0.f}, ahi = {0.f,0.f,0.f,0.f};
#define TAP(K, CLO, CHI) { float4 xv = w[K];                                   \
            alo.x += (CLO) * xv.x; alo.y += (CLO) * xv.y;                      \
            alo.z += (CLO) * xv.z; alo.w += (CLO) * xv.w;                      \
            ahi.x += (CHI) * xv.x; ahi.y += (CHI) * xv.y;                      \
            ahi.z += (CHI) * xv.z; ahi.w += (CHI) * xv.w; }
            AFB_TAPS(TAP)
#undef TAP
            *(float4*)plo = alo;
            *(float4*)phi = ahi;
        }
        if (u < 3) {
            #pragma unroll
            for (int k = 0; k < 10; k++) w[k] = w[k + 2];
            int t0n = tb + 12 + 2 * u;
            int t1n = t0n + 1;
            t0n = (t0n >= nf_in) ? (2 * nf_in - 1 - t0n) : t0n;
            t1n = (t1n >= nf_in) ? (2 * nf_in - 1 - t1n) : t1n;
            w[10] = *(const float4*)(pin + t0n * sf_in);
            w[11] = *(const float4*)(pin + t1n * sf_in);
            plo += sf_out;
            phi += sf_out;
        }
    }
}

__global__ __launch_bounds__(256) void afb_kernel(
    const float* __restrict__ in, float* __restrict__ lo, float* __restrict__ hi,
    int nf_in, int nf_out, int sf_in, int so_in, int sf_out, int so_out) {
    afb_core(in, lo, hi, nf_in, nf_out, sf_in, so_in, sf_out, so_out,
             blockIdx.x, blockIdx.y, blockIdx.z);
}

__global__ __launch_bounds__(256) void afb_pair(
    const float* __restrict__ in0, float* __restrict__ lo0, float* __restrict__ hi0,
    const float* __restrict__ in1, float* __restrict__ lo1, float* __restrict__ hi1,
    int nf_in, int nf_out, int sf_in, int so_in, int sf_out, int so_out) {
    int sel = blockIdx.z >> 2, bz = blockIdx.z & 3;
    afb_core(sel ? in1 : in0, sel ? lo1 : lo0, sel ? hi1 : hi0,
             nf_in, nf_out, sf_in, so_in, sf_out, so_out,
             blockIdx.x, blockIdx.y, bz);
}

// ---------------- sfb core (sliding window, 4 outputs/thread) ---------------
__device__ __forceinline__ void sfb_core(
    const float* __restrict__ lo, const float* __restrict__ hi, float* __restrict__ out,
    int n_t, int nf_out, int sflo, int solo, int sfhi, int sohi,
    int sf_out, int so_out, int bx, int by, int bz) {
    int lane = threadIdx.x & 31;
    int mm = threadIdx.x >> 5;
    int m0 = (bx * 8 + mm) * 4;
    if (m0 >= nf_out) return;
    int vo = bz * 128 + lane * 4;
    const float* plo = lo + by * solo + vo;
    const float* phi = hi + by * sohi + vo;
    int t0 = m0 >> 1;
    float4 wl[6], wh[6];
    #pragma unroll
    for (int k = 0; k < 6; k++) {
        int t = t0 + k;
        bool ok = (unsigned)t < (unsigned)n_t;
        wl[k] = ok ? *(const float4*)(plo + t * sflo) : make_float4(0.f,0.f,0.f,0.f);
        wh[k] = ok ? *(const float4*)(phi + t * sfhi) : make_float4(0.f,0.f,0.f,0.f);
    }
    float* pout = out + by * so_out + m0 * sf_out + vo;
    #pragma unroll
    for (int p = 0; p < 2; p++) {
        float4 ae = {0.f,0.f,0.f,0.f}, ao = {0.f,0.f,0.f,0.f};
#define ETAP(KK, CLO, CHI) { float4 a = wl[KK]; float4 b = wh[KK];             \
        ae.x += (CLO)*a.x; ae.x += (CHI)*b.x;  ae.y += (CLO)*a.y; ae.y += (CHI)*b.y; \
        ae.z += (CLO)*a.z; ae.z += (CHI)*b.z;  ae.w += (CLO)*a.w; ae.w += (CHI)*b.w; }
        SFB_EVEN(ETAP)
#undef ETAP
#define OTAP(KK, CLO, CHI) { float4 a = wl[KK]; float4 b = wh[KK];             \
        ao.x += (CLO)*a.x; ao.x += (CHI)*b.x;  ao.y += (CLO)*a.y; ao.y += (CHI)*b.y; \
        ao.z += (CLO)*a.z; ao.z += (CHI)*b.z;  ao.w += (CLO)*a.w; ao.w += (CHI)*b.w; }
        SFB_ODD(OTAP)
#undef OTAP
        int me = m0 + 2 * p;
        if (me < nf_out)     *(float4*)pout = ae;
        if (me + 1 < nf_out) *(float4*)(pout + sf_out) = ao;
        if (p == 0) {
            #pragma unroll
            for (int k = 0; k < 5; k++) { wl[k] = wl[k + 1]; wh[k] = wh[k + 1]; }
            int t = t0 + 6;
            bool ok = (unsigned)t < (unsigned)n_t;
            wl[5] = ok ? *(const float4*)(plo + t * sflo) : make_float4(0.f,0.f,0.f,0.f);
            wh[5] = ok ? *(const float4*)(phi + t * sfhi) : make_float4(0.f,0.f,0.f,0.f);
            pout += 2 * sf_out;
        }
    }
}

__global__ __launch_bounds__(256) void sfb_kernel(
    const float* __restrict__ lo, const float* __restrict__ hi, float* __restrict__ out,
    int n_t, int nf_out, int sflo, int solo, int sfhi, int sohi,
    int sf_out, int so_out) {
    sfb_core(lo, hi, out, n_t, nf_out, sflo, solo, sfhi, sohi, sf_out, so_out,
             blockIdx.x, blockIdx.y, blockIdx.z);
}

__global__ __launch_bounds__(256) void sfb_pair(
    const float* __restrict__ lo0, const float* __restrict__ hi0, float* __restrict__ out0,
    const float* __restrict__ lo1, const float* __restrict__ hi1, float* __restrict__ out1,
    int n_t, int nf_out, int sflo0, int sflo1, int solo, int sfhi, int sohi,
    int sf_out, int so_out) {
    int sel = blockIdx.z >> 2, bz = blockIdx.z & 3;
    sfb_core(sel ? lo1 : lo0, sel ? hi1 : hi0, sel ? out1 : out0,
             n_t, nf_out, sel ? sflo1 : sflo0, solo, sfhi, sohi, sf_out, so_out,
             blockIdx.x, blockIdx.y, bz);
}

// ---------------- conv: 2 vertical pixels/CTA, SHARED corner loads ----------
// x-cell identical for both pixels; y0B in {y0A, y0A+1}. Cooperative blend:
//   same y-cell  -> 4 corner LDG streams feed both w_s buffers
//   adjacent     -> 6 corner LDG streams (middle row shared)
__global__ __launch_bounds__(128, 4) void conv2(
    float* p0, float* p1, float* p2, int n) {
    constexpr int S = 3;
    constexpr int R = S * 8;          // 24
    constexpr int TR = R / 4;         // 6 rows per thread
    __shared__ float w_s[2][64 * 64];
    __shared__ float in_s[2][R * 68];
    int tid = threadIdx.x;
    int sel = tid >> 6, t = tid & 63;
    int jx = blockIdx.y;
    int jyA = blockIdx.x * 2;
    int jy = jyA + sel;
    bool act = jy < n;
    float sc = (float)(64.0 / n);
    float xc = fminf(fmaxf((jx + 0.5f) * sc - 0.5f, 0.0f), 63.0f);
    int x0 = (int)floorf(xc), x1 = min(x0 + 1, 63);
    float tx = xc - (float)x0;
    float ycA = fminf(fmaxf((jyA + 0.5f) * sc - 0.5f, 0.0f), 63.0f);
    int jyBc = min(jyA + 1, n - 1);
    float ycB = fminf(fmaxf((jyBc + 0.5f) * sc - 0.5f, 0.0f), 63.0f);
    int y0A = (int)floorf(ycA), y0B = (int)floorf(ycB);
    float tyA = ycA - (float)y0A, tyB = ycB - (float)y0B;
    float c00A = (1.f - tyA) * (1.f - tx), c01A = (1.f - tyA) * tx;
    float c10A = tyA * (1.f - tx),         c11A = tyA * tx;
    float c00B = (1.f - tyB) * (1.f - tx), c01B = (1.f - tyB) * tx;
    float c10B = tyB * (1.f - tx),         c11B = tyB * tx;

    if (y0B == y0A) {
        // both pixels share the 4 corners; 4 LDG streams, 2 blended outputs
        int y1 = min(y0A + 1, 63);
        const float* w00 = g_wt + ((long)y0A * 64 + x0) * 4096;
        const float* w01 = g_wt + ((long)y0A * 64 + x1) * 4096;
        const float* w10 = g_wt + ((long)y1  * 64 + x0) * 4096;
        const float* w11 = g_wt + ((long)y1  * 64 + x1) * 4096;
        #pragma unroll 4
        for (int it = 0; it < 8; it++) {
            int e = it * 512 + tid * 4;
            float4 a = *(const float4*)(w00 + e);
            float4 b = *(const float4*)(w01 + e);
            float4 d = *(const float4*)(w10 + e);
            float4 f = *(const float4*)(w11 + e);
            float4 wa, wb;
            wa.x = c00A*a.x + c01A*b.x + c10A*d.x + c11A*f.x;
            wa.y = c00A*a.y + c01A*b.y + c10A*d.y + c11A*f.y;
            wa.z = c00A*a.z + c01A*b.z + c10A*d.z + c11A*f.z;
            wa.w = c00A*a.w + c01A*b.w + c10A*d.w + c11A*f.w;
            wb.x = c00B*a.x + c01B*b.x + c10B*d.x + c11B*f.x;
            wb.y = c00B*a.y + c01B*b.y + c10B*d.y + c11B*f.y;
            wb.z = c00B*a.z + c01B*b.z + c10B*d.z + c11B*f.z;
            wb.w = c00B*a.w + c01B*b.w + c10B*d.w + c11B*f.w;
            *(float4*)&w_s[0][e] = wa;
            *(float4*)&w_s[1][e] = wb;
        }
    } else {
        // rows r0 (A only), r1 (shared), r2 (B only): 6 LDG streams
        int r0 = y0A, r1 = y0A + 1, r2 = min(y0A + 2, 63);
        const float* wa0 = g_wt + ((long)r0 * 64 + x0) * 4096;
        const float* wa1 = g_wt + ((long)r0 * 64 + x1) * 4096;
        const float* wm0 = g_wt + ((long)r1 * 64 + x0) * 4096;
        const float* wm1 = g_wt + ((long)r1 * 64 + x1) * 4096;
        const float* wb0 = g_wt + ((long)r2 * 64 + x0) * 4096;
        const float* wb1 = g_wt + ((long)r2 * 64 + x1) * 4096;
        #pragma unroll 2
        for (int it = 0; it < 8; it++) {
            int e = it * 512 + tid * 4;
            float4 a0 = *(const float4*)(wa0 + e);
            float4 a1 = *(const float4*)(wa1 + e);
            float4 m0 = *(const float4*)(wm0 + e);
            float4 m1 = *(const float4*)(wm1 + e);
            float4 b0 = *(const float4*)(wb0 + e);
            float4 b1 = *(const float4*)(wb1 + e);
            float4 wa, wb;
            wa.x = c00A*a0.x + c01A*a1.x + c10A*m0.x + c11A*m1.x;
            wa.y = c00A*a0.y + c01A*a1.y + c10A*m0.y + c11A*m1.y;
            wa.z = c00A*a0.z + c01A*a1.z + c10A*m0.z + c11A*m1.z;
            wa.w = c00A*a0.w + c01A*a1.w + c10A*m0.w + c11A*m1.w;
            wb.x = c00B*m0.x + c01B*m1.x + c10B*b0.x + c11B*b1.x;
            wb.y = c00B*m0.y + c01B*m1.y + c10B*b0.y + c11B*b1.y;
            wb.z = c00B*m0.z + c01B*m1.z + c10B*b0.z + c11B*b1.z;
            wb.w = c00B*m0.w + c01B*m1.w + c10B*b0.w + c11B*b1.w;
            *(float4*)&w_s[0][e] = wa;
            *(float4*)&w_s[1][e] = wb;
        }
    }

    long pix = ((long)jy * n + jx) * V;
    if (act) {
        #pragma unroll
        for (int l = 0; l < R / 4; l++) {
            int idx = l * 64 + t;
            int r = idx >> 4, i4 = (idx & 15) * 4;
            int ss = r >> 3, b = r & 7;
            const float* p = (ss == 0) ? p0 : (ss == 1) ? p1 : p2;
            *(float4*)&in_s[sel][r * 68 + i4] = *(const float4*)(p + pix + b * 64 + i4);
        }
    }
    __syncthreads();
    if (act) {
        int colg = t & 15, rowg = t >> 4;
        int o0 = colg * 4, r0 = rowg * TR;
        unsigned long long a01[TR], a23[TR];
        #pragma unroll
        for (int r = 0; r < TR; r++) { a01[r] = 0ull; a23[r] = 0ull; }
        #pragma unroll 8
        for (int i = 0; i < 64; i += 4) {
            ulonglong2 w0 = *(const ulonglong2*)&w_s[sel][(i + 0) * 64 + o0];
            ulonglong2 w1 = *(const ulonglong2*)&w_s[sel][(i + 1) * 64 + o0];
            ulonglong2 w2 = *(const ulonglong2*)&w_s[sel][(i + 2) * 64 + o0];
            ulonglong2 w3 = *(const ulonglong2*)&w_s[sel][(i + 3) * 64 + o0];
            #pragma unroll
            for (int r = 0; r < TR; r++) {
                float4 v = *(const float4*)&in_s[sel][(r0 + r) * 68 + i];
                unsigned long long vx, vy, vz, vw;
                BCAST2(vx, v.x); BCAST2(vy, v.y);
                BCAST2(vz, v.z); BCAST2(vw, v.w);
                FFMA2(a01[r], w0.x, vx); FFMA2(a23[r], w0.y, vx);
                FFMA2(a01[r], w1.x, vy); FFMA2(a23[r], w1.y, vy);
                FFMA2(a01[r], w2.x, vz); FFMA2(a23[r], w2.y, vz);
                FFMA2(a01[r], w3.x, vw); FFMA2(a23[r], w3.y, vw);
            }
        }
        #pragma unroll
        for (int r = 0; r < TR; r++) {
            int rr = r0 + r;
            int ss = rr >> 3, b = rr & 7;
            float* p = (ss == 0) ? p0 : (ss == 1) ? p1 : p2;
            float4 outv;
            UNPACK2(outv.x, outv.y, a01[r]);
            UNPACK2(outv.z, outv.w, a23[r]);
            *(float4*)(p + pix + b * 64 + o0) = outv;
        }
    }
}

// ---------------- per-pixel conv (level 3, S=4), f32x2 packed GEMM ----------
template <int S>
__global__ __launch_bounds__(128, 4) void conv_kernel(
    float* p0, float* p1, float* p2, float* p3, int n) {
    constexpr int R  = S * 8;
    constexpr int TR = R / 8;
    __shared__ float w_s[64 * 64];
    __shared__ float in_s[R * 68];
    int jx = blockIdx.x, jy = blockIdx.y, tid = threadIdx.x;
    float sc = (float)(64.0 / n);
    float yc = fminf(fmaxf((jy + 0.5f) * sc - 0.5f, 0.0f), 63.0f);
    float xc = fminf(fmaxf((jx + 0.5f) * sc - 0.5f, 0.0f), 63.0f);
    int y0 = (int)floorf(yc), x0 = (int)floorf(xc);
    int y1 = min(y0 + 1, 63), x1 = min(x0 + 1, 63);
    float ty = yc - (float)y0, tx = xc - (float)x0;
    float c00 = (1.f - ty) * (1.f - tx), c01 = (1.f - ty) * tx;
    float c10 = ty * (1.f - tx),         c11 = ty * tx;
    const float* w00 = g_wt + ((long)y0 * 64 + x0) * 4096;
    const float* w01 = g_wt + ((long)y0 * 64 + x1) * 4096;
    const float* w10 = g_wt + ((long)y1 * 64 + x0) * 4096;
    const float* w11 = g_wt + ((long)y1 * 64 + x1) * 4096;
    #pragma unroll 4
    for (int c = 0; c < 8; c++) {
        int e = c * 512 + tid * 4;
        float4 a = *(const float4*)(w00 + e);
        float4 b = *(const float4*)(w01 + e);
        float4 d = *(const float4*)(w10 + e);
        float4 f = *(const float4*)(w11 + e);
        float4 wv;
        wv.x = c00 * a.x + c01 * b.x + c10 * d.x + c11 * f.x;
        wv.y = c00 * a.y + c01 * b.y + c10 * d.y + c11 * f.y;
        wv.z = c00 * a.z + c01 * b.z + c10 * d.z + c11 * f.z;
        wv.w = c00 * a.w + c01 * b.w + c10 * d.w + c11 * f.w;
        *(float4*)&w_s[e] = wv;
    }
    long pix = ((long)jy * n + jx) * V;
    {
        int b = tid >> 4, i4 = (tid & 15) * 4;
        #pragma unroll
        for (int ss = 0; ss < S; ss++) {
            const float* p = (ss == 0) ? p0 : (ss == 1) ? p1 : (ss == 2) ? p2 : p3;
            *(float4*)&in_s[(ss * 8 + b) * 68 + i4] = *(const float4*)(p + pix + b * 64 + i4);
        }
    }
    __syncthreads();
    int colg = tid & 15, rowg = tid >> 4;
    int o0 = colg * 4, r0 = rowg * TR;
    unsigned long long a01[TR], a23[TR];
    #pragma unroll
    for (int r = 0; r < TR; r++) { a01[r] = 0ull; a23[r] = 0ull; }
    #pragma unroll 8
    for (int i = 0; i < 64; i += 4) {
        ulonglong2 w0 = *(const ulonglong2*)&w_s[(i + 0) * 64 + o0];
        ulonglong2 w1 = *(const ulonglong2*)&w_s[(i + 1) * 64 + o0];
        ulonglong2 w2 = *(const ulonglong2*)&w_s[(i + 2) * 64 + o0];
        ulonglong2 w3 = *(const ulonglong2*)&w_s[(i + 3) * 64 + o0];
        #pragma unroll
        for (int r = 0; r < TR; r++) {
            float4 v = *(const float4*)&in_s[(r0 + r) * 68 + i];
            unsigned long long vx, vy, vz, vw;
            BCAST2(vx, v.x); BCAST2(vy, v.y);
            BCAST2(vz, v.z); BCAST2(vw, v.w);
            FFMA2(a01[r], w0.x, vx); FFMA2(a23[r], w0.y, vx);
            FFMA2(a01[r], w1.x, vy); FFMA2(a23[r], w1.y, vy);
            FFMA2(a01[r], w2.x, vz); FFMA2(a23[r], w2.y, vz);
            FFMA2(a01[r], w3.x, vw); FFMA2(a23[r], w3.y, vw);
        }
    }
    #pragma unroll
    for (int r = 0; r < TR; r++) {
        int rr = r0 + r;
        int ss = rr >> 3, b = rr & 7;
        float* p = (ss == 0) ? p0 : (ss == 1) ? p1 : (ss == 2) ? p2 : p3;
        float4 outv;
        UNPACK2(outv.x, outv.y, a01[r]);
        UNPACK2(outv.z, outv.w, a23[r]);
        *(float4*)(p + pix + b * 64 + o0) = outv;
    }
}

// ---------------- host ----------------
#define SYM(var, sym) float* var; { void* _p; cudaGetSymbolAddress(&_p, sym); var = (float*)_p; }

extern "C" void kernel_launch(void* const* d_in, const int* in_sizes, int n_in,
                              void* d_out, int out_size) {
    const float* x = (const float*)d_in[0];
    const float* w = (const float*)d_in[1];
    float* out = (float*)d_out;
    SYM(TLO, g_tlo) SYM(THI, g_thi)
    SYM(LL1, g_ll1) SYM(LH1, g_lh1) SYM(HL1, g_hl1) SYM(HH1, g_hh1)
    SYM(LL2, g_ll2) SYM(LH2, g_lh2) SYM(HL2, g_hl2) SYM(HH2, g_hh2)
    SYM(LL3, g_ll3) SYM(LH3, g_lh3) SYM(HL3, g_hl3) SYM(HH3, g_hh3)
    SYM(R2, g_r2)  SYM(WT, g_wt)

    // #1..#3
    wtrans2<<<dim3(8, 2, 128), 256>>>(w, WT);
    afb_w_first<<<dim3(16, 256), 256>>>(x, TLO, THI);
    afb_pair<<<dim3(5, 133, 8), 256>>>(TLO, LL1, LH1, THI, HL1, HH1,
                                       256, 133, 133*512, 512, 133*512, 512);
    // #4: the dominant conv — profiled slot
    conv2<<<dim3(67, 133), 128>>>(LH1, HL1, HH1, 133);
    // remaining DWT
    afb_kernel<<<dim3(3, 133, 4), 256>>>(LL1, TLO, THI, 133, 72, 512, 133*512, 512, 72*512);
    afb_pair<<<dim3(3, 72, 8), 256>>>(TLO, LL2, LH2, THI, HL2, HH2,
                                      133, 72, 72*512, 512, 72*512, 512);
    conv2<<<dim3(36, 72), 128>>>(LH2, HL2, HH2, 72);
    afb_kernel<<<dim3(2, 72, 4), 256>>>(LL2, TLO, THI, 72, 41, 512, 72*512, 512, 41*512);
    afb_pair<<<dim3(2, 41, 8), 256>>>(TLO, LL3, LH3, THI, HL3, HH3,
                                      72, 41, 41*512, 512, 41*512, 512);
    conv_kernel<4><<<dim3(41, 41), 128>>>(LL3, LH3, HL3, HH3, 41);

    // ---- IDWT ----
    sfb_pair<<<dim3(3, 41, 8), 256>>>(LL3, LH3, TLO, HL3, HH3, THI,
        41, 72, 41*512, 41*512, 512, 41*512, 512, 41*512, 512);
    sfb_kernel<<<dim3(3, 72, 4), 256>>>(TLO, THI, LL2, 41, 72,
        512, 41*512, 512, 41*512, 512, 72*512);
    sfb_pair<<<dim3(5, 72, 8), 256>>>(LL2, LH2, TLO, HL2, HH2, THI,
        72, 134, 72*512, 72*512, 512, 72*512, 512, 72*512, 512);
    sfb_kernel<<<dim3(5, 134, 4), 256>>>(TLO, THI, R2, 72, 134,
        512, 72*512, 512, 72*512, 512, 134*512);
    sfb_pair<<<dim3(8, 133, 8), 256>>>(R2, LH1, TLO, HL1, HH1, THI,
        133, 256, 134*512, 133*512, 512, 133*512, 512, 133*512, 512);
    sfb_w_last<<<dim3(16, 256), 256>>>(TLO, THI, out);
}

// round 17
// speedup vs baseline: 1.1281x; 1.0033x over previous
#include <cuda_runtime.h>

#define V 512

// ---------------- scratch (device globals; no runtime alloc) ----------------
__device__ float g_tlo[256*133*V];
__device__ float g_thi[256*133*V];
__device__ float g_ll1[133*133*V];
__device__ float g_lh1[133*133*V];
__device__ float g_hl1[133*133*V];
__device__ float g_hh1[133*133*V];
__device__ float g_ll2[72*72*V];
__device__ float g_lh2[72*72*V];
__device__ float g_hl2[72*72*V];
__device__ float g_hh2[72*72*V];
__device__ float g_ll3[41*41*V];
__device__ float g_lh3[41*41*V];
__device__ float g_hl3[41*41*V];
__device__ float g_hh3[41*41*V];
__device__ float g_r2 [134*134*V];
__device__ float g_wt [64*64*64*64]; // weights transposed to [gy*64+gx][i][o]

// ---------------- filter taps as literal constants ----------------
#define AFB_TAPS(X) \
  X(0,  0.11154074335008017f,    -0.00107730108499558f)   \
  X(1,  0.4946238903983854f,     -0.004777257511010651f)  \
  X(2,  0.7511339080215775f,      0.0005538422009938016f) \
  X(3,  0.3152503517092432f,      0.031582039318031156f)  \
  X(4, -0.22626469396516913f,     0.02752286553001629f)   \
  X(5, -0.12976686756709563f,    -0.09750160558707936f)   \
  X(6,  0.09750160558707936f,    -0.12976686756709563f)   \
  X(7,  0.02752286553001629f,     0.22626469396516913f)   \
  X(8, -0.031582039318031156f,    0.3152503517092432f)    \
  X(9,  0.0005538422009938016f,  -0.7511339080215775f)    \
  X(10, 0.004777257511010651f,    0.4946238903983854f)    \
  X(11,-0.00107730108499558f,    -0.11154074335008017f)

#define SFB_EVEN(X) \
  X(0,  0.004777257511010651f,    0.4946238903983854f)    \
  X(1, -0.031582039318031156f,    0.3152503517092432f)    \
  X(2,  0.09750160558707936f,    -0.12976686756709563f)   \
  X(3, -0.22626469396516913f,     0.02752286553001629f)   \
  X(4,  0.7511339080215775f,      0.0005538422009938016f) \
  X(5,  0.11154074335008017f,    -0.00107730108499558f)
#define SFB_ODD(X) \
  X(0, -0.00107730108499558f,    -0.11154074335008017f)   \
  X(1,  0.0005538422009938016f,  -0.7511339080215775f)    \
  X(2,  0.02752286553001629f,     0.22626469396516913f)   \
  X(3, -0.12976686756709563f,    -0.09750160558707936f)   \
  X(4,  0.3152503517092432f,      0.031582039318031156f)  \
  X(5,  0.4946238903983854f,     -0.004777257511010651f)

// packed fp32x2 FMA helpers (Blackwell FFMA2 — only reachable via PTX)
#define FFMA2(acc, w2, v2) \
    asm("fma.rn.f32x2 %0, %1, %2, %3;" : "=l"(acc) : "l"(w2), "l"(v2), "l"(acc))
#define BCAST2(dst, f) \
    asm("mov.b64 %0, {%1, %1};" : "=l"(dst) : "r"(__float_as_uint(f)))
#define UNPACK2(lo, hi, p) \
    asm("mov.b64 {%0, %1}, %2;" : "=f"(lo), "=f"(hi) : "l"(p))

// ---------------- weight transpose: in[i][o][c] -> out[c][i][o] -------------
__global__ __launch_bounds__(256) void wtrans2(const float* __restrict__ in,
                                               float* __restrict__ out) {
    __shared__ float t[8][32][33];
    int i0 = blockIdx.x * 8, o0 = blockIdx.y * 32, c0 = blockIdx.z * 32;
    int tid = threadIdx.x;
    for (int l = tid; l < 8192; l += 256) {
        int ii = l >> 10, rest = l & 1023;
        int oy = rest >> 5, cx = rest & 31;
        t[ii][oy][cx] = in[(long)(i0 + ii) * 262144 + (long)(o0 + oy) * 4096 + c0 + cx];
    }
    __syncthreads();
    int ii = tid >> 5, ox = tid & 31;
    long ob = (long)(i0 + ii) * 64 + o0 + ox;
    #pragma unroll
    for (int cr = 0; cr < 32; cr++)
        out[(long)(c0 + cr) * 4096 + ob] = t[ii][ox][cr];
}

// ---------------- fused: NCHW input -> level-1 W-direction afb -> HWC -------
__global__ __launch_bounds__(256) void afb_w_first(const float* __restrict__ x,
    float* __restrict__ lo, float* __restrict__ hi) {
    __shared__ float srow[32][277];
    int y = blockIdx.y, q0 = blockIdx.x * 32;
    int tid = threadIdx.x;
    for (int idx = tid; idx < 32 * 276; idx += 256) {
        int ql = idx / 276, ew = idx - ql * 276;
        int t = ew - 10;
        t = (t < 0) ? (-1 - t) : ((t >= 256) ? (511 - t) : t);
        srow[ql][ew] = x[(q0 + ql) * 65536 + y * 256 + t];
    }
    __syncthreads();
    int ql = tid & 31, jj = tid >> 5;
    int j0 = jj * 17;
    float w[12];
    #pragma unroll
    for (int k = 0; k < 12; k++) w[k] = srow[ql][2 * j0 + k];
    int ob = y * 133 * 512 + q0 + ql;
    #pragma unroll
    for (int u = 0; u < 17; u++) {
        int j = j0 + u;
        if (j < 133) {
            float alo = 0.f, ahi = 0.f;
#define TAP(K, CLO, CHI) { float xv = w[K]; alo += (CLO) * xv; ahi += (CHI) * xv; }
            AFB_TAPS(TAP)
#undef TAP
            lo[ob + j * 512] = alo;
            hi[ob + j * 512] = ahi;
        }
        if (u < 16 && j < 132) {
            #pragma unroll
            for (int k = 0; k < 10; k++) w[k] = w[k + 2];
            w[10] = srow[ql][2 * j + 12];
            w[11] = srow[ql][2 * j + 13];
        }
    }
}

// ---------------- fused: final W-direction sfb -> NCHW output ---------------
__global__ __launch_bounds__(256) void sfb_w_last(const float* __restrict__ lo,
    const float* __restrict__ hi, float* __restrict__ out) {
    __shared__ float sout[256][33];
    int y = blockIdx.y, q0 = blockIdx.x * 32;
    int tid = threadIdx.x, ql = tid & 31, mm = tid >> 5;
    int m0 = mm * 32;
    const float* plo = lo + y * 133 * 512 + q0 + ql;
    const float* phi = hi + y * 133 * 512 + q0 + ql;
    int t0 = m0 >> 1;
    float wl[6], wh[6];
    #pragma unroll
    for (int k = 0; k < 6; k++) {
        wl[k] = plo[(t0 + k) * 512];
        wh[k] = phi[(t0 + k) * 512];
    }
    #pragma unroll
    for (int p = 0; p < 16; p++) {
        float ae = 0.f, ao = 0.f;
#define ETAP(KK, CLO, CHI) { ae += (CLO) * wl[KK]; ae += (CHI) * wh[KK]; }
        SFB_EVEN(ETAP)
#undef ETAP
#define OTAP(KK, CLO, CHI) { ao += (CLO) * wl[KK]; ao += (CHI) * wh[KK]; }
        SFB_ODD(OTAP)
#undef OTAP
        sout[m0 + 2 * p][ql]     = ae;
        sout[m0 + 2 * p + 1][ql] = ao;
        if (p < 15) {
            #pragma unroll
            for (int k = 0; k < 5; k++) { wl[k] = wl[k + 1]; wh[k] = wh[k + 1]; }
            int t = t0 + p + 6;
            wl[5] = plo[t * 512];
            wh[5] = phi[t * 512];
        }
    }
    __syncthreads();
    int obase = y * 256 + tid;
    #pragma unroll
    for (int i = 0; i < 32; i++)
        out[(q0 + i) * 65536 + obase] = sout[tid][i];
}

// ---------------- afb core (sliding window, 4 outputs/thread) ---------------
__device__ __forceinline__ void afb_core(
    const float* __restrict__ in, float* __restrict__ lo, float* __restrict__ hi,
    int nf_in, int nf_out, int sf_in, int so_in, int sf_out, int so_out,
    int bx, int by, int bz) {
    int lane = threadIdx.x & 31;
    int jj = threadIdx.x >> 5;
    int j0 = (bx * 8 + jj) * 4;
    if (j0 >= nf_out) return;
    int vo = bz * 128 + lane * 4;
    const float* pin = in + by * so_in + vo;
    int tb = 2 * j0 - 10;
    float4 w[12];
    #pragma unroll
    for (int k = 0; k < 12; k++) {
        int t = tb + k;
        t = (t < 0) ? (-1 - t) : ((t >= nf_in) ? (2 * nf_in - 1 - t) : t);
        w[k] = *(const float4*)(pin + t * sf_in);
    }
    int oo = by * so_out + j0 * sf_out + vo;
    float* plo = lo + oo;
    float* phi = hi + oo;
    #pragma unroll
    for (int u = 0; u < 4; u++) {
        if (j0 + u < nf_out) {
            float4 alo = {0.f,0.f,0.f,0.f}, ahi = {0.f,0.f,0.f,0.f};
#define TAP(K, CLO, CHI) { float4 xv = w[K];                                   \
            alo.x += (CLO) * xv.x; alo.y += (CLO) * xv.y;                      \
            alo.z += (CLO) * xv.z; alo.w += (CLO) * xv.w;                      \
            ahi.x += (CHI) * xv.x; ahi.y += (CHI) * xv.y;                      \
            ahi.z += (CHI) * xv.z; ahi.w += (CHI) * xv.w; }
            AFB_TAPS(TAP)
#undef TAP
            *(float4*)plo = alo;
            *(float4*)phi = ahi;
        }
        if (u < 3) {
            #pragma unroll
            for (int k = 0; k < 10; k++) w[k] = w[k + 2];
            int t0n = tb + 12 + 2 * u;
            int t1n = t0n + 1;
            t0n = (t0n >= nf_in) ? (2 * nf_in - 1 - t0n) : t0n;
            t1n = (t1n >= nf_in) ? (2 * nf_in - 1 - t1n) : t1n;
            w[10] = *(const float4*)(pin + t0n * sf_in);
            w[11] = *(const float4*)(pin + t1n * sf_in);
            plo += sf_out;
            phi += sf_out;
        }
    }
}

__global__ __launch_bounds__(256) void afb_kernel(
    const float* __restrict__ in, float* __restrict__ lo, float* __restrict__ hi,
    int nf_in, int nf_out, int sf_in, int so_in, int sf_out, int so_out) {
    afb_core(in, lo, hi, nf_in, nf_out, sf_in, so_in, sf_out, so_out,
             blockIdx.x, blockIdx.y, blockIdx.z);
}

__global__ __launch_bounds__(256) void afb_pair(
    const float* __restrict__ in0, float* __restrict__ lo0, float* __restrict__ hi0,
    const float* __restrict__ in1, float* __restrict__ lo1, float* __restrict__ hi1,
    int nf_in, int nf_out, int sf_in, int so_in, int sf_out, int so_out) {
    int sel = blockIdx.z >> 2, bz = blockIdx.z & 3;
    afb_core(sel ? in1 : in0, sel ? lo1 : lo0, sel ? hi1 : hi0,
             nf_in, nf_out, sf_in, so_in, sf_out, so_out,
             blockIdx.x, blockIdx.y, bz);
}

// ---------------- sfb core (sliding window, 4 outputs/thread) ---------------
__device__ __forceinline__ void sfb_core(
    const float* __restrict__ lo, const float* __restrict__ hi, float* __restrict__ out,
    int n_t, int nf_out, int sflo, int solo, int sfhi, int sohi,
    int sf_out, int so_out, int bx, int by, int bz) {
    int lane = threadIdx.x & 31;
    int mm = threadIdx.x >> 5;
    int m0 = (bx * 8 + mm) * 4;
    if (m0 >= nf_out) return;
    int vo = bz * 128 + lane * 4;
    const float* plo = lo + by * solo + vo;
    const float* phi = hi + by * sohi + vo;
    int t0 = m0 >> 1;
    float4 wl[6], wh[6];
    #pragma unroll
    for (int k = 0; k < 6; k++) {
        int t = t0 + k;
        bool ok = (unsigned)t < (unsigned)n_t;
        wl[k] = ok ? *(const float4*)(plo + t * sflo) : make_float4(0.f,0.f,0.f,0.f);
        wh[k] = ok ? *(const float4*)(phi + t * sfhi) : make_float4(0.f,0.f,0.f,0.f);
    }
    float* pout = out + by * so_out + m0 * sf_out + vo;
    #pragma unroll
    for (int p = 0; p < 2; p++) {
        float4 ae = {0.f,0.f,0.f,0.f}, ao = {0.f,0.f,0.f,0.f};
#define ETAP(KK, CLO, CHI) { float4 a = wl[KK]; float4 b = wh[KK];             \
        ae.x += (CLO)*a.x; ae.x += (CHI)*b.x;  ae.y += (CLO)*a.y; ae.y += (CHI)*b.y; \
        ae.z += (CLO)*a.z; ae.z += (CHI)*b.z;  ae.w += (CLO)*a.w; ae.w += (CHI)*b.w; }
        SFB_EVEN(ETAP)
#undef ETAP
#define OTAP(KK, CLO, CHI) { float4 a = wl[KK]; float4 b = wh[KK];             \
        ao.x += (CLO)*a.x; ao.x += (CHI)*b.x;  ao.y += (CLO)*a.y; ao.y += (CHI)*b.y; \
        ao.z += (CLO)*a.z; ao.z += (CHI)*b.z;  ao.w += (CLO)*a.w; ao.w += (CHI)*b.w; }
        SFB_ODD(OTAP)
#undef OTAP
        int me = m0 + 2 * p;
        if (me < nf_out)     *(float4*)pout = ae;
        if (me + 1 < nf_out) *(float4*)(pout + sf_out) = ao;
        if (p == 0) {
            #pragma unroll
            for (int k = 0; k < 5; k++) { wl[k] = wl[k + 1]; wh[k] = wh[k + 1]; }
            int t = t0 + 6;
            bool ok = (unsigned)t < (unsigned)n_t;
            wl[5] = ok ? *(const float4*)(plo + t * sflo) : make_float4(0.f,0.f,0.f,0.f);
            wh[5] = ok ? *(const float4*)(phi + t * sfhi) : make_float4(0.f,0.f,0.f,0.f);
            pout += 2 * sf_out;
        }
    }
}

__global__ __launch_bounds__(256) void sfb_kernel(
    const float* __restrict__ lo, const float* __restrict__ hi, float* __restrict__ out,
    int n_t, int nf_out, int sflo, int solo, int sfhi, int sohi,
    int sf_out, int so_out) {
    sfb_core(lo, hi, out, n_t, nf_out, sflo, solo, sfhi, sohi, sf_out, so_out,
             blockIdx.x, blockIdx.y, blockIdx.z);
}

__global__ __launch_bounds__(256) void sfb_pair(
    const float* __restrict__ lo0, const float* __restrict__ hi0, float* __restrict__ out0,
    const float* __restrict__ lo1, const float* __restrict__ hi1, float* __restrict__ out1,
    int n_t, int nf_out, int sflo0, int sflo1, int solo, int sfhi, int sohi,
    int sf_out, int so_out) {
    int sel = blockIdx.z >> 2, bz = blockIdx.z & 3;
    sfb_core(sel ? lo1 : lo0, sel ? hi1 : hi0, sel ? out1 : out0,
             n_t, nf_out, sel ? sflo1 : sflo0, solo, sfhi, sohi, sf_out, so_out,
             blockIdx.x, blockIdx.y, bz);
}

// ---------------- conv: 2 vertical pixels/CTA, SHARED corner loads ----------
// in_s stride 68 (aligned 16B; row-pair delta 6*68 % 32 = 24, conflict-free).
// smem 45,824 B -> 5 CTAs/SM fit (229,120 B <= 228 KB).
__global__ __launch_bounds__(128, 5) void conv2(
    float* p0, float* p1, float* p2, int n) {
    constexpr int S = 3;
    constexpr int R = S * 8;          // 24
    constexpr int TR = R / 4;         // 6 rows per thread
    constexpr int IST = 68;
    __shared__ float w_s[2][64 * 64];
    __shared__ float in_s[2][R * IST];
    int tid = threadIdx.x;
    int sel = tid >> 6, t = tid & 63;
    int jx = blockIdx.y;
    int jyA = blockIdx.x * 2;
    int jy = jyA + sel;
    bool act = jy < n;
    float sc = (float)(64.0 / n);
    float xc = fminf(fmaxf((jx + 0.5f) * sc - 0.5f, 0.0f), 63.0f);
    int x0 = (int)floorf(xc), x1 = min(x0 + 1, 63);
    float tx = xc - (float)x0;
    float ycA = fminf(fmaxf((jyA + 0.5f) * sc - 0.5f, 0.0f), 63.0f);
    int jyBc = min(jyA + 1, n - 1);
    float ycB = fminf(fmaxf((jyBc + 0.5f) * sc - 0.5f, 0.0f), 63.0f);
    int y0A = (int)floorf(ycA), y0B = (int)floorf(ycB);
    float tyA = ycA - (float)y0A, tyB = ycB - (float)y0B;
    float c00A = (1.f - tyA) * (1.f - tx), c01A = (1.f - tyA) * tx;
    float c10A = tyA * (1.f - tx),         c11A = tyA * tx;
    float c00B = (1.f - tyB) * (1.f - tx), c01B = (1.f - tyB) * tx;
    float c10B = tyB * (1.f - tx),         c11B = tyB * tx;

    if (y0B == y0A) {
        int y1 = min(y0A + 1, 63);
        const float* w00 = g_wt + ((long)y0A * 64 + x0) * 4096;
        const float* w01 = g_wt + ((long)y0A * 64 + x1) * 4096;
        const float* w10 = g_wt + ((long)y1  * 64 + x0) * 4096;
        const float* w11 = g_wt + ((long)y1  * 64 + x1) * 4096;
        #pragma unroll 4
        for (int it = 0; it < 8; it++) {
            int e = it * 512 + tid * 4;
            float4 a = *(const float4*)(w00 + e);
            float4 b = *(const float4*)(w01 + e);
            float4 d = *(const float4*)(w10 + e);
            float4 f = *(const float4*)(w11 + e);
            float4 wa, wb;
            wa.x = c00A*a.x + c01A*b.x + c10A*d.x + c11A*f.x;
            wa.y = c00A*a.y + c01A*b.y + c10A*d.y + c11A*f.y;
            wa.z = c00A*a.z + c01A*b.z + c10A*d.z + c11A*f.z;
            wa.w = c00A*a.w + c01A*b.w + c10A*d.w + c11A*f.w;
            wb.x = c00B*a.x + c01B*b.x + c10B*d.x + c11B*f.x;
            wb.y = c00B*a.y + c01B*b.y + c10B*d.y + c11B*f.y;
            wb.z = c00B*a.z + c01B*b.z + c10B*d.z + c11B*f.z;
            wb.w = c00B*a.w + c01B*b.w + c10B*d.w + c11B*f.w;
            *(float4*)&w_s[0][e] = wa;
            *(float4*)&w_s[1][e] = wb;
        }
    } else {
        int r0 = y0A, r1 = y0A + 1, r2 = min(y0A + 2, 63);
        const float* wa0 = g_wt + ((long)r0 * 64 + x0) * 4096;
        const float* wa1 = g_wt + ((long)r0 * 64 + x1) * 4096;
        const float* wm0 = g_wt + ((long)r1 * 64 + x0) * 4096;
        const float* wm1 = g_wt + ((long)r1 * 64 + x1) * 4096;
        const float* wb0 = g_wt + ((long)r2 * 64 + x0) * 4096;
        const float* wb1 = g_wt + ((long)r2 * 64 + x1) * 4096;
        #pragma unroll 2
        for (int it = 0; it < 8; it++) {
            int e = it * 512 + tid * 4;
            float4 a0 = *(const float4*)(wa0 + e);
            float4 a1 = *(const float4*)(wa1 + e);
            float4 m0 = *(const float4*)(wm0 + e);
            float4 m1 = *(const float4*)(wm1 + e);
            float4 b0 = *(const float4*)(wb0 + e);
            float4 b1 = *(const float4*)(wb1 + e);
            float4 wa, wb;
            wa.x = c00A*a0.x + c01A*a1.x + c10A*m0.x + c11A*m1.x;
            wa.y = c00A*a0.y + c01A*a1.y + c10A*m0.y + c11A*m1.y;
            wa.z = c00A*a0.z + c01A*a1.z + c10A*m0.z + c11A*m1.z;
            wa.w = c00A*a0.w + c01A*a1.w + c10A*m0.w + c11A*m1.w;
            wb.x = c00B*m0.x + c01B*m1.x + c10B*b0.x + c11B*b1.x;
            wb.y = c00B*m0.y + c01B*m1.y + c10B*b0.y + c11B*b1.y;
            wb.z = c00B*m0.z + c01B*m1.z + c10B*b0.z + c11B*b1.z;
            wb.w = c00B*m0.w + c01B*m1.w + c10B*b0.w + c11B*b1.w;
            *(float4*)&w_s[0][e] = wa;
            *(float4*)&w_s[1][e] = wb;
        }
    }

    long pix = ((long)jy * n + jx) * V;
    if (act) {
        #pragma unroll
        for (int l = 0; l < R / 4; l++) {
            int idx = l * 64 + t;
            int r = idx >> 4, i4 = (idx & 15) * 4;
            int ss = r >> 3, b = r & 7;
            const float* p = (ss == 0) ? p0 : (ss == 1) ? p1 : p2;
            *(float4*)&in_s[sel][r * IST + i4] = *(const float4*)(p + pix + b * 64 + i4);
        }
    }
    __syncthreads();
    if (act) {
        int colg = t & 15, rowg = t >> 4;
        int o0 = colg * 4, r0 = rowg * TR;
        unsigned long long a01[TR], a23[TR];
        #pragma unroll
        for (int r = 0; r < TR; r++) { a01[r] = 0ull; a23[r] = 0ull; }
        #pragma unroll 8
        for (int i = 0; i < 64; i += 4) {
            ulonglong2 w0 = *(const ulonglong2*)&w_s[sel][(i + 0) * 64 + o0];
            ulonglong2 w1 = *(const ulonglong2*)&w_s[sel][(i + 1) * 64 + o0];
            ulonglong2 w2 = *(const ulonglong2*)&w_s[sel][(i + 2) * 64 + o0];
            ulonglong2 w3 = *(const ulonglong2*)&w_s[sel][(i + 3) * 64 + o0];
            #pragma unroll
            for (int r = 0; r < TR; r++) {
                float4 v = *(const float4*)&in_s[sel][(r0 + r) * IST + i];
                unsigned long long vx, vy, vz, vw;
                BCAST2(vx, v.x); BCAST2(vy, v.y);
                BCAST2(vz, v.z); BCAST2(vw, v.w);
                FFMA2(a01[r], w0.x, vx); FFMA2(a23[r], w0.y, vx);
                FFMA2(a01[r], w1.x, vy); FFMA2(a23[r], w1.y, vy);
                FFMA2(a01[r], w2.x, vz); FFMA2(a23[r], w2.y, vz);
                FFMA2(a01[r], w3.x, vw); FFMA2(a23[r], w3.y, vw);
            }
        }
        #pragma unroll
        for (int r = 0; r < TR; r++) {
            int rr = r0 + r;
            int ss = rr >> 3, b = rr & 7;
            float* p = (ss == 0) ? p0 : (ss == 1) ? p1 : p2;
            float4 outv;
            UNPACK2(outv.x, outv.y, a01[r]);
            UNPACK2(outv.z, outv.w, a23[r]);
            *(float4*)(p + pix + b * 64 + o0) = outv;
        }
    }
}

// ---------------- per-pixel conv (level 3, S=4), f32x2 packed GEMM ----------
template <int S>
__global__ __launch_bounds__(128, 5) void conv_kernel(
    float* p0, float* p1, float* p2, float* p3, int n) {
    constexpr int R  = S * 8;
    constexpr int TR = R / 8;
    constexpr int IST = 68;
    __shared__ float w_s[64 * 64];
    __shared__ float in_s[R * IST];
    int jx = blockIdx.x, jy = blockIdx.y, tid = threadIdx.x;
    float sc = (float)(64.0 / n);
    float yc = fminf(fmaxf((jy + 0.5f) * sc - 0.5f, 0.0f), 63.0f);
    float xc = fminf(fmaxf((jx + 0.5f) * sc - 0.5f, 0.0f), 63.0f);
    int y0 = (int)floorf(yc), x0 = (int)floorf(xc);
    int y1 = min(y0 + 1, 63), x1 = min(x0 + 1, 63);
    float ty = yc - (float)y0, tx = xc - (float)x0;
    float c00 = (1.f - ty) * (1.f - tx), c01 = (1.f - ty) * tx;
    float c10 = ty * (1.f - tx),         c11 = ty * tx;
    const float* w00 = g_wt + ((long)y0 * 64 + x0) * 4096;
    const float* w01 = g_wt + ((long)y0 * 64 + x1) * 4096;
    const float* w10 = g_wt + ((long)y1 * 64 + x0) * 4096;
    const float* w11 = g_wt + ((long)y1 * 64 + x1) * 4096;
    #pragma unroll 4
    for (int c = 0; c < 8; c++) {
        int e = c * 512 + tid * 4;
        float4 a = *(const float4*)(w00 + e);
        float4 b = *(const float4*)(w01 + e);
        float4 d = *(const float4*)(w10 + e);
        float4 f = *(const float4*)(w11 + e);
        float4 wv;
        wv.x = c00 * a.x + c01 * b.x + c10 * d.x + c11 * f.x;
        wv.y = c00 * a.y + c01 * b.y + c10 * d.y + c11 * f.y;
        wv.z = c00 * a.z + c01 * b.z + c10 * d.z + c11 * f.z;
        wv.w = c00 * a.w + c01 * b.w + c10 * d.w + c11 * f.w;
        *(float4*)&w_s[e] = wv;
    }
    long pix = ((long)jy * n + jx) * V;
    {
        int b = tid >> 4, i4 = (tid & 15) * 4;
        #pragma unroll
        for (int ss = 0; ss < S; ss++) {
            const float* p = (ss == 0) ? p0 : (ss == 1) ? p1 : (ss == 2) ? p2 : p3;
            *(float4*)&in_s[(ss * 8 + b) * IST + i4] = *(const float4*)(p + pix + b * 64 + i4);
        }
    }
    __syncthreads();
    int colg = tid & 15, rowg = tid >> 4;
    int o0 = colg * 4, r0 = rowg * TR;
    unsigned long long a01[TR], a23[TR];
    #pragma unroll
    for (int r = 0; r < TR; r++) { a01[r] = 0ull; a23[r] = 0ull; }
    #pragma unroll 8
    for (int i = 0; i < 64; i += 4) {
        ulonglong2 w0 = *(const ulonglong2*)&w_s[(i + 0) * 64 + o0];
        ulonglong2 w1 = *(const ulonglong2*)&w_s[(i + 1) * 64 + o0];
        ulonglong2 w2 = *(const ulonglong2*)&w_s[(i + 2) * 64 + o0];
        ulonglong2 w3 = *(const ulonglong2*)&w_s[(i + 3) * 64 + o0];
        #pragma unroll
        for (int r = 0; r < TR; r++) {
            float4 v = *(const float4*)&in_s[(r0 + r) * IST + i];
            unsigned long long vx, vy, vz, vw;
            BCAST2(vx, v.x); BCAST2(vy, v.y);
            BCAST2(vz, v.z); BCAST2(vw, v.w);
            FFMA2(a01[r], w0.x, vx); FFMA2(a23[r], w0.y, vx);
            FFMA2(a01[r], w1.x, vy); FFMA2(a23[r], w1.y, vy);
            FFMA2(a01[r], w2.x, vz); FFMA2(a23[r], w2.y, vz);
            FFMA2(a01[r], w3.x, vw); FFMA2(a23[r], w3.y, vw);
        }
    }
    #pragma unroll
    for (int r = 0; r < TR; r++) {
        int rr = r0 + r;
        int ss = rr >> 3, b = rr & 7;
        float* p = (ss == 0) ? p0 : (ss == 1) ? p1 : (ss == 2) ? p2 : p3;
        float4 outv;
        UNPACK2(outv.x, outv.y, a01[r]);
        UNPACK2(outv.z, outv.w, a23[r]);
        *(float4*)(p + pix + b * 64 + o0) = outv;
    }
}

// ---------------- host ----------------
#define SYM(var, sym) float* var; { void* _p; cudaGetSymbolAddress(&_p, sym); var = (float*)_p; }

extern "C" void kernel_launch(void* const* d_in, const int* in_sizes, int n_in,
                              void* d_out, int out_size) {
    const float* x = (const float*)d_in[0];
    const float* w = (const float*)d_in[1];
    float* out = (float*)d_out;
    SYM(TLO, g_tlo) SYM(THI, g_thi)
    SYM(LL1, g_ll1) SYM(LH1, g_lh1) SYM(HL1, g_hl1) SYM(HH1, g_hh1)
    SYM(LL2, g_ll2) SYM(LH2, g_lh2) SYM(HL2, g_hl2) SYM(HH2, g_hh2)
    SYM(LL3, g_ll3) SYM(LH3, g_lh3) SYM(HL3, g_hl3) SYM(HH3, g_hh3)
    SYM(R2, g_r2)  SYM(WT, g_wt)

    // #1..#3
    wtrans2<<<dim3(8, 2, 128), 256>>>(w, WT);
    afb_w_first<<<dim3(16, 256), 256>>>(x, TLO, THI);
    afb_pair<<<dim3(5, 133, 8), 256>>>(TLO, LL1, LH1, THI, HL1, HH1,
                                       256, 133, 133*512, 512, 133*512, 512);
    // #4: the dominant conv — profiled slot
    conv2<<<dim3(67, 133), 128>>>(LH1, HL1, HH1, 133);
    // remaining DWT
    afb_kernel<<<dim3(3, 133, 4), 256>>>(LL1, TLO, THI, 133, 72, 512, 133*512, 512, 72*512);
    afb_pair<<<dim3(3, 72, 8), 256>>>(TLO, LL2, LH2, THI, HL2, HH2,
                                      133, 72, 72*512, 512, 72*512, 512);
    conv2<<<dim3(36, 72), 128>>>(LH2, HL2, HH2, 72);
    afb_kernel<<<dim3(2, 72, 4), 256>>>(LL2, TLO, THI, 72, 41, 512, 72*512, 512, 41*512);
    afb_pair<<<dim3(2, 41, 8), 256>>>(TLO, LL3, LH3, THI, HL3, HH3,
                                      72, 41, 41*512, 512, 41*512, 512);
    conv_kernel<4><<<dim3(41, 41), 128>>>(LL3, LH3, HL3, HH3, 41);

    // ---- IDWT ----
    sfb_pair<<<dim3(3, 41, 8), 256>>>(LL3, LH3, TLO, HL3, HH3, THI,
        41, 72, 41*512, 41*512, 512, 41*512, 512, 41*512, 512);
    sfb_kernel<<<dim3(3, 72, 4), 256>>>(TLO, THI, LL2, 41, 72,
        512, 41*512, 512, 41*512, 512, 72*512);
    sfb_pair<<<dim3(5, 72, 8), 256>>>(LL2, LH2, TLO, HL2, HH2, THI,
        72, 134, 72*512, 72*512, 512, 72*512, 512, 72*512, 512);
    sfb_kernel<<<dim3(5, 134, 4), 256>>>(TLO, THI, R2, 72, 134,
        512, 72*512, 512, 72*512, 512, 134*512);
    sfb_pair<<<dim3(8, 133, 8), 256>>>(R2, LH1, TLO, HL1, HH1, THI,
        133, 256, 134*512, 133*512, 512, 133*512, 512, 133*512, 512);
    sfb_w_last<<<dim3(16, 256), 256>>>(TLO, THI, out);
}